// round 6
// baseline (speedup 1.0000x reference)
#include <cuda_runtime.h>
#include <cuda_bf16.h>
#include <math.h>
#include <stdint.h>

// ---------------- problem dims ----------------
#define BB    2
#define TT    1024
#define NTOK  2048
#define DD    1024
#define HQn   16
#define HKVn  4
#define KDn   64
#define VDn   64
#define Gn    4
#define En    8
#define CAPn  1024
#define HIDn  2048

// ---------------- fp32 scratch ----------------
__device__ float g_qkv [NTOK*1536];
__device__ float g_x1  [NTOK*DD];
__device__ float g_h2  [NTOK*DD];
__device__ float g_grp [En*CAPn*DD];
__device__ float g_t1  [En*CAPn*HIDn];
__device__ float g_t2  [En*CAPn*HIDn];
__device__ float g_eout[En*CAPn*DD];
__device__ int   g_assign[NTOK*2];
__device__ float g_gate  [NTOK*2];
__device__ int   g_slot  [NTOK*2];
__device__ int   g_keep  [NTOK*2];

// ---------------- bf16 hi/lo scratch ----------------
#define SZ_H    (NTOK*DD)
#define SZ_Q    (NTOK*HQn*KDn)
#define SZ_K    (NTOK*HKVn*KDn)
#define SZ_VT   (BB*HKVn*VDn*TT)
#define SZ_ATT  (NTOK*DD)
#define SZ_GRP  (En*CAPn*DD)
#define SZ_T1   (En*CAPn*HIDn)
#define SZ_QKVW (1536*DD)
#define SZ_WOT  (DD*DD)
#define SZ_W1T  (En*HIDn*DD)
#define SZ_W3T  (En*DD*HIDn)

__device__ __nv_bfloat16 b_h    [2*SZ_H];
__device__ __nv_bfloat16 b_q    [2*SZ_Q];
__device__ __nv_bfloat16 b_k    [2*SZ_K];
__device__ __nv_bfloat16 b_vt   [2*SZ_VT];
__device__ __nv_bfloat16 b_attn [2*SZ_ATT];
__device__ __nv_bfloat16 b_grp  [2*SZ_GRP];
__device__ __nv_bfloat16 b_t1   [2*SZ_T1];
__device__ __nv_bfloat16 b_wqkvT[2*SZ_QKVW];
__device__ __nv_bfloat16 b_woT  [2*SZ_WOT];
__device__ __nv_bfloat16 b_w1T  [2*SZ_W1T];
__device__ __nv_bfloat16 b_w2T  [2*SZ_W1T];
__device__ __nv_bfloat16 b_w3T  [2*SZ_W3T];

// ---------------- helpers ----------------
__device__ __forceinline__ uint32_t pack2(float a, float b) {
    __nv_bfloat162 t = __floats2bfloat162_rn(a, b);
    return *reinterpret_cast<uint32_t*>(&t);
}
__device__ __forceinline__ float lopart(float x) {
    return x - __bfloat162float(__float2bfloat16(x));
}
__device__ __forceinline__ int swz(int row, int k) {
    return row * 16 + ((((k >> 3) ^ (row >> 2)) & 1) << 3) + (k & 7);
}

#define LDSM4(r0,r1,r2,r3,a) \
  asm volatile("ldmatrix.sync.aligned.m8n8.x4.shared.b16 {%0,%1,%2,%3}, [%4];" \
    : "=r"(r0), "=r"(r1), "=r"(r2), "=r"(r3) : "r"(a))

#define MMA16816(d, a, b) \
  asm volatile("mma.sync.aligned.m16n8k16.row.col.f32.bf16.bf16.f32 " \
    "{%0,%1,%2,%3}, {%4,%5,%6,%7}, {%8,%9}, {%0,%1,%2,%3};" \
    : "+f"(d[0]), "+f"(d[1]), "+f"(d[2]), "+f"(d[3]) \
    : "r"(a[0]), "r"(a[1]), "r"(a[2]), "r"(a[3]), "r"(b[0]), "r"(b[1]))

#define MMAS(d, a, b0, b1) \
  asm volatile("mma.sync.aligned.m16n8k16.row.col.f32.bf16.bf16.f32 " \
    "{%0,%1,%2,%3}, {%4,%5,%6,%7}, {%8,%9}, {%0,%1,%2,%3};" \
    : "+f"(d[0]), "+f"(d[1]), "+f"(d[2]), "+f"(d[3]) \
    : "r"(a[0]), "r"(a[1]), "r"(a[2]), "r"(a[3]), "r"(b0), "r"(b1))

// ---------------- small kernels ----------------
__global__ void rmsnorm_kernel(const float* __restrict__ x,
                               const float* __restrict__ scale,
                               float* __restrict__ outF,
                               __nv_bfloat16* __restrict__ outH,
                               __nv_bfloat16* __restrict__ outL) {
    int row = blockIdx.x;
    const float* xr = x + (long long)row * DD;
    __shared__ float red[256];
    float s = 0.f;
    for (int d = threadIdx.x; d < DD; d += 256) { float v = xr[d]; s += v * v; }
    red[threadIdx.x] = s; __syncthreads();
    for (int o = 128; o > 0; o >>= 1) {
        if (threadIdx.x < o) red[threadIdx.x] += red[threadIdx.x + o];
        __syncthreads();
    }
    float inv = 1.0f / sqrtf(red[0] / (float)DD + 1e-6f);
    for (int d = threadIdx.x; d < DD; d += 256) {
        float v = xr[d] * inv * scale[d];
        if (outF) outF[(long long)row * DD + d] = v;
        if (outH) {
            __nv_bfloat16 hb = __float2bfloat16(v);
            outH[(long long)row * DD + d] = hb;
            outL[(long long)row * DD + d] = __float2bfloat16(v - __bfloat162float(hb));
        }
    }
}

__global__ void rope_kernel(float* __restrict__ p, int colBase, int H, long long total) {
    long long i = (long long)blockIdx.x * 256 + threadIdx.x;
    if (i >= total) return;
    int j = (int)(i & 31);
    long long nh = i >> 5;
    int h = (int)(nh % H);
    long long n = nh / H;
    int t = (int)(n % TT);
    float* v = p + n * 1536 + colBase + h * 64;
    float theta = powf(10000.0f, -(2.0f * j) / 64.0f);
    float a = (float)t * theta;
    float c = cosf(a), s = sinf(a);
    float x1 = v[j], x2 = v[j + 32];
    v[j]      = x1 * c - x2 * s;
    v[j + 32] = x2 * c + x1 * s;
}

__global__ void router_kernel(const float* __restrict__ rw, const float* __restrict__ rb) {
    int t = blockIdx.x;
    const float* xr = g_h2 + (long long)t * DD;
    float part[En];
    #pragma unroll
    for (int e = 0; e < En; e++) part[e] = 0.f;
    for (int d = threadIdx.x; d < DD; d += 256) {
        float xv = xr[d];
        #pragma unroll
        for (int e = 0; e < En; e++) part[e] += xv * rw[d * En + e];
    }
    __shared__ float red[En][8];
    int lane = threadIdx.x & 31, warp = threadIdx.x >> 5;
    #pragma unroll
    for (int e = 0; e < En; e++) {
        float v = part[e];
        for (int o = 16; o > 0; o >>= 1) v += __shfl_down_sync(0xffffffffu, v, o);
        if (lane == 0) red[e][warp] = v;
    }
    __syncthreads();
    if (threadIdx.x == 0) {
        float lg[En];
        #pragma unroll
        for (int e = 0; e < En; e++) {
            float s = 0.f;
            for (int w = 0; w < 8; w++) s += red[e][w];
            lg[e] = s + rb[e];
        }
        int i0 = 0;
        for (int e = 1; e < En; e++) if (lg[e] > lg[i0]) i0 = e;
        int i1 = -1;
        for (int e = 0; e < En; e++) {
            if (e == i0) continue;
            if (i1 < 0 || lg[e] > lg[i1]) i1 = e;
        }
        float e1 = expf(lg[i1] - lg[i0]);
        float denom = 1.f + e1;
        g_assign[2 * t] = i0;     g_assign[2 * t + 1] = i1;
        g_gate[2 * t] = 1.f / denom; g_gate[2 * t + 1] = e1 / denom;
    }
}

__global__ void scan_kernel() {
    int lane = threadIdx.x & 31;
    int e = threadIdx.x >> 5;
    uint32_t mle = 0xFFFFFFFFu >> (31 - lane);
    int base0 = 0, base1 = 0;
    for (int chunk = 0; chunk < NTOK / 32; chunk++) {
        int t = chunk * 32 + lane;
        int a0 = g_assign[2 * t], a1 = g_assign[2 * t + 1];
        uint32_t b0 = __ballot_sync(0xFFFFFFFFu, a0 == e);
        uint32_t b1 = __ballot_sync(0xFFFFFFFFu, a1 == e);
        int incl0 = __popc(b0 & mle);
        int incl1 = __popc(b1 & mle);
        if (a0 == e) {
            int p0 = base0 + incl0;
            g_slot[2 * t] = p0; g_keep[2 * t] = (p0 < CAPn) ? 1 : 0;
        }
        if (a1 == e) {
            int p1 = (base0 + incl0) + (base1 + incl1);
            g_slot[2 * t + 1] = p1; g_keep[2 * t + 1] = (p1 < CAPn) ? 1 : 0;
        }
        base0 += __popc(b0); base1 += __popc(b1);
    }
}

__global__ void zero_kernel(float* __restrict__ p, long long n) {
    long long i = (long long)blockIdx.x * 256 + threadIdx.x;
    if (i < n) p[i] = 0.f;
}

__global__ void scatter_kernel() {
    int i = blockIdx.x;
    if (!g_keep[i]) return;
    int t = i >> 1;
    int e = g_assign[i], s = g_slot[i];
    float* dst = g_grp + ((long long)e * CAPn + s) * DD;
    const float* src = g_h2 + (long long)t * DD;
    for (int d = threadIdx.x; d < DD; d += 256) atomicAdd(&dst[d], src[d]);
}

__global__ void gelu_mul_kernel(__nv_bfloat16* __restrict__ oh,
                                __nv_bfloat16* __restrict__ ol, long long n4) {
    long long i = (long long)blockIdx.x * 256 + threadIdx.x;
    if (i >= n4) return;
    float4 a = *(const float4*)&g_t1[i * 4];
    float4 b = *(const float4*)&g_t2[i * 4];
    float r[4];
    float xs[4] = {a.x * b.x, a.y * b.y, a.z * b.z, a.w * b.w};
    #pragma unroll
    for (int j = 0; j < 4; j++) {
        float x = xs[j];
        float inner = 0.7978845608028654f * (x + 0.044715f * x * x * x);
        r[j] = 0.5f * x * (1.0f + tanhf(inner));
    }
    uint2 hv, lv;
    hv.x = pack2(r[0], r[1]); hv.y = pack2(r[2], r[3]);
    lv.x = pack2(lopart(r[0]), lopart(r[1]));
    lv.y = pack2(lopart(r[2]), lopart(r[3]));
    *(uint2*)&oh[i * 4] = hv;
    *(uint2*)&ol[i * 4] = lv;
}

__global__ void combine_kernel(float* __restrict__ out) {
    int t = blockIdx.x;
    float gte0 = g_gate[2 * t], gte1 = g_gate[2 * t + 1];
    const float* s0 = g_keep[2 * t]
        ? g_eout + ((long long)g_assign[2 * t] * CAPn + g_slot[2 * t]) * DD
        : g_h2 + (long long)t * DD;
    const float* s1 = g_keep[2 * t + 1]
        ? g_eout + ((long long)g_assign[2 * t + 1] * CAPn + g_slot[2 * t + 1]) * DD
        : g_h2 + (long long)t * DD;
    const float* xr = g_x1 + (long long)t * DD;
    float* orow = out + (long long)t * DD;
    for (int d = threadIdx.x; d < DD; d += 256)
        orow[d] = xr[d] + gte0 * s0[d] + gte1 * s1[d];
}

__global__ void conv4_kernel(const float* __restrict__ src, __nv_bfloat16* __restrict__ hi,
                             __nv_bfloat16* __restrict__ lo, long long n4) {
    long long i = (long long)blockIdx.x * 256 + threadIdx.x;
    if (i >= n4) return;
    float4 v = *(const float4*)&src[i * 4];
    uint2 hv, lv;
    hv.x = pack2(v.x, v.y); hv.y = pack2(v.z, v.w);
    lv.x = pack2(lopart(v.x), lopart(v.y));
    lv.y = pack2(lopart(v.z), lopart(v.w));
    *(uint2*)&hi[i * 4] = hv;
    *(uint2*)&lo[i * 4] = lv;
}

__global__ void sconv_kernel(const float* __restrict__ src, int srcStride, int width,
                             __nv_bfloat16* __restrict__ hi, __nv_bfloat16* __restrict__ lo,
                             long long n) {
    long long i = (long long)blockIdx.x * 256 + threadIdx.x;
    if (i >= n) return;
    int row = (int)(i / width), col = (int)(i % width);
    float v = src[(long long)row * srcStride + col];
    __nv_bfloat16 h = __float2bfloat16(v);
    hi[i] = h; lo[i] = __float2bfloat16(v - __bfloat162float(h));
}

__global__ void tconv_kernel(const float* __restrict__ src, __nv_bfloat16* __restrict__ hi,
                             __nv_bfloat16* __restrict__ lo, int R, int C, int lds,
                             long long so, long long si, int zdiv) {
    int z = blockIdx.z;
    src += (long long)(z / zdiv) * so + (long long)(z % zdiv) * si;
    long long d = (long long)z * R * C;
    hi += d; lo += d;
    __shared__ float t[32][33];
    int c0 = blockIdx.x * 32, r0 = blockIdx.y * 32;
    for (int i = threadIdx.y; i < 32; i += 8) {
        int r = r0 + i, c = c0 + threadIdx.x;
        if (r < R && c < C) t[i][threadIdx.x] = src[(long long)r * lds + c];
    }
    __syncthreads();
    for (int i = threadIdx.y; i < 32; i += 8) {
        int c = c0 + i, r = r0 + threadIdx.x;
        if (r < R && c < C) {
            float v = t[threadIdx.x][i];
            __nv_bfloat16 hh = __float2bfloat16(v);
            hi[(long long)c * R + r] = hh;
            lo[(long long)c * R + r] = __float2bfloat16(v - __bfloat162float(hh));
        }
    }
}

// ---------------- bf16 split-precision tensor-core GEMM (NT), templated tile ----------------
template<int NTILE>
__global__ void __launch_bounds__(256, 1)
bgemm_kernel(int M, int N, int K,
             const __nv_bfloat16* __restrict__ Ah, const __nv_bfloat16* __restrict__ Al,
             int lda, long long soA, long long siA, int divA,
             const __nv_bfloat16* __restrict__ Bh, const __nv_bfloat16* __restrict__ Bl,
             int ldb, long long soB, long long siB, int divB,
             float* __restrict__ C, int ldc, long long soC, long long siC, int divC,
             int zdiv, int epi, const float* __restrict__ Rz) {
    constexpr int NF = NTILE / 32;
    constexpr int AE = 128 * 16;
    constexpr int BE = NTILE * 16;
    constexpr int STGE = 2 * AE + 2 * BE;
    constexpr int NB = NTILE / 128;

    int z = blockIdx.z;
    long long offA = (long long)(z / zdiv) * soA + (long long)((z % zdiv) / divA) * siA;
    long long offB = (long long)(z / zdiv) * soB + (long long)((z % zdiv) / divB) * siB;
    long long offC = (long long)(z / zdiv) * soC + (long long)((z % zdiv) / divC) * siC;
    Ah += offA; Al += offA; Bh += offB; Bl += offB; C += offC;
    const float* Rp = Rz ? (Rz + offC) : (const float*)0;

    int m0 = blockIdx.y * 128, n0 = blockIdx.x * NTILE;
    int tid = threadIdx.x;

    extern __shared__ __nv_bfloat16 sm[];
    uint32_t sbase = (uint32_t)__cvta_generic_to_shared(sm);

    int lr = tid >> 1, lc = tid & 1;
    const __nv_bfloat16* gAh = Ah + (long long)(m0 + lr) * lda + lc * 8;
    const __nv_bfloat16* gAl = Al + (long long)(m0 + lr) * lda + lc * 8;
    const __nv_bfloat16* gBh[NB];
    const __nv_bfloat16* gBl[NB];
    uint32_t soffB[NB];
    #pragma unroll
    for (int i = 0; i < NB; i++) {
        int brow = n0 + i * 128 + lr;
        gBh[i] = Bh + (long long)brow * ldb + lc * 8;
        gBl[i] = Bl + (long long)brow * ldb + lc * 8;
        soffB[i] = (uint32_t)swz(i * 128 + lr, lc * 8) * 2;
    }
    uint32_t soffA = (uint32_t)swz(lr, lc * 8) * 2;

    int KT = K / 16;

    auto prefetch = [&](int kt, int st) {
        long long ko = (long long)kt * 16;
        uint32_t b0 = sbase + (uint32_t)(st * STGE * 2);
        asm volatile("cp.async.cg.shared.global [%0], [%1], 16;"
                     :: "r"(b0 + soffA), "l"(gAh + ko));
        asm volatile("cp.async.cg.shared.global [%0], [%1], 16;"
                     :: "r"(b0 + (uint32_t)(AE * 2) + soffA), "l"(gAl + ko));
        #pragma unroll
        for (int i = 0; i < NB; i++) {
            asm volatile("cp.async.cg.shared.global [%0], [%1], 16;"
                         :: "r"(b0 + (uint32_t)(2 * AE * 2) + soffB[i]), "l"(gBh[i] + ko));
            asm volatile("cp.async.cg.shared.global [%0], [%1], 16;"
                         :: "r"(b0 + (uint32_t)((2 * AE + BE) * 2) + soffB[i]), "l"(gBl[i] + ko));
        }
        asm volatile("cp.async.commit_group;");
    };

    float acc[4][NF][4];
    #pragma unroll
    for (int i = 0; i < 4; i++)
        #pragma unroll
        for (int j = 0; j < NF; j++)
            #pragma unroll
            for (int e = 0; e < 4; e++) acc[i][j][e] = 0.f;

    int lane = tid & 31, wid = tid >> 5;
    int wm = wid & 1, wn = wid >> 1;
    int arow = wm * 64 + (lane & 15);
    int ak = (lane >> 4) * 8;
    int browf = wn * (NTILE / 4) + (lane & 7) + ((lane & 16) ? 8 : 0);
    int bk = (lane & 8) ? 8 : 0;

    prefetch(0, 0);
    if (KT > 1) prefetch(1, 1);

    for (int kt = 0; kt < KT; kt++) {
        if (kt + 2 < KT) {
            prefetch(kt + 2, (kt + 2) % 3);
            asm volatile("cp.async.wait_group 2;");
        } else if (kt + 1 < KT) {
            asm volatile("cp.async.wait_group 1;");
        } else {
            asm volatile("cp.async.wait_group 0;");
        }
        __syncthreads();

        uint32_t base = sbase + (uint32_t)((kt % 3) * STGE * 2);
        uint32_t fAh[4][4], fAl[4][4];
        #pragma unroll
        for (int mi = 0; mi < 4; mi++) {
            uint32_t ao = base + (uint32_t)swz(arow + mi * 16, ak) * 2;
            LDSM4(fAh[mi][0], fAh[mi][1], fAh[mi][2], fAh[mi][3], ao);
            LDSM4(fAl[mi][0], fAl[mi][1], fAl[mi][2], fAl[mi][3], ao + (uint32_t)(AE * 2));
        }
        #pragma unroll
        for (int nj = 0; nj < NF / 2; nj++) {
            uint32_t bo = base + (uint32_t)(2 * AE * 2) + (uint32_t)swz(browf + nj * 16, bk) * 2;
            uint32_t h0, h1, h2, h3, l0, l1, l2, l3;
            LDSM4(h0, h1, h2, h3, bo);
            LDSM4(l0, l1, l2, l3, bo + (uint32_t)(BE * 2));
            uint32_t fb0[2] = {h0, h1}, fb1[2] = {h2, h3};
            uint32_t gl0[2] = {l0, l1}, gl1[2] = {l2, l3};
            #pragma unroll
            for (int mi = 0; mi < 4; mi++) {
                MMA16816(acc[mi][nj * 2],     fAh[mi], fb0);
                MMA16816(acc[mi][nj * 2],     fAh[mi], gl0);
                MMA16816(acc[mi][nj * 2],     fAl[mi], fb0);
                MMA16816(acc[mi][nj * 2 + 1], fAh[mi], fb1);
                MMA16816(acc[mi][nj * 2 + 1], fAh[mi], gl1);
                MMA16816(acc[mi][nj * 2 + 1], fAl[mi], fb1);
            }
        }
        __syncthreads();
    }

    int r4 = lane >> 2, c2 = (lane & 3) * 2;
    #pragma unroll
    for (int mi = 0; mi < 4; mi++)
        #pragma unroll
        for (int ni = 0; ni < NF; ni++) {
            int row = m0 + wm * 64 + mi * 16 + r4;
            int col = n0 + wn * (NTILE / 4) + ni * 8 + c2;
            #pragma unroll
            for (int e = 0; e < 4; e++) {
                int rr = row + (e >> 1) * 8;
                int cc = col + (e & 1);
                float v = acc[mi][ni][e];
                if (epi == 2) v += Rp[(long long)rr * ldc + cc];
                C[(long long)rr * ldc + cc] = v;
            }
        }
}

// ---------------- flash attention ----------------
__global__ void __launch_bounds__(256, 1)
flash_kernel(const __nv_bfloat16* __restrict__ bq,
             const __nv_bfloat16* __restrict__ bk,
             const __nv_bfloat16* __restrict__ bvt,
             __nv_bfloat16* __restrict__ batt) {
    extern __shared__ __nv_bfloat16 smf[];
    __nv_bfloat16 *qh = smf,          *ql = smf + 8192;
    __nv_bfloat16 *kh = smf + 16384,  *kl = smf + 24576;
    __nv_bfloat16 *vh = smf + 32768,  *vl = smf + 40960;

    int tid = threadIdx.x, lane = tid & 31, w = tid >> 5;
    int qb = blockIdx.x, bhid = blockIdx.y;
    int b = bhid >> 4, h = bhid & 15, hk = h >> 2;

    const __nv_bfloat16 *gqh = bq,  *gql = bq + SZ_Q;
    const __nv_bfloat16 *gkh = bk,  *gkl = bk + SZ_K;
    const __nv_bfloat16 *gvh = bvt, *gvl = bvt + SZ_VT;

    for (int idx = tid; idx < 2048; idx += 256) {
        int row = idx >> 4, c4 = (idx & 15) * 4;
        long long ga = ((long long)((b * 1024 + qb * 128 + row) * 16 + h)) * 64 + c4;
        int sa = (c4 >> 4) * 2048 + swz(row, c4 & 15);
        *(uint2*)&qh[sa] = *(const uint2*)&gqh[ga];
        *(uint2*)&ql[sa] = *(const uint2*)&gql[ga];
    }

    uint32_t qbase  = (uint32_t)__cvta_generic_to_shared(qh);
    uint32_t qlbase = (uint32_t)__cvta_generic_to_shared(ql);
    uint32_t kbase  = (uint32_t)__cvta_generic_to_shared(kh);
    uint32_t klbase = (uint32_t)__cvta_generic_to_shared(kl);
    uint32_t vbase  = (uint32_t)__cvta_generic_to_shared(vh);
    uint32_t vlbase = (uint32_t)__cvta_generic_to_shared(vl);

    float oAcc[8][4];
    #pragma unroll
    for (int i = 0; i < 8; i++)
        #pragma unroll
        for (int e = 0; e < 4; e++) oAcc[i][e] = 0.f;
    float m_prev[2] = {-1e30f, -1e30f};
    float l_run[2] = {0.f, 0.f};

    int arow = w * 16 + (lane & 15), akk = (lane >> 4) * 8;
    int brow = (lane & 7) + ((lane & 16) ? 8 : 0);
    int bko = (lane & 8) ? 8 : 0;
    int r4 = lane >> 2, c2 = (lane & 3) * 2;

    for (int kb = 0; kb <= qb; kb++) {
        __syncthreads();
        for (int idx = tid; idx < 2048; idx += 256) {
            int row = idx >> 4, c4 = (idx & 15) * 4;
            long long ga = ((long long)((b * 1024 + kb * 128 + row) * 4 + hk)) * 64 + c4;
            int sa = (c4 >> 4) * 2048 + swz(row, c4 & 15);
            *(uint2*)&kh[sa] = *(const uint2*)&gkh[ga];
            *(uint2*)&kl[sa] = *(const uint2*)&gkl[ga];
        }
        for (int idx = tid; idx < 2048; idx += 256) {
            int vd = idx >> 5, t4 = (idx & 31) * 4;
            long long ga = ((long long)((b * 4 + hk) * 64 + vd)) * 1024 + kb * 128 + t4;
            int sa = (t4 >> 4) * 1024 + swz(vd, t4 & 15);
            *(uint2*)&vh[sa] = *(const uint2*)&gvh[ga];
            *(uint2*)&vl[sa] = *(const uint2*)&gvl[ga];
        }
        __syncthreads();

        float sAcc[16][4];
        #pragma unroll
        for (int t = 0; t < 16; t++)
            #pragma unroll
            for (int e = 0; e < 4; e++) sAcc[t][e] = 0.f;

        #pragma unroll
        for (int kk = 0; kk < 4; kk++) {
            uint32_t aH[4], aL[4];
            uint32_t qa = qbase + (uint32_t)(kk * 2048 + swz(arow, akk)) * 2;
            LDSM4(aH[0], aH[1], aH[2], aH[3], qa);
            uint32_t qla = qlbase + (uint32_t)(kk * 2048 + swz(arow, akk)) * 2;
            LDSM4(aL[0], aL[1], aL[2], aL[3], qla);
            #pragma unroll
            for (int nb = 0; nb < 8; nb++) {
                uint32_t off = (uint32_t)(kk * 2048 + swz(nb * 16 + brow, bko)) * 2;
                uint32_t r0, r1, r2, r3, s0, s1, s2, s3;
                LDSM4(r0, r1, r2, r3, kbase + off);
                LDSM4(s0, s1, s2, s3, klbase + off);
                MMAS(sAcc[2 * nb],     aH, r0, r1);
                MMAS(sAcc[2 * nb],     aH, s0, s1);
                MMAS(sAcc[2 * nb],     aL, r0, r1);
                MMAS(sAcc[2 * nb + 1], aH, r2, r3);
                MMAS(sAcc[2 * nb + 1], aH, s2, s3);
                MMAS(sAcc[2 * nb + 1], aL, r2, r3);
            }
        }

        #pragma unroll
        for (int t = 0; t < 16; t++)
            #pragma unroll
            for (int e = 0; e < 4; e++) {
                float v = sAcc[t][e] * 0.125f;
                if (kb == qb) {
                    int col = t * 8 + c2 + (e & 1);
                    int rowl = w * 16 + r4 + ((e >> 1) ? 8 : 0);
                    if (col > rowl) v = -1e30f;
                }
                sAcc[t][e] = v;
            }

        float m0 = -1e30f, m1 = -1e30f;
        #pragma unroll
        for (int t = 0; t < 16; t++) {
            m0 = fmaxf(m0, fmaxf(sAcc[t][0], sAcc[t][1]));
            m1 = fmaxf(m1, fmaxf(sAcc[t][2], sAcc[t][3]));
        }
        m0 = fmaxf(m0, __shfl_xor_sync(0xFFFFFFFFu, m0, 1));
        m0 = fmaxf(m0, __shfl_xor_sync(0xFFFFFFFFu, m0, 2));
        m1 = fmaxf(m1, __shfl_xor_sync(0xFFFFFFFFu, m1, 1));
        m1 = fmaxf(m1, __shfl_xor_sync(0xFFFFFFFFu, m1, 2));
        float mn0 = fmaxf(m_prev[0], m0), mn1 = fmaxf(m_prev[1], m1);
        float al0 = __expf(m_prev[0] - mn0), al1 = __expf(m_prev[1] - mn1);
        float rs0 = 0.f, rs1 = 0.f;
        #pragma unroll
        for (int t = 0; t < 16; t++) {
            sAcc[t][0] = __expf(sAcc[t][0] - mn0);
            sAcc[t][1] = __expf(sAcc[t][1] - mn0);
            sAcc[t][2] = __expf(sAcc[t][2] - mn1);
            sAcc[t][3] = __expf(sAcc[t][3] - mn1);
            rs0 += sAcc[t][0] + sAcc[t][1];
            rs1 += sAcc[t][2] + sAcc[t][3];
        }
        rs0 += __shfl_xor_sync(0xFFFFFFFFu, rs0, 1);
        rs0 += __shfl_xor_sync(0xFFFFFFFFu, rs0, 2);
        rs1 += __shfl_xor_sync(0xFFFFFFFFu, rs1, 1);
        rs1 += __shfl_xor_sync(0xFFFFFFFFu, rs1, 2);
        l_run[0] = l_run[0] * al0 + rs0;
        l_run[1] = l_run[1] * al1 + rs1;
        m_prev[0] = mn0; m_prev[1] = mn1;
        #pragma unroll
        for (int ot = 0; ot < 8; ot++) {
            oAcc[ot][0] *= al0; oAcc[ot][1] *= al0;
            oAcc[ot][2] *= al1; oAcc[ot][3] *= al1;
        }

        #pragma unroll
        for (int kk = 0; kk < 8; kk++) {
            float* sA = sAcc[2 * kk];
            float* sB = sAcc[2 * kk + 1];
            uint32_t aH[4], aL[4];
            aH[0] = pack2(sA[0], sA[1]); aH[1] = pack2(sA[2], sA[3]);
            aH[2] = pack2(sB[0], sB[1]); aH[3] = pack2(sB[2], sB[3]);
            aL[0] = pack2(lopart(sA[0]), lopart(sA[1]));
            aL[1] = pack2(lopart(sA[2]), lopart(sA[3]));
            aL[2] = pack2(lopart(sB[0]), lopart(sB[1]));
            aL[3] = pack2(lopart(sB[2]), lopart(sB[3]));
            #pragma unroll
            for (int vb = 0; vb < 4; vb++) {
                uint32_t off = (uint32_t)(kk * 1024 + swz(vb * 16 + brow, bko)) * 2;
                uint32_t r0, r1, r2, r3, s0, s1, s2, s3;
                LDSM4(r0, r1, r2, r3, vbase + off);
                LDSM4(s0, s1, s2, s3, vlbase + off);
                MMAS(oAcc[2 * vb],     aH, r0, r1);
                MMAS(oAcc[2 * vb],     aH, s0, s1);
                MMAS(oAcc[2 * vb],     aL, r0, r1);
                MMAS(oAcc[2 * vb + 1], aH, r2, r3);
                MMAS(oAcc[2 * vb + 1], aH, s2, s3);
                MMAS(oAcc[2 * vb + 1], aL, r2, r3);
            }
        }
    }

    float inv0 = 1.f / l_run[0], inv1 = 1.f / l_run[1];
    __nv_bfloat16 *oh = batt, *ol = batt + SZ_ATT;
    #pragma unroll
    for (int ot = 0; ot < 8; ot++)
        #pragma unroll
        for (int e = 0; e < 4; e++) {
            float v = oAcc[ot][e] * ((e >> 1) ? inv1 : inv0);
            int rowl = w * 16 + r4 + ((e >> 1) ? 8 : 0);
            long long oi = ((long long)(b * 1024 + qb * 128 + rowl)) * 1024
                           + h * 64 + ot * 8 + c2 + (e & 1);
            __nv_bfloat16 hb = __float2bfloat16(v);
            oh[oi] = hb;
            ol[oi] = __float2bfloat16(v - __bfloat162float(hb));
        }
}

// ---------------- launch ----------------
extern "C" void kernel_launch(void* const* d_in, const int* in_sizes, int n_in,
                              void* d_out, int out_size) {
    const float* x   = (const float*)d_in[0];
    const float* wq  = (const float*)d_in[1];
    const float* wk  = (const float*)d_in[2];
    const float* wv  = (const float*)d_in[3];
    const float* wo  = (const float*)d_in[4];
    const float* rw  = (const float*)d_in[5];
    const float* rb  = (const float*)d_in[6];
    const float* w1  = (const float*)d_in[7];
    const float* w2  = (const float*)d_in[8];
    const float* w3  = (const float*)d_in[9];
    const float* ns1 = (const float*)d_in[10];
    const float* ns2 = (const float*)d_in[11];

    float *qkv, *x1, *h2, *grp, *t1, *t2, *eout;
    cudaGetSymbolAddress((void**)&qkv, g_qkv);
    cudaGetSymbolAddress((void**)&x1, g_x1);
    cudaGetSymbolAddress((void**)&h2, g_h2);
    cudaGetSymbolAddress((void**)&grp, g_grp);
    cudaGetSymbolAddress((void**)&t1, g_t1);
    cudaGetSymbolAddress((void**)&t2, g_t2);
    cudaGetSymbolAddress((void**)&eout, g_eout);

    __nv_bfloat16 *bh, *bq, *bk, *bvt, *batt, *bgrp, *bt1;
    __nv_bfloat16 *wqkvT, *woT, *w1T, *w2T, *w3T;
    cudaGetSymbolAddress((void**)&bh, b_h);
    cudaGetSymbolAddress((void**)&bq, b_q);
    cudaGetSymbolAddress((void**)&bk, b_k);
    cudaGetSymbolAddress((void**)&bvt, b_vt);
    cudaGetSymbolAddress((void**)&batt, b_attn);
    cudaGetSymbolAddress((void**)&bgrp, b_grp);
    cudaGetSymbolAddress((void**)&bt1, b_t1);
    cudaGetSymbolAddress((void**)&wqkvT, b_wqkvT);
    cudaGetSymbolAddress((void**)&woT, b_woT);
    cudaGetSymbolAddress((void**)&w1T, b_w1T);
    cudaGetSymbolAddress((void**)&w2T, b_w2T);
    cudaGetSymbolAddress((void**)&w3T, b_w3T);

    const int SM128 = 3 * (2 * 128 * 16 + 2 * 128 * 16) * 2;    // 49152
    const int SM256 = 3 * (2 * 128 * 16 + 2 * 256 * 16) * 2;    // 73728
    cudaFuncSetAttribute(bgemm_kernel<128>, cudaFuncAttributeMaxDynamicSharedMemorySize, SM128);
    cudaFuncSetAttribute(bgemm_kernel<256>, cudaFuncAttributeMaxDynamicSharedMemorySize, SM256);
    cudaFuncSetAttribute(flash_kernel, cudaFuncAttributeMaxDynamicSharedMemorySize, 98304);

    auto tconv = [&](const float* s, __nv_bfloat16* d, __nv_bfloat16* dlo,
                     int R, int C, int lds, long long so, long long si, int zdiv, int Z) {
        dim3 grid((C + 31) / 32, (R + 31) / 32, Z);
        tconv_kernel<<<grid, dim3(32, 8)>>>(s, d, dlo, R, C, lds, so, si, zdiv);
    };
    auto bgemm = [&](int NT, int M, int N, int K,
                     const __nv_bfloat16* A, long long szA, int lda, long long soA, long long siA, int divA,
                     const __nv_bfloat16* B, long long szB, int ldb, long long soB, long long siB, int divB,
                     float* C, int ldc, long long soC, long long siC, int divC,
                     int Z, int zdiv, int epi, const float* R) {
        dim3 grid(N / NT, M / 128, Z);
        if (NT == 128)
            bgemm_kernel<128><<<grid, 256, SM128>>>(M, N, K, A, A + szA, lda, soA, siA, divA,
                B, B + szB, ldb, soB, siB, divB, C, ldc, soC, siC, divC, zdiv, epi, R);
        else
            bgemm_kernel<256><<<grid, 256, SM256>>>(M, N, K, A, A + szA, lda, soA, siA, divA,
                B, B + szB, ldb, soB, siB, divB, C, ldc, soC, siC, divC, zdiv, epi, R);
    };

    // pack wq|wk|wv transposed into one NT-layout buffer [1536][1024] hi/lo
    tconv(wq, wqkvT,               wqkvT + SZ_QKVW,               1024, 1024, 1024, 0, 0, 1, 1);
    tconv(wk, wqkvT + 1024 * 1024, wqkvT + SZ_QKVW + 1024 * 1024, 1024, 256, 256, 0, 0, 1, 1);
    tconv(wv, wqkvT + 1280 * 1024, wqkvT + SZ_QKVW + 1280 * 1024, 1024, 256, 256, 0, 0, 1, 1);
    tconv(wo, woT, woT + SZ_WOT, 1024, 1024, 1024, 0, 0, 1, 1);
    tconv(w1, w1T, w1T + SZ_W1T, 1024, 2048, 2048, (long long)DD * HIDn, 0, 1, En);
    tconv(w2, w2T, w2T + SZ_W1T, 1024, 2048, 2048, (long long)DD * HIDn, 0, 1, En);
    tconv(w3, w3T, w3T + SZ_W3T, 2048, 1024, 1024, (long long)HIDn * DD, 0, 1, En);

    // ---- attention ----
    rmsnorm_kernel<<<NTOK, 256>>>(x, ns1, nullptr, bh, bh + SZ_H);
    bgemm(128, NTOK, 1536, 1024, bh, SZ_H, 1024, 0, 0, 1,
          wqkvT, SZ_QKVW, 1024, 0, 0, 1, qkv, 1536, 0, 0, 1, 1, 1, 0, nullptr);
    {
        long long tq = (long long)NTOK * HQn * 32;
        rope_kernel<<<(unsigned)((tq + 255) / 256), 256>>>(qkv, 0, HQn, tq);
        long long tk = (long long)NTOK * HKVn * 32;
        rope_kernel<<<(unsigned)((tk + 255) / 256), 256>>>(qkv, 1024, HKVn, tk);
    }
    sconv_kernel<<<(SZ_Q + 255) / 256, 256>>>(qkv, 1536, 1024, bq, bq + SZ_Q, SZ_Q);
    sconv_kernel<<<(SZ_K + 255) / 256, 256>>>(qkv + 1024, 1536, 256, bk, bk + SZ_K, SZ_K);
    tconv(qkv + 1280, bvt, bvt + SZ_VT, TT, VDn, 1536,
          (long long)TT * 1536, VDn, HKVn, BB * HKVn);

    flash_kernel<<<dim3(8, 32), 256, 98304>>>(bq, bk, bvt, batt);

    bgemm(128, NTOK, 1024, 1024, batt, SZ_ATT, 1024, 0, 0, 1,
          woT, SZ_WOT, 1024, 0, 0, 1, x1, 1024, 0, 0, 1, 1, 1, 2, x);

    // ---- MoE ----
    rmsnorm_kernel<<<NTOK, 256>>>(x1, ns2, h2, nullptr, nullptr);
    router_kernel<<<NTOK, 256>>>(rw, rb);
    scan_kernel<<<1, 256>>>();
    {
        long long n = (long long)En * CAPn * DD;
        zero_kernel<<<(unsigned)((n + 255) / 256), 256>>>(grp, n);
    }
    scatter_kernel<<<NTOK * 2, 256>>>();
    conv4_kernel<<<(SZ_GRP / 4 + 255) / 256, 256>>>(grp, bgrp, bgrp + SZ_GRP, SZ_GRP / 4);
    bgemm(256, CAPn, HIDn, DD,
          bgrp, SZ_GRP, 1024, (long long)CAPn * DD, 0, 1,
          w1T, SZ_W1T, 1024, (long long)HIDn * DD, 0, 1,
          t1, HIDn, (long long)CAPn * HIDn, 0, 1, En, 1, 0, nullptr);
    bgemm(256, CAPn, HIDn, DD,
          bgrp, SZ_GRP, 1024, (long long)CAPn * DD, 0, 1,
          w2T, SZ_W1T, 1024, (long long)HIDn * DD, 0, 1,
          t2, HIDn, (long long)CAPn * HIDn, 0, 1, En, 1, 0, nullptr);
    gelu_mul_kernel<<<(SZ_T1 / 4 + 255) / 256, 256>>>(bt1, bt1 + SZ_T1, SZ_T1 / 4);
    bgemm(256, CAPn, DD, HIDn,
          bt1, SZ_T1, HIDn, (long long)CAPn * HIDn, 0, 1,
          w3T, SZ_W3T, 2048, (long long)DD * HIDn, 0, 1,
          eout, DD, (long long)CAPn * DD, 0, 1, En, 1, 0, nullptr);
    combine_kernel<<<NTOK, 256>>>((float*)d_out);
}

// round 7
// speedup vs baseline: 1.4716x; 1.4716x over previous
#include <cuda_runtime.h>
#include <cuda_bf16.h>
#include <math.h>
#include <stdint.h>

// ---------------- problem dims ----------------
#define BB    2
#define TT    1024
#define NTOK  2048
#define DD    1024
#define HQn   16
#define HKVn  4
#define KDn   64
#define VDn   64
#define Gn    4
#define En    8
#define CAPn  1024
#define HIDn  2048

// ---------------- fp32 scratch ----------------
__device__ float g_qkv [NTOK*1536];
__device__ float g_x1  [NTOK*DD];
__device__ float g_h2  [NTOK*DD];
__device__ float g_grp [En*CAPn*DD];
__device__ float g_t1  [En*CAPn*HIDn];
__device__ float g_t2  [En*CAPn*HIDn];
__device__ float g_eout[En*CAPn*DD];
__device__ int   g_assign[NTOK*2];
__device__ float g_gate  [NTOK*2];
__device__ int   g_slot  [NTOK*2];
__device__ int   g_keep  [NTOK*2];

// ---------------- bf16 hi/lo scratch ----------------
#define SZ_H    (NTOK*DD)
#define SZ_Q    (NTOK*HQn*KDn)
#define SZ_K    (NTOK*HKVn*KDn)
#define SZ_VT   (BB*HKVn*VDn*TT)
#define SZ_ATT  (NTOK*DD)
#define SZ_GRP  (En*CAPn*DD)
#define SZ_T1   (En*CAPn*HIDn)
#define SZ_QKVW (1536*DD)
#define SZ_WOT  (DD*DD)
#define SZ_W1T  (En*HIDn*DD)
#define SZ_W3T  (En*DD*HIDn)

__device__ __nv_bfloat16 b_h    [2*SZ_H];
__device__ __nv_bfloat16 b_q    [2*SZ_Q];
__device__ __nv_bfloat16 b_k    [2*SZ_K];
__device__ __nv_bfloat16 b_vt   [2*SZ_VT];
__device__ __nv_bfloat16 b_attn [2*SZ_ATT];
__device__ __nv_bfloat16 b_grp  [2*SZ_GRP];
__device__ __nv_bfloat16 b_t1   [2*SZ_T1];
__device__ __nv_bfloat16 b_wqkvT[2*SZ_QKVW];
__device__ __nv_bfloat16 b_woT  [2*SZ_WOT];
__device__ __nv_bfloat16 b_w1T  [2*SZ_W1T];
__device__ __nv_bfloat16 b_w2T  [2*SZ_W1T];
__device__ __nv_bfloat16 b_w3T  [2*SZ_W3T];

// ---------------- helpers ----------------
__device__ __forceinline__ uint32_t pack2(float a, float b) {
    __nv_bfloat162 t = __floats2bfloat162_rn(a, b);
    return *reinterpret_cast<uint32_t*>(&t);
}
__device__ __forceinline__ float lopart(float x) {
    return x - __bfloat162float(__float2bfloat16(x));
}
__device__ __forceinline__ int swz(int row, int k) {
    return row * 16 + ((((k >> 3) ^ (row >> 2)) & 1) << 3) + (k & 7);
}

#define LDSM4(r0,r1,r2,r3,a) \
  asm volatile("ldmatrix.sync.aligned.m8n8.x4.shared.b16 {%0,%1,%2,%3}, [%4];" \
    : "=r"(r0), "=r"(r1), "=r"(r2), "=r"(r3) : "r"(a))

#define MMA16816(d, a, b) \
  asm volatile("mma.sync.aligned.m16n8k16.row.col.f32.bf16.bf16.f32 " \
    "{%0,%1,%2,%3}, {%4,%5,%6,%7}, {%8,%9}, {%0,%1,%2,%3};" \
    : "+f"(d[0]), "+f"(d[1]), "+f"(d[2]), "+f"(d[3]) \
    : "r"(a[0]), "r"(a[1]), "r"(a[2]), "r"(a[3]), "r"(b[0]), "r"(b[1]))

#define MMAS(d, a, b0, b1) \
  asm volatile("mma.sync.aligned.m16n8k16.row.col.f32.bf16.bf16.f32 " \
    "{%0,%1,%2,%3}, {%4,%5,%6,%7}, {%8,%9}, {%0,%1,%2,%3};" \
    : "+f"(d[0]), "+f"(d[1]), "+f"(d[2]), "+f"(d[3]) \
    : "r"(a[0]), "r"(a[1]), "r"(a[2]), "r"(a[3]), "r"(b0), "r"(b1))

// ---------------- small kernels ----------------
__global__ void rmsnorm_kernel(const float* __restrict__ x,
                               const float* __restrict__ scale,
                               float* __restrict__ outF,
                               __nv_bfloat16* __restrict__ outH,
                               __nv_bfloat16* __restrict__ outL) {
    int row = blockIdx.x;
    const float* xr = x + (long long)row * DD;
    __shared__ float red[256];
    float s = 0.f;
    for (int d = threadIdx.x; d < DD; d += 256) { float v = xr[d]; s += v * v; }
    red[threadIdx.x] = s; __syncthreads();
    for (int o = 128; o > 0; o >>= 1) {
        if (threadIdx.x < o) red[threadIdx.x] += red[threadIdx.x + o];
        __syncthreads();
    }
    float inv = 1.0f / sqrtf(red[0] / (float)DD + 1e-6f);
    for (int d = threadIdx.x; d < DD; d += 256) {
        float v = xr[d] * inv * scale[d];
        if (outF) outF[(long long)row * DD + d] = v;
        if (outH) {
            __nv_bfloat16 hb = __float2bfloat16(v);
            outH[(long long)row * DD + d] = hb;
            outL[(long long)row * DD + d] = __float2bfloat16(v - __bfloat162float(hb));
        }
    }
}

__global__ void rope_kernel(float* __restrict__ p, int colBase, int H, long long total) {
    long long i = (long long)blockIdx.x * 256 + threadIdx.x;
    if (i >= total) return;
    int j = (int)(i & 31);
    long long nh = i >> 5;
    int h = (int)(nh % H);
    long long n = nh / H;
    int t = (int)(n % TT);
    float* v = p + n * 1536 + colBase + h * 64;
    float theta = powf(10000.0f, -(2.0f * j) / 64.0f);
    float a = (float)t * theta;
    float c = cosf(a), s = sinf(a);
    float x1 = v[j], x2 = v[j + 32];
    v[j]      = x1 * c - x2 * s;
    v[j + 32] = x2 * c + x1 * s;
}

__global__ void router_kernel(const float* __restrict__ rw, const float* __restrict__ rb) {
    int t = blockIdx.x;
    const float* xr = g_h2 + (long long)t * DD;
    float part[En];
    #pragma unroll
    for (int e = 0; e < En; e++) part[e] = 0.f;
    for (int d = threadIdx.x; d < DD; d += 256) {
        float xv = xr[d];
        #pragma unroll
        for (int e = 0; e < En; e++) part[e] += xv * rw[d * En + e];
    }
    __shared__ float red[En][8];
    int lane = threadIdx.x & 31, warp = threadIdx.x >> 5;
    #pragma unroll
    for (int e = 0; e < En; e++) {
        float v = part[e];
        for (int o = 16; o > 0; o >>= 1) v += __shfl_down_sync(0xffffffffu, v, o);
        if (lane == 0) red[e][warp] = v;
    }
    __syncthreads();
    if (threadIdx.x == 0) {
        float lg[En];
        #pragma unroll
        for (int e = 0; e < En; e++) {
            float s = 0.f;
            for (int w = 0; w < 8; w++) s += red[e][w];
            lg[e] = s + rb[e];
        }
        int i0 = 0;
        for (int e = 1; e < En; e++) if (lg[e] > lg[i0]) i0 = e;
        int i1 = -1;
        for (int e = 0; e < En; e++) {
            if (e == i0) continue;
            if (i1 < 0 || lg[e] > lg[i1]) i1 = e;
        }
        float e1 = expf(lg[i1] - lg[i0]);
        float denom = 1.f + e1;
        g_assign[2 * t] = i0;     g_assign[2 * t + 1] = i1;
        g_gate[2 * t] = 1.f / denom; g_gate[2 * t + 1] = e1 / denom;
    }
}

__global__ void scan_kernel() {
    int lane = threadIdx.x & 31;
    int e = threadIdx.x >> 5;
    uint32_t mle = 0xFFFFFFFFu >> (31 - lane);
    int base0 = 0, base1 = 0;
    for (int chunk = 0; chunk < NTOK / 32; chunk++) {
        int t = chunk * 32 + lane;
        int a0 = g_assign[2 * t], a1 = g_assign[2 * t + 1];
        uint32_t b0 = __ballot_sync(0xFFFFFFFFu, a0 == e);
        uint32_t b1 = __ballot_sync(0xFFFFFFFFu, a1 == e);
        int incl0 = __popc(b0 & mle);
        int incl1 = __popc(b1 & mle);
        if (a0 == e) {
            int p0 = base0 + incl0;
            g_slot[2 * t] = p0; g_keep[2 * t] = (p0 < CAPn) ? 1 : 0;
        }
        if (a1 == e) {
            int p1 = (base0 + incl0) + (base1 + incl1);
            g_slot[2 * t + 1] = p1; g_keep[2 * t + 1] = (p1 < CAPn) ? 1 : 0;
        }
        base0 += __popc(b0); base1 += __popc(b1);
    }
}

__global__ void zero_kernel(float* __restrict__ p, long long n) {
    long long i = (long long)blockIdx.x * 256 + threadIdx.x;
    if (i < n) p[i] = 0.f;
}

__global__ void scatter_kernel() {
    int i = blockIdx.x;
    if (!g_keep[i]) return;
    int t = i >> 1;
    int e = g_assign[i], s = g_slot[i];
    float* dst = g_grp + ((long long)e * CAPn + s) * DD;
    const float* src = g_h2 + (long long)t * DD;
    for (int d = threadIdx.x; d < DD; d += 256) atomicAdd(&dst[d], src[d]);
}

__global__ void gelu_mul_kernel(__nv_bfloat16* __restrict__ oh,
                                __nv_bfloat16* __restrict__ ol, long long n4) {
    long long i = (long long)blockIdx.x * 256 + threadIdx.x;
    if (i >= n4) return;
    float4 a = *(const float4*)&g_t1[i * 4];
    float4 b = *(const float4*)&g_t2[i * 4];
    float r[4];
    float xs[4] = {a.x * b.x, a.y * b.y, a.z * b.z, a.w * b.w};
    #pragma unroll
    for (int j = 0; j < 4; j++) {
        float x = xs[j];
        float inner = 0.7978845608028654f * (x + 0.044715f * x * x * x);
        r[j] = 0.5f * x * (1.0f + tanhf(inner));
    }
    uint2 hv, lv;
    hv.x = pack2(r[0], r[1]); hv.y = pack2(r[2], r[3]);
    lv.x = pack2(lopart(r[0]), lopart(r[1]));
    lv.y = pack2(lopart(r[2]), lopart(r[3]));
    *(uint2*)&oh[i * 4] = hv;
    *(uint2*)&ol[i * 4] = lv;
}

__global__ void combine_kernel(float* __restrict__ out) {
    int t = blockIdx.x;
    float gte0 = g_gate[2 * t], gte1 = g_gate[2 * t + 1];
    const float* s0 = g_keep[2 * t]
        ? g_eout + ((long long)g_assign[2 * t] * CAPn + g_slot[2 * t]) * DD
        : g_h2 + (long long)t * DD;
    const float* s1 = g_keep[2 * t + 1]
        ? g_eout + ((long long)g_assign[2 * t + 1] * CAPn + g_slot[2 * t + 1]) * DD
        : g_h2 + (long long)t * DD;
    const float* xr = g_x1 + (long long)t * DD;
    float* orow = out + (long long)t * DD;
    for (int d = threadIdx.x; d < DD; d += 256)
        orow[d] = xr[d] + gte0 * s0[d] + gte1 * s1[d];
}

__global__ void conv4_kernel(const float* __restrict__ src, __nv_bfloat16* __restrict__ hi,
                             __nv_bfloat16* __restrict__ lo, long long n4) {
    long long i = (long long)blockIdx.x * 256 + threadIdx.x;
    if (i >= n4) return;
    float4 v = *(const float4*)&src[i * 4];
    uint2 hv, lv;
    hv.x = pack2(v.x, v.y); hv.y = pack2(v.z, v.w);
    lv.x = pack2(lopart(v.x), lopart(v.y));
    lv.y = pack2(lopart(v.z), lopart(v.w));
    *(uint2*)&hi[i * 4] = hv;
    *(uint2*)&lo[i * 4] = lv;
}

__global__ void sconv_kernel(const float* __restrict__ src, int srcStride, int width,
                             __nv_bfloat16* __restrict__ hi, __nv_bfloat16* __restrict__ lo,
                             long long n) {
    long long i = (long long)blockIdx.x * 256 + threadIdx.x;
    if (i >= n) return;
    int row = (int)(i / width), col = (int)(i % width);
    float v = src[(long long)row * srcStride + col];
    __nv_bfloat16 h = __float2bfloat16(v);
    hi[i] = h; lo[i] = __float2bfloat16(v - __bfloat162float(h));
}

__global__ void tconv_kernel(const float* __restrict__ src, __nv_bfloat16* __restrict__ hi,
                             __nv_bfloat16* __restrict__ lo, int R, int C, int lds,
                             long long so, long long si, int zdiv) {
    int z = blockIdx.z;
    src += (long long)(z / zdiv) * so + (long long)(z % zdiv) * si;
    long long d = (long long)z * R * C;
    hi += d; lo += d;
    __shared__ float t[32][33];
    int c0 = blockIdx.x * 32, r0 = blockIdx.y * 32;
    for (int i = threadIdx.y; i < 32; i += 8) {
        int r = r0 + i, c = c0 + threadIdx.x;
        if (r < R && c < C) t[i][threadIdx.x] = src[(long long)r * lds + c];
    }
    __syncthreads();
    for (int i = threadIdx.y; i < 32; i += 8) {
        int c = c0 + i, r = r0 + threadIdx.x;
        if (r < R && c < C) {
            float v = t[threadIdx.x][i];
            __nv_bfloat16 hh = __float2bfloat16(v);
            hi[(long long)c * R + r] = hh;
            lo[(long long)c * R + r] = __float2bfloat16(v - __bfloat162float(hh));
        }
    }
}

// ---------------- bf16 split-precision tensor-core GEMM (NT), 3-stage ----------------
// R3-proven structure: 128x128 CTA tile, 8 warps (2m x 4n), warp tile 64x32.
#define TILEE (128*16)

__global__ void __launch_bounds__(256)
bgemm_kernel(int M, int N, int K,
             const __nv_bfloat16* __restrict__ Ah, const __nv_bfloat16* __restrict__ Al,
             int lda, long long soA, long long siA, int divA,
             const __nv_bfloat16* __restrict__ Bh, const __nv_bfloat16* __restrict__ Bl,
             int ldb, long long soB, long long siB, int divB,
             float* __restrict__ C, int ldc, long long soC, long long siC, int divC,
             int zdiv, int epi, const float* __restrict__ Rz) {
    int z = blockIdx.z;
    long long offA = (long long)(z / zdiv) * soA + (long long)((z % zdiv) / divA) * siA;
    long long offB = (long long)(z / zdiv) * soB + (long long)((z % zdiv) / divB) * siB;
    long long offC = (long long)(z / zdiv) * soC + (long long)((z % zdiv) / divC) * siC;
    Ah += offA; Al += offA; Bh += offB; Bl += offB; C += offC;
    const float* Rp = Rz ? (Rz + offC) : (const float*)0;

    int m0 = blockIdx.y * 128, n0 = blockIdx.x * 128;
    int tid = threadIdx.x;

    __shared__ __nv_bfloat16 sm[3][4][TILEE];   // 48KB
    uint32_t sbase = (uint32_t)__cvta_generic_to_shared(&sm[0][0][0]);

    int lr = tid >> 1, lc = tid & 1;
    const __nv_bfloat16* gAh = Ah + (long long)(m0 + lr) * lda + lc * 8;
    const __nv_bfloat16* gAl = Al + (long long)(m0 + lr) * lda + lc * 8;
    int brow = n0 + lr;
    const __nv_bfloat16* gBh = Bh + (long long)brow * ldb + lc * 8;
    const __nv_bfloat16* gBl = Bl + (long long)brow * ldb + lc * 8;
    uint32_t soff = (uint32_t)swz(lr, lc * 8) * 2;

    int KT = K / 16;

    auto prefetch = [&](int kt, int st) {
        long long ko = (long long)kt * 16;
        uint32_t b0 = sbase + (uint32_t)(st * 4 * TILEE * 2);
        asm volatile("cp.async.cg.shared.global [%0], [%1], 16;"
                     :: "r"(b0 + soff), "l"(gAh + ko));
        asm volatile("cp.async.cg.shared.global [%0], [%1], 16;"
                     :: "r"(b0 + (uint32_t)(TILEE * 2) + soff), "l"(gAl + ko));
        asm volatile("cp.async.cg.shared.global [%0], [%1], 16;"
                     :: "r"(b0 + (uint32_t)(2 * TILEE * 2) + soff), "l"(gBh + ko));
        asm volatile("cp.async.cg.shared.global [%0], [%1], 16;"
                     :: "r"(b0 + (uint32_t)(3 * TILEE * 2) + soff), "l"(gBl + ko));
        asm volatile("cp.async.commit_group;");
    };

    float acc[4][4][4];
    #pragma unroll
    for (int i = 0; i < 4; i++)
        #pragma unroll
        for (int j = 0; j < 4; j++)
            #pragma unroll
            for (int e = 0; e < 4; e++) acc[i][j][e] = 0.f;

    int lane = tid & 31, wid = tid >> 5;
    int wm = wid & 1, wn = wid >> 1;
    int arow = wm * 64 + (lane & 15);
    int ak = (lane >> 4) * 8;
    int brow2 = wn * 32 + (lane & 7) + ((lane & 16) ? 8 : 0);
    int bk = (lane & 8) ? 8 : 0;

    prefetch(0, 0);
    if (KT > 1) prefetch(1, 1);

    for (int kt = 0; kt < KT; kt++) {
        if (kt + 2 < KT) {
            prefetch(kt + 2, (kt + 2) % 3);
            asm volatile("cp.async.wait_group 2;");
        } else if (kt + 1 < KT) {
            asm volatile("cp.async.wait_group 1;");
        } else {
            asm volatile("cp.async.wait_group 0;");
        }
        __syncthreads();

        uint32_t base = sbase + (uint32_t)((kt % 3) * 4 * TILEE * 2);
        uint32_t fAh[4][4], fAl[4][4], fBh[4][2], fBl[4][2];
        #pragma unroll
        for (int mi = 0; mi < 4; mi++) {
            uint32_t ao = base + (uint32_t)swz(arow + mi * 16, ak) * 2;
            LDSM4(fAh[mi][0], fAh[mi][1], fAh[mi][2], fAh[mi][3], ao);
            LDSM4(fAl[mi][0], fAl[mi][1], fAl[mi][2], fAl[mi][3], ao + (uint32_t)(TILEE * 2));
        }
        #pragma unroll
        for (int nj = 0; nj < 2; nj++) {
            uint32_t bo = base + (uint32_t)(2 * TILEE * 2) + (uint32_t)swz(brow2 + nj * 16, bk) * 2;
            uint32_t r0, r1, r2, r3;
            LDSM4(r0, r1, r2, r3, bo);
            fBh[nj * 2][0] = r0; fBh[nj * 2][1] = r1;
            fBh[nj * 2 + 1][0] = r2; fBh[nj * 2 + 1][1] = r3;
            LDSM4(r0, r1, r2, r3, bo + (uint32_t)(TILEE * 2));
            fBl[nj * 2][0] = r0; fBl[nj * 2][1] = r1;
            fBl[nj * 2 + 1][0] = r2; fBl[nj * 2 + 1][1] = r3;
        }
        #pragma unroll
        for (int mi = 0; mi < 4; mi++)
            #pragma unroll
            for (int ni = 0; ni < 4; ni++) {
                MMA16816(acc[mi][ni], fAh[mi], fBh[ni]);
                MMA16816(acc[mi][ni], fAh[mi], fBl[ni]);
                MMA16816(acc[mi][ni], fAl[mi], fBh[ni]);
            }
        __syncthreads();
    }

    int r4 = lane >> 2, c2 = (lane & 3) * 2;
    #pragma unroll
    for (int mi = 0; mi < 4; mi++)
        #pragma unroll
        for (int ni = 0; ni < 4; ni++) {
            int row = m0 + wm * 64 + mi * 16 + r4;
            int col = n0 + wn * 32 + ni * 8 + c2;
            #pragma unroll
            for (int e = 0; e < 4; e++) {
                int rr = row + (e >> 1) * 8;
                int cc = col + (e & 1);
                float v = acc[mi][ni][e];
                if (epi == 2) v += Rp[(long long)rr * ldc + cc];
                C[(long long)rr * ldc + cc] = v;
            }
        }
}

// ---------------- flash attention ----------------
__global__ void __launch_bounds__(256, 1)
flash_kernel(const __nv_bfloat16* __restrict__ bq,
             const __nv_bfloat16* __restrict__ bk,
             const __nv_bfloat16* __restrict__ bvt,
             __nv_bfloat16* __restrict__ batt) {
    extern __shared__ __nv_bfloat16 smf[];
    __nv_bfloat16 *qh = smf,          *ql = smf + 8192;
    __nv_bfloat16 *kh = smf + 16384,  *kl = smf + 24576;
    __nv_bfloat16 *vh = smf + 32768,  *vl = smf + 40960;

    int tid = threadIdx.x, lane = tid & 31, w = tid >> 5;
    int qb = blockIdx.x, bhid = blockIdx.y;
    int b = bhid >> 4, h = bhid & 15, hk = h >> 2;

    const __nv_bfloat16 *gqh = bq,  *gql = bq + SZ_Q;
    const __nv_bfloat16 *gkh = bk,  *gkl = bk + SZ_K;
    const __nv_bfloat16 *gvh = bvt, *gvl = bvt + SZ_VT;

    for (int idx = tid; idx < 2048; idx += 256) {
        int row = idx >> 4, c4 = (idx & 15) * 4;
        long long ga = ((long long)((b * 1024 + qb * 128 + row) * 16 + h)) * 64 + c4;
        int sa = (c4 >> 4) * 2048 + swz(row, c4 & 15);
        *(uint2*)&qh[sa] = *(const uint2*)&gqh[ga];
        *(uint2*)&ql[sa] = *(const uint2*)&gql[ga];
    }

    uint32_t qbase  = (uint32_t)__cvta_generic_to_shared(qh);
    uint32_t qlbase = (uint32_t)__cvta_generic_to_shared(ql);
    uint32_t kbase  = (uint32_t)__cvta_generic_to_shared(kh);
    uint32_t klbase = (uint32_t)__cvta_generic_to_shared(kl);
    uint32_t vbase  = (uint32_t)__cvta_generic_to_shared(vh);
    uint32_t vlbase = (uint32_t)__cvta_generic_to_shared(vl);

    float oAcc[8][4];
    #pragma unroll
    for (int i = 0; i < 8; i++)
        #pragma unroll
        for (int e = 0; e < 4; e++) oAcc[i][e] = 0.f;
    float m_prev[2] = {-1e30f, -1e30f};
    float l_run[2] = {0.f, 0.f};

    int arow = w * 16 + (lane & 15), akk = (lane >> 4) * 8;
    int brow = (lane & 7) + ((lane & 16) ? 8 : 0);
    int bko = (lane & 8) ? 8 : 0;
    int r4 = lane >> 2, c2 = (lane & 3) * 2;

    for (int kb = 0; kb <= qb; kb++) {
        __syncthreads();
        for (int idx = tid; idx < 2048; idx += 256) {
            int row = idx >> 4, c4 = (idx & 15) * 4;
            long long ga = ((long long)((b * 1024 + kb * 128 + row) * 4 + hk)) * 64 + c4;
            int sa = (c4 >> 4) * 2048 + swz(row, c4 & 15);
            *(uint2*)&kh[sa] = *(const uint2*)&gkh[ga];
            *(uint2*)&kl[sa] = *(const uint2*)&gkl[ga];
        }
        for (int idx = tid; idx < 2048; idx += 256) {
            int vd = idx >> 5, t4 = (idx & 31) * 4;
            long long ga = ((long long)((b * 4 + hk) * 64 + vd)) * 1024 + kb * 128 + t4;
            int sa = (t4 >> 4) * 1024 + swz(vd, t4 & 15);
            *(uint2*)&vh[sa] = *(const uint2*)&gvh[ga];
            *(uint2*)&vl[sa] = *(const uint2*)&gvl[ga];
        }
        __syncthreads();

        float sAcc[16][4];
        #pragma unroll
        for (int t = 0; t < 16; t++)
            #pragma unroll
            for (int e = 0; e < 4; e++) sAcc[t][e] = 0.f;

        #pragma unroll
        for (int kk = 0; kk < 4; kk++) {
            uint32_t aH[4], aL[4];
            uint32_t qa = qbase + (uint32_t)(kk * 2048 + swz(arow, akk)) * 2;
            LDSM4(aH[0], aH[1], aH[2], aH[3], qa);
            uint32_t qla = qlbase + (uint32_t)(kk * 2048 + swz(arow, akk)) * 2;
            LDSM4(aL[0], aL[1], aL[2], aL[3], qla);
            #pragma unroll
            for (int nb = 0; nb < 8; nb++) {
                uint32_t off = (uint32_t)(kk * 2048 + swz(nb * 16 + brow, bko)) * 2;
                uint32_t r0, r1, r2, r3, s0, s1, s2, s3;
                LDSM4(r0, r1, r2, r3, kbase + off);
                LDSM4(s0, s1, s2, s3, klbase + off);
                MMAS(sAcc[2 * nb],     aH, r0, r1);
                MMAS(sAcc[2 * nb],     aH, s0, s1);
                MMAS(sAcc[2 * nb],     aL, r0, r1);
                MMAS(sAcc[2 * nb + 1], aH, r2, r3);
                MMAS(sAcc[2 * nb + 1], aH, s2, s3);
                MMAS(sAcc[2 * nb + 1], aL, r2, r3);
            }
        }

        #pragma unroll
        for (int t = 0; t < 16; t++)
            #pragma unroll
            for (int e = 0; e < 4; e++) {
                float v = sAcc[t][e] * 0.125f;
                if (kb == qb) {
                    int col = t * 8 + c2 + (e & 1);
                    int rowl = w * 16 + r4 + ((e >> 1) ? 8 : 0);
                    if (col > rowl) v = -1e30f;
                }
                sAcc[t][e] = v;
            }

        float m0 = -1e30f, m1 = -1e30f;
        #pragma unroll
        for (int t = 0; t < 16; t++) {
            m0 = fmaxf(m0, fmaxf(sAcc[t][0], sAcc[t][1]));
            m1 = fmaxf(m1, fmaxf(sAcc[t][2], sAcc[t][3]));
        }
        m0 = fmaxf(m0, __shfl_xor_sync(0xFFFFFFFFu, m0, 1));
        m0 = fmaxf(m0, __shfl_xor_sync(0xFFFFFFFFu, m0, 2));
        m1 = fmaxf(m1, __shfl_xor_sync(0xFFFFFFFFu, m1, 1));
        m1 = fmaxf(m1, __shfl_xor_sync(0xFFFFFFFFu, m1, 2));
        float mn0 = fmaxf(m_prev[0], m0), mn1 = fmaxf(m_prev[1], m1);
        float al0 = __expf(m_prev[0] - mn0), al1 = __expf(m_prev[1] - mn1);
        float rs0 = 0.f, rs1 = 0.f;
        #pragma unroll
        for (int t = 0; t < 16; t++) {
            sAcc[t][0] = __expf(sAcc[t][0] - mn0);
            sAcc[t][1] = __expf(sAcc[t][1] - mn0);
            sAcc[t][2] = __expf(sAcc[t][2] - mn1);
            sAcc[t][3] = __expf(sAcc[t][3] - mn1);
            rs0 += sAcc[t][0] + sAcc[t][1];
            rs1 += sAcc[t][2] + sAcc[t][3];
        }
        rs0 += __shfl_xor_sync(0xFFFFFFFFu, rs0, 1);
        rs0 += __shfl_xor_sync(0xFFFFFFFFu, rs0, 2);
        rs1 += __shfl_xor_sync(0xFFFFFFFFu, rs1, 1);
        rs1 += __shfl_xor_sync(0xFFFFFFFFu, rs1, 2);
        l_run[0] = l_run[0] * al0 + rs0;
        l_run[1] = l_run[1] * al1 + rs1;
        m_prev[0] = mn0; m_prev[1] = mn1;
        #pragma unroll
        for (int ot = 0; ot < 8; ot++) {
            oAcc[ot][0] *= al0; oAcc[ot][1] *= al0;
            oAcc[ot][2] *= al1; oAcc[ot][3] *= al1;
        }

        #pragma unroll
        for (int kk = 0; kk < 8; kk++) {
            float* sA = sAcc[2 * kk];
            float* sB = sAcc[2 * kk + 1];
            uint32_t aH[4], aL[4];
            aH[0] = pack2(sA[0], sA[1]); aH[1] = pack2(sA[2], sA[3]);
            aH[2] = pack2(sB[0], sB[1]); aH[3] = pack2(sB[2], sB[3]);
            aL[0] = pack2(lopart(sA[0]), lopart(sA[1]));
            aL[1] = pack2(lopart(sA[2]), lopart(sA[3]));
            aL[2] = pack2(lopart(sB[0]), lopart(sB[1]));
            aL[3] = pack2(lopart(sB[2]), lopart(sB[3]));
            #pragma unroll
            for (int vb = 0; vb < 4; vb++) {
                uint32_t off = (uint32_t)(kk * 1024 + swz(vb * 16 + brow, bko)) * 2;
                uint32_t r0, r1, r2, r3, s0, s1, s2, s3;
                LDSM4(r0, r1, r2, r3, vbase + off);
                LDSM4(s0, s1, s2, s3, vlbase + off);
                MMAS(oAcc[2 * vb],     aH, r0, r1);
                MMAS(oAcc[2 * vb],     aH, s0, s1);
                MMAS(oAcc[2 * vb],     aL, r0, r1);
                MMAS(oAcc[2 * vb + 1], aH, r2, r3);
                MMAS(oAcc[2 * vb + 1], aH, s2, s3);
                MMAS(oAcc[2 * vb + 1], aL, r2, r3);
            }
        }
    }

    float inv0 = 1.f / l_run[0], inv1 = 1.f / l_run[1];
    __nv_bfloat16 *oh = batt, *ol = batt + SZ_ATT;
    #pragma unroll
    for (int ot = 0; ot < 8; ot++)
        #pragma unroll
        for (int e = 0; e < 4; e++) {
            float v = oAcc[ot][e] * ((e >> 1) ? inv1 : inv0);
            int rowl = w * 16 + r4 + ((e >> 1) ? 8 : 0);
            long long oi = ((long long)(b * 1024 + qb * 128 + rowl)) * 1024
                           + h * 64 + ot * 8 + c2 + (e & 1);
            __nv_bfloat16 hb = __float2bfloat16(v);
            oh[oi] = hb;
            ol[oi] = __float2bfloat16(v - __bfloat162float(hb));
        }
}

// ---------------- launch ----------------
extern "C" void kernel_launch(void* const* d_in, const int* in_sizes, int n_in,
                              void* d_out, int out_size) {
    const float* x   = (const float*)d_in[0];
    const float* wq  = (const float*)d_in[1];
    const float* wk  = (const float*)d_in[2];
    const float* wv  = (const float*)d_in[3];
    const float* wo  = (const float*)d_in[4];
    const float* rw  = (const float*)d_in[5];
    const float* rb  = (const float*)d_in[6];
    const float* w1  = (const float*)d_in[7];
    const float* w2  = (const float*)d_in[8];
    const float* w3  = (const float*)d_in[9];
    const float* ns1 = (const float*)d_in[10];
    const float* ns2 = (const float*)d_in[11];

    float *qkv, *x1, *h2, *grp, *t1, *t2, *eout;
    cudaGetSymbolAddress((void**)&qkv, g_qkv);
    cudaGetSymbolAddress((void**)&x1, g_x1);
    cudaGetSymbolAddress((void**)&h2, g_h2);
    cudaGetSymbolAddress((void**)&grp, g_grp);
    cudaGetSymbolAddress((void**)&t1, g_t1);
    cudaGetSymbolAddress((void**)&t2, g_t2);
    cudaGetSymbolAddress((void**)&eout, g_eout);

    __nv_bfloat16 *bh, *bq, *bk, *bvt, *batt, *bgrp, *bt1;
    __nv_bfloat16 *wqkvT, *woT, *w1T, *w2T, *w3T;
    cudaGetSymbolAddress((void**)&bh, b_h);
    cudaGetSymbolAddress((void**)&bq, b_q);
    cudaGetSymbolAddress((void**)&bk, b_k);
    cudaGetSymbolAddress((void**)&bvt, b_vt);
    cudaGetSymbolAddress((void**)&batt, b_attn);
    cudaGetSymbolAddress((void**)&bgrp, b_grp);
    cudaGetSymbolAddress((void**)&bt1, b_t1);
    cudaGetSymbolAddress((void**)&wqkvT, b_wqkvT);
    cudaGetSymbolAddress((void**)&woT, b_woT);
    cudaGetSymbolAddress((void**)&w1T, b_w1T);
    cudaGetSymbolAddress((void**)&w2T, b_w2T);
    cudaGetSymbolAddress((void**)&w3T, b_w3T);

    cudaFuncSetAttribute(flash_kernel, cudaFuncAttributeMaxDynamicSharedMemorySize, 98304);

    auto tconv = [&](const float* s, __nv_bfloat16* d, __nv_bfloat16* dlo,
                     int R, int C, int lds, long long so, long long si, int zdiv, int Z) {
        dim3 grid((C + 31) / 32, (R + 31) / 32, Z);
        tconv_kernel<<<grid, dim3(32, 8)>>>(s, d, dlo, R, C, lds, so, si, zdiv);
    };
    auto bgemm = [&](int M, int N, int K,
                     const __nv_bfloat16* A, long long szA, int lda, long long soA, long long siA, int divA,
                     const __nv_bfloat16* B, long long szB, int ldb, long long soB, long long siB, int divB,
                     float* C, int ldc, long long soC, long long siC, int divC,
                     int Z, int zdiv, int epi, const float* R) {
        dim3 grid(N / 128, M / 128, Z);
        bgemm_kernel<<<grid, 256>>>(M, N, K, A, A + szA, lda, soA, siA, divA,
            B, B + szB, ldb, soB, siB, divB, C, ldc, soC, siC, divC, zdiv, epi, R);
    };

    // pack wq|wk|wv transposed into one NT-layout buffer [1536][1024] hi/lo
    tconv(wq, wqkvT,               wqkvT + SZ_QKVW,               1024, 1024, 1024, 0, 0, 1, 1);
    tconv(wk, wqkvT + 1024 * 1024, wqkvT + SZ_QKVW + 1024 * 1024, 1024, 256, 256, 0, 0, 1, 1);
    tconv(wv, wqkvT + 1280 * 1024, wqkvT + SZ_QKVW + 1280 * 1024, 1024, 256, 256, 0, 0, 1, 1);
    tconv(wo, woT, woT + SZ_WOT, 1024, 1024, 1024, 0, 0, 1, 1);
    tconv(w1, w1T, w1T + SZ_W1T, 1024, 2048, 2048, (long long)DD * HIDn, 0, 1, En);
    tconv(w2, w2T, w2T + SZ_W1T, 1024, 2048, 2048, (long long)DD * HIDn, 0, 1, En);
    tconv(w3, w3T, w3T + SZ_W3T, 2048, 1024, 1024, (long long)HIDn * DD, 0, 1, En);

    // ---- attention ----
    rmsnorm_kernel<<<NTOK, 256>>>(x, ns1, nullptr, bh, bh + SZ_H);
    bgemm(NTOK, 1536, 1024, bh, SZ_H, 1024, 0, 0, 1,
          wqkvT, SZ_QKVW, 1024, 0, 0, 1, qkv, 1536, 0, 0, 1, 1, 1, 0, nullptr);
    {
        long long tq = (long long)NTOK * HQn * 32;
        rope_kernel<<<(unsigned)((tq + 255) / 256), 256>>>(qkv, 0, HQn, tq);
        long long tk = (long long)NTOK * HKVn * 32;
        rope_kernel<<<(unsigned)((tk + 255) / 256), 256>>>(qkv, 1024, HKVn, tk);
    }
    sconv_kernel<<<(SZ_Q + 255) / 256, 256>>>(qkv, 1536, 1024, bq, bq + SZ_Q, SZ_Q);
    sconv_kernel<<<(SZ_K + 255) / 256, 256>>>(qkv + 1024, 1536, 256, bk, bk + SZ_K, SZ_K);
    tconv(qkv + 1280, bvt, bvt + SZ_VT, TT, VDn, 1536,
          (long long)TT * 1536, VDn, HKVn, BB * HKVn);

    flash_kernel<<<dim3(8, 32), 256, 98304>>>(bq, bk, bvt, batt);

    bgemm(NTOK, 1024, 1024, batt, SZ_ATT, 1024, 0, 0, 1,
          woT, SZ_WOT, 1024, 0, 0, 1, x1, 1024, 0, 0, 1, 1, 1, 2, x);

    // ---- MoE ----
    rmsnorm_kernel<<<NTOK, 256>>>(x1, ns2, h2, nullptr, nullptr);
    router_kernel<<<NTOK, 256>>>(rw, rb);
    scan_kernel<<<1, 256>>>();
    {
        long long n = (long long)En * CAPn * DD;
        zero_kernel<<<(unsigned)((n + 255) / 256), 256>>>(grp, n);
    }
    scatter_kernel<<<NTOK * 2, 256>>>();
    conv4_kernel<<<(SZ_GRP / 4 + 255) / 256, 256>>>(grp, bgrp, bgrp + SZ_GRP, SZ_GRP / 4);
    bgemm(CAPn, HIDn, DD,
          bgrp, SZ_GRP, 1024, (long long)CAPn * DD, 0, 1,
          w1T, SZ_W1T, 1024, (long long)HIDn * DD, 0, 1,
          t1, HIDn, (long long)CAPn * HIDn, 0, 1, En, 1, 0, nullptr);
    bgemm(CAPn, HIDn, DD,
          bgrp, SZ_GRP, 1024, (long long)CAPn * DD, 0, 1,
          w2T, SZ_W1T, 1024, (long long)HIDn * DD, 0, 1,
          t2, HIDn, (long long)CAPn * HIDn, 0, 1, En, 1, 0, nullptr);
    gelu_mul_kernel<<<(SZ_T1 / 4 + 255) / 256, 256>>>(bt1, bt1 + SZ_T1, SZ_T1 / 4);
    bgemm(CAPn, DD, HIDn,
          bt1, SZ_T1, HIDn, (long long)CAPn * HIDn, 0, 1,
          w3T, SZ_W3T, 2048, (long long)DD * HIDn, 0, 1,
          eout, DD, (long long)CAPn * DD, 0, 1, En, 1, 0, nullptr);
    combine_kernel<<<NTOK, 256>>>((float*)d_out);
}

// round 8
// speedup vs baseline: 2.9682x; 2.0170x over previous
#include <cuda_runtime.h>
#include <cuda_bf16.h>
#include <cuda_fp16.h>
#include <math.h>
#include <stdint.h>

// ---------------- problem dims ----------------
#define BB    2
#define TT    1024
#define NTOK  2048
#define DD    1024
#define HQn   16
#define HKVn  4
#define KDn   64
#define VDn   64
#define Gn    4
#define En    8
#define CAPn  1024
#define HIDn  2048

// ---------------- fp32 scratch ----------------
__device__ float g_qkv [NTOK*1536];
__device__ float g_x1  [NTOK*DD];
__device__ float g_h2  [NTOK*DD];
__device__ float g_grp [En*CAPn*DD];
__device__ float g_t1  [En*CAPn*HIDn];
__device__ float g_t2  [En*CAPn*HIDn];
__device__ float g_eout[En*CAPn*DD];
__device__ int   g_assign[NTOK*2];
__device__ float g_gate  [NTOK*2];
__device__ int   g_slot  [NTOK*2];
__device__ int   g_keep  [NTOK*2];

// ---------------- fp16 scratch (single precision, 1-pass MMA) ----------------
#define SZ_H    (NTOK*DD)
#define SZ_Q    (NTOK*HQn*KDn)
#define SZ_K    (NTOK*HKVn*KDn)
#define SZ_VT   (BB*HKVn*VDn*TT)
#define SZ_ATT  (NTOK*DD)
#define SZ_GRP  (En*CAPn*DD)
#define SZ_T1   (En*CAPn*HIDn)
#define SZ_QKVW (1536*DD)
#define SZ_WOT  (DD*DD)
#define SZ_W1T  (En*HIDn*DD)
#define SZ_W3T  (En*DD*HIDn)

__device__ __half b_h    [SZ_H];
__device__ __half b_q    [SZ_Q];
__device__ __half b_k    [SZ_K];
__device__ __half b_vt   [SZ_VT];
__device__ __half b_attn [SZ_ATT];
__device__ __half b_grp  [SZ_GRP];
__device__ __half b_t1   [SZ_T1];
__device__ __half b_wqkvT[SZ_QKVW];
__device__ __half b_woT  [SZ_WOT];
__device__ __half b_w1T  [SZ_W1T];
__device__ __half b_w2T  [SZ_W1T];
__device__ __half b_w3T  [SZ_W3T];

// ---------------- helpers ----------------
__device__ __forceinline__ uint32_t pack2h(float a, float b) {
    __half2 t = __floats2half2_rn(a, b);
    return *reinterpret_cast<uint32_t*>(&t);
}
__device__ __forceinline__ int swz(int row, int k) {
    return row * 16 + ((((k >> 3) ^ (row >> 2)) & 1) << 3) + (k & 7);
}

#define LDSM4(r0,r1,r2,r3,a) \
  asm volatile("ldmatrix.sync.aligned.m8n8.x4.shared.b16 {%0,%1,%2,%3}, [%4];" \
    : "=r"(r0), "=r"(r1), "=r"(r2), "=r"(r3) : "r"(a))

#define HMMA(d, a, b0, b1) \
  asm volatile("mma.sync.aligned.m16n8k16.row.col.f32.f16.f16.f32 " \
    "{%0,%1,%2,%3}, {%4,%5,%6,%7}, {%8,%9}, {%0,%1,%2,%3};" \
    : "+f"(d[0]), "+f"(d[1]), "+f"(d[2]), "+f"(d[3]) \
    : "r"(a[0]), "r"(a[1]), "r"(a[2]), "r"(a[3]), "r"(b0), "r"(b1))

// ---------------- small kernels ----------------
__global__ void rmsnorm_kernel(const float* __restrict__ x,
                               const float* __restrict__ scale,
                               float* __restrict__ outF,
                               __half* __restrict__ outH) {
    int row = blockIdx.x;
    const float* xr = x + (long long)row * DD;
    __shared__ float red[256];
    float s = 0.f;
    for (int d = threadIdx.x; d < DD; d += 256) { float v = xr[d]; s += v * v; }
    red[threadIdx.x] = s; __syncthreads();
    for (int o = 128; o > 0; o >>= 1) {
        if (threadIdx.x < o) red[threadIdx.x] += red[threadIdx.x + o];
        __syncthreads();
    }
    float inv = 1.0f / sqrtf(red[0] / (float)DD + 1e-6f);
    for (int d = threadIdx.x; d < DD; d += 256) {
        float v = xr[d] * inv * scale[d];
        if (outF) outF[(long long)row * DD + d] = v;
        if (outH) outH[(long long)row * DD + d] = __float2half(v);
    }
}

__global__ void rope_kernel(float* __restrict__ p, int colBase, int H, long long total) {
    long long i = (long long)blockIdx.x * 256 + threadIdx.x;
    if (i >= total) return;
    int j = (int)(i & 31);
    long long nh = i >> 5;
    int h = (int)(nh % H);
    long long n = nh / H;
    int t = (int)(n % TT);
    float* v = p + n * 1536 + colBase + h * 64;
    float theta = powf(10000.0f, -(2.0f * j) / 64.0f);
    float a = (float)t * theta;
    float c = cosf(a), s = sinf(a);
    float x1 = v[j], x2 = v[j + 32];
    v[j]      = x1 * c - x2 * s;
    v[j + 32] = x2 * c + x1 * s;
}

__global__ void router_kernel(const float* __restrict__ rw, const float* __restrict__ rb) {
    int t = blockIdx.x;
    const float* xr = g_h2 + (long long)t * DD;
    float part[En];
    #pragma unroll
    for (int e = 0; e < En; e++) part[e] = 0.f;
    for (int d = threadIdx.x; d < DD; d += 256) {
        float xv = xr[d];
        #pragma unroll
        for (int e = 0; e < En; e++) part[e] += xv * rw[d * En + e];
    }
    __shared__ float red[En][8];
    int lane = threadIdx.x & 31, warp = threadIdx.x >> 5;
    #pragma unroll
    for (int e = 0; e < En; e++) {
        float v = part[e];
        for (int o = 16; o > 0; o >>= 1) v += __shfl_down_sync(0xffffffffu, v, o);
        if (lane == 0) red[e][warp] = v;
    }
    __syncthreads();
    if (threadIdx.x == 0) {
        float lg[En];
        #pragma unroll
        for (int e = 0; e < En; e++) {
            float s = 0.f;
            for (int w = 0; w < 8; w++) s += red[e][w];
            lg[e] = s + rb[e];
        }
        int i0 = 0;
        for (int e = 1; e < En; e++) if (lg[e] > lg[i0]) i0 = e;
        int i1 = -1;
        for (int e = 0; e < En; e++) {
            if (e == i0) continue;
            if (i1 < 0 || lg[e] > lg[i1]) i1 = e;
        }
        float e1 = expf(lg[i1] - lg[i0]);
        float denom = 1.f + e1;
        g_assign[2 * t] = i0;     g_assign[2 * t + 1] = i1;
        g_gate[2 * t] = 1.f / denom; g_gate[2 * t + 1] = e1 / denom;
    }
}

__global__ void scan_kernel() {
    int lane = threadIdx.x & 31;
    int e = threadIdx.x >> 5;
    uint32_t mle = 0xFFFFFFFFu >> (31 - lane);
    int base0 = 0, base1 = 0;
    for (int chunk = 0; chunk < NTOK / 32; chunk++) {
        int t = chunk * 32 + lane;
        int a0 = g_assign[2 * t], a1 = g_assign[2 * t + 1];
        uint32_t b0 = __ballot_sync(0xFFFFFFFFu, a0 == e);
        uint32_t b1 = __ballot_sync(0xFFFFFFFFu, a1 == e);
        int incl0 = __popc(b0 & mle);
        int incl1 = __popc(b1 & mle);
        if (a0 == e) {
            int p0 = base0 + incl0;
            g_slot[2 * t] = p0; g_keep[2 * t] = (p0 < CAPn) ? 1 : 0;
        }
        if (a1 == e) {
            int p1 = (base0 + incl0) + (base1 + incl1);
            g_slot[2 * t + 1] = p1; g_keep[2 * t + 1] = (p1 < CAPn) ? 1 : 0;
        }
        base0 += __popc(b0); base1 += __popc(b1);
    }
}

__global__ void zero_kernel(float* __restrict__ p, long long n) {
    long long i = (long long)blockIdx.x * 256 + threadIdx.x;
    if (i < n) p[i] = 0.f;
}

__global__ void scatter_kernel() {
    int i = blockIdx.x;
    if (!g_keep[i]) return;
    int t = i >> 1;
    int e = g_assign[i], s = g_slot[i];
    float* dst = g_grp + ((long long)e * CAPn + s) * DD;
    const float* src = g_h2 + (long long)t * DD;
    for (int d = threadIdx.x; d < DD; d += 256) atomicAdd(&dst[d], src[d]);
}

__global__ void gelu_mul_kernel(__half* __restrict__ oh, long long n4) {
    long long i = (long long)blockIdx.x * 256 + threadIdx.x;
    if (i >= n4) return;
    float4 a = *(const float4*)&g_t1[i * 4];
    float4 b = *(const float4*)&g_t2[i * 4];
    float r[4];
    float xs[4] = {a.x * b.x, a.y * b.y, a.z * b.z, a.w * b.w};
    #pragma unroll
    for (int j = 0; j < 4; j++) {
        float x = xs[j];
        float inner = 0.7978845608028654f * (x + 0.044715f * x * x * x);
        r[j] = 0.5f * x * (1.0f + tanhf(inner));
    }
    uint2 hv;
    hv.x = pack2h(r[0], r[1]); hv.y = pack2h(r[2], r[3]);
    *(uint2*)&oh[i * 4] = hv;
}

__global__ void combine_kernel(float* __restrict__ out) {
    int t = blockIdx.x;
    float gte0 = g_gate[2 * t], gte1 = g_gate[2 * t + 1];
    const float* s0 = g_keep[2 * t]
        ? g_eout + ((long long)g_assign[2 * t] * CAPn + g_slot[2 * t]) * DD
        : g_h2 + (long long)t * DD;
    const float* s1 = g_keep[2 * t + 1]
        ? g_eout + ((long long)g_assign[2 * t + 1] * CAPn + g_slot[2 * t + 1]) * DD
        : g_h2 + (long long)t * DD;
    const float* xr = g_x1 + (long long)t * DD;
    float* orow = out + (long long)t * DD;
    for (int d = threadIdx.x; d < DD; d += 256)
        orow[d] = xr[d] + gte0 * s0[d] + gte1 * s1[d];
}

__global__ void conv4_kernel(const float* __restrict__ src, __half* __restrict__ hi, long long n4) {
    long long i = (long long)blockIdx.x * 256 + threadIdx.x;
    if (i >= n4) return;
    float4 v = *(const float4*)&src[i * 4];
    uint2 hv;
    hv.x = pack2h(v.x, v.y); hv.y = pack2h(v.z, v.w);
    *(uint2*)&hi[i * 4] = hv;
}

__global__ void sconv_kernel(const float* __restrict__ src, int srcStride, int width,
                             __half* __restrict__ hi, long long n) {
    long long i = (long long)blockIdx.x * 256 + threadIdx.x;
    if (i >= n) return;
    int row = (int)(i / width), col = (int)(i % width);
    hi[i] = __float2half(src[(long long)row * srcStride + col]);
}

__global__ void tconv_kernel(const float* __restrict__ src, __half* __restrict__ hi,
                             int R, int C, int lds, long long so, long long si, int zdiv) {
    int z = blockIdx.z;
    src += (long long)(z / zdiv) * so + (long long)(z % zdiv) * si;
    hi += (long long)z * R * C;
    __shared__ float t[32][33];
    int c0 = blockIdx.x * 32, r0 = blockIdx.y * 32;
    for (int i = threadIdx.y; i < 32; i += 8) {
        int r = r0 + i, c = c0 + threadIdx.x;
        if (r < R && c < C) t[i][threadIdx.x] = src[(long long)r * lds + c];
    }
    __syncthreads();
    for (int i = threadIdx.y; i < 32; i += 8) {
        int c = c0 + i, r = r0 + threadIdx.x;
        if (r < R && c < C)
            hi[(long long)c * R + r] = __float2half(t[threadIdx.x][i]);
    }
}

// ---------------- fp16 single-pass tensor-core GEMM (NT), 3-stage ----------------
#define TILEE (128*16)

__global__ void __launch_bounds__(256)
hgemm_kernel(int M, int N, int K,
             const __half* __restrict__ A, int lda, long long soA, long long siA, int divA,
             const __half* __restrict__ B, int ldb, long long soB, long long siB, int divB,
             float* __restrict__ C, int ldc, long long soC, long long siC, int divC,
             int zdiv, int epi, const float* __restrict__ Rz) {
    int z = blockIdx.z;
    long long offA = (long long)(z / zdiv) * soA + (long long)((z % zdiv) / divA) * siA;
    long long offB = (long long)(z / zdiv) * soB + (long long)((z % zdiv) / divB) * siB;
    long long offC = (long long)(z / zdiv) * soC + (long long)((z % zdiv) / divC) * siC;
    A += offA; B += offB; C += offC;
    const float* Rp = Rz ? (Rz + offC) : (const float*)0;

    int m0 = blockIdx.y * 128, n0 = blockIdx.x * 128;
    int tid = threadIdx.x;

    __shared__ __half sm[3][2][TILEE];   // 24KB
    uint32_t sbase = (uint32_t)__cvta_generic_to_shared(&sm[0][0][0]);

    int lr = tid >> 1, lc = tid & 1;
    const __half* gA = A + (long long)(m0 + lr) * lda + lc * 8;
    const __half* gB = B + (long long)(n0 + lr) * ldb + lc * 8;
    uint32_t soff = (uint32_t)swz(lr, lc * 8) * 2;

    int KT = K / 16;

    auto prefetch = [&](int kt, int st) {
        long long ko = (long long)kt * 16;
        uint32_t b0 = sbase + (uint32_t)(st * 2 * TILEE * 2);
        asm volatile("cp.async.cg.shared.global [%0], [%1], 16;"
                     :: "r"(b0 + soff), "l"(gA + ko));
        asm volatile("cp.async.cg.shared.global [%0], [%1], 16;"
                     :: "r"(b0 + (uint32_t)(TILEE * 2) + soff), "l"(gB + ko));
        asm volatile("cp.async.commit_group;");
    };

    float acc[4][4][4];
    #pragma unroll
    for (int i = 0; i < 4; i++)
        #pragma unroll
        for (int j = 0; j < 4; j++)
            #pragma unroll
            for (int e = 0; e < 4; e++) acc[i][j][e] = 0.f;

    int lane = tid & 31, wid = tid >> 5;
    int wm = wid & 1, wn = wid >> 1;
    int arow = wm * 64 + (lane & 15);
    int ak = (lane >> 4) * 8;
    int brow2 = wn * 32 + (lane & 7) + ((lane & 16) ? 8 : 0);
    int bk = (lane & 8) ? 8 : 0;

    prefetch(0, 0);
    if (KT > 1) prefetch(1, 1);

    for (int kt = 0; kt < KT; kt++) {
        if (kt + 2 < KT) {
            prefetch(kt + 2, (kt + 2) % 3);
            asm volatile("cp.async.wait_group 2;");
        } else if (kt + 1 < KT) {
            asm volatile("cp.async.wait_group 1;");
        } else {
            asm volatile("cp.async.wait_group 0;");
        }
        __syncthreads();

        uint32_t base = sbase + (uint32_t)((kt % 3) * 2 * TILEE * 2);
        uint32_t fA[4][4], fB[4][2];
        #pragma unroll
        for (int mi = 0; mi < 4; mi++) {
            uint32_t ao = base + (uint32_t)swz(arow + mi * 16, ak) * 2;
            LDSM4(fA[mi][0], fA[mi][1], fA[mi][2], fA[mi][3], ao);
        }
        #pragma unroll
        for (int nj = 0; nj < 2; nj++) {
            uint32_t bo = base + (uint32_t)(TILEE * 2) + (uint32_t)swz(brow2 + nj * 16, bk) * 2;
            uint32_t r0, r1, r2, r3;
            LDSM4(r0, r1, r2, r3, bo);
            fB[nj * 2][0] = r0; fB[nj * 2][1] = r1;
            fB[nj * 2 + 1][0] = r2; fB[nj * 2 + 1][1] = r3;
        }
        #pragma unroll
        for (int mi = 0; mi < 4; mi++)
            #pragma unroll
            for (int ni = 0; ni < 4; ni++)
                HMMA(acc[mi][ni], fA[mi], fB[ni][0], fB[ni][1]);
        __syncthreads();
    }

    int r4 = lane >> 2, c2 = (lane & 3) * 2;
    #pragma unroll
    for (int mi = 0; mi < 4; mi++)
        #pragma unroll
        for (int ni = 0; ni < 4; ni++) {
            int row = m0 + wm * 64 + mi * 16 + r4;
            int col = n0 + wn * 32 + ni * 8 + c2;
            #pragma unroll
            for (int e = 0; e < 4; e++) {
                int rr = row + (e >> 1) * 8;
                int cc = col + (e & 1);
                float v = acc[mi][ni][e];
                if (epi == 2) v += Rp[(long long)rr * ldc + cc];
                C[(long long)rr * ldc + cc] = v;
            }
        }
}

// ---------------- flash attention (fp16 single-pass) ----------------
__global__ void __launch_bounds__(256, 1)
flash_kernel(const __half* __restrict__ bq,
             const __half* __restrict__ bk,
             const __half* __restrict__ bvt,
             __half* __restrict__ batt) {
    extern __shared__ __half smf[];
    __half *qh = smf, *kh = smf + 8192, *vh = smf + 16384;

    int tid = threadIdx.x, lane = tid & 31, w = tid >> 5;
    int qb = blockIdx.x, bhid = blockIdx.y;
    int b = bhid >> 4, h = bhid & 15, hk = h >> 2;

    for (int idx = tid; idx < 2048; idx += 256) {
        int row = idx >> 4, c4 = (idx & 15) * 4;
        long long ga = ((long long)((b * 1024 + qb * 128 + row) * 16 + h)) * 64 + c4;
        int sa = (c4 >> 4) * 2048 + swz(row, c4 & 15);
        *(uint2*)&qh[sa] = *(const uint2*)&bq[ga];
    }

    uint32_t qbase = (uint32_t)__cvta_generic_to_shared(qh);
    uint32_t kbase = (uint32_t)__cvta_generic_to_shared(kh);
    uint32_t vbase = (uint32_t)__cvta_generic_to_shared(vh);

    float oAcc[8][4];
    #pragma unroll
    for (int i = 0; i < 8; i++)
        #pragma unroll
        for (int e = 0; e < 4; e++) oAcc[i][e] = 0.f;
    float m_prev[2] = {-1e30f, -1e30f};
    float l_run[2] = {0.f, 0.f};

    int arow = w * 16 + (lane & 15), akk = (lane >> 4) * 8;
    int brow = (lane & 7) + ((lane & 16) ? 8 : 0);
    int bko = (lane & 8) ? 8 : 0;
    int r4 = lane >> 2, c2 = (lane & 3) * 2;

    for (int kb = 0; kb <= qb; kb++) {
        __syncthreads();
        for (int idx = tid; idx < 2048; idx += 256) {
            int row = idx >> 4, c4 = (idx & 15) * 4;
            long long ga = ((long long)((b * 1024 + kb * 128 + row) * 4 + hk)) * 64 + c4;
            int sa = (c4 >> 4) * 2048 + swz(row, c4 & 15);
            *(uint2*)&kh[sa] = *(const uint2*)&bk[ga];
        }
        for (int idx = tid; idx < 2048; idx += 256) {
            int vd = idx >> 5, t4 = (idx & 31) * 4;
            long long ga = ((long long)((b * 4 + hk) * 64 + vd)) * 1024 + kb * 128 + t4;
            int sa = (t4 >> 4) * 1024 + swz(vd, t4 & 15);
            *(uint2*)&vh[sa] = *(const uint2*)&bvt[ga];
        }
        __syncthreads();

        float sAcc[16][4];
        #pragma unroll
        for (int t = 0; t < 16; t++)
            #pragma unroll
            for (int e = 0; e < 4; e++) sAcc[t][e] = 0.f;

        #pragma unroll
        for (int kk = 0; kk < 4; kk++) {
            uint32_t aH[4];
            uint32_t qa = qbase + (uint32_t)(kk * 2048 + swz(arow, akk)) * 2;
            LDSM4(aH[0], aH[1], aH[2], aH[3], qa);
            #pragma unroll
            for (int nb = 0; nb < 8; nb++) {
                uint32_t off = (uint32_t)(kk * 2048 + swz(nb * 16 + brow, bko)) * 2;
                uint32_t r0, r1, r2, r3;
                LDSM4(r0, r1, r2, r3, kbase + off);
                HMMA(sAcc[2 * nb],     aH, r0, r1);
                HMMA(sAcc[2 * nb + 1], aH, r2, r3);
            }
        }

        #pragma unroll
        for (int t = 0; t < 16; t++)
            #pragma unroll
            for (int e = 0; e < 4; e++) {
                float v = sAcc[t][e] * 0.125f;
                if (kb == qb) {
                    int col = t * 8 + c2 + (e & 1);
                    int rowl = w * 16 + r4 + ((e >> 1) ? 8 : 0);
                    if (col > rowl) v = -1e30f;
                }
                sAcc[t][e] = v;
            }

        float m0 = -1e30f, m1 = -1e30f;
        #pragma unroll
        for (int t = 0; t < 16; t++) {
            m0 = fmaxf(m0, fmaxf(sAcc[t][0], sAcc[t][1]));
            m1 = fmaxf(m1, fmaxf(sAcc[t][2], sAcc[t][3]));
        }
        m0 = fmaxf(m0, __shfl_xor_sync(0xFFFFFFFFu, m0, 1));
        m0 = fmaxf(m0, __shfl_xor_sync(0xFFFFFFFFu, m0, 2));
        m1 = fmaxf(m1, __shfl_xor_sync(0xFFFFFFFFu, m1, 1));
        m1 = fmaxf(m1, __shfl_xor_sync(0xFFFFFFFFu, m1, 2));
        float mn0 = fmaxf(m_prev[0], m0), mn1 = fmaxf(m_prev[1], m1);
        float al0 = __expf(m_prev[0] - mn0), al1 = __expf(m_prev[1] - mn1);
        float rs0 = 0.f, rs1 = 0.f;
        #pragma unroll
        for (int t = 0; t < 16; t++) {
            sAcc[t][0] = __expf(sAcc[t][0] - mn0);
            sAcc[t][1] = __expf(sAcc[t][1] - mn0);
            sAcc[t][2] = __expf(sAcc[t][2] - mn1);
            sAcc[t][3] = __expf(sAcc[t][3] - mn1);
            rs0 += sAcc[t][0] + sAcc[t][1];
            rs1 += sAcc[t][2] + sAcc[t][3];
        }
        rs0 += __shfl_xor_sync(0xFFFFFFFFu, rs0, 1);
        rs0 += __shfl_xor_sync(0xFFFFFFFFu, rs0, 2);
        rs1 += __shfl_xor_sync(0xFFFFFFFFu, rs1, 1);
        rs1 += __shfl_xor_sync(0xFFFFFFFFu, rs1, 2);
        l_run[0] = l_run[0] * al0 + rs0;
        l_run[1] = l_run[1] * al1 + rs1;
        m_prev[0] = mn0; m_prev[1] = mn1;
        #pragma unroll
        for (int ot = 0; ot < 8; ot++) {
            oAcc[ot][0] *= al0; oAcc[ot][1] *= al0;
            oAcc[ot][2] *= al1; oAcc[ot][3] *= al1;
        }

        #pragma unroll
        for (int kk = 0; kk < 8; kk++) {
            float* sA = sAcc[2 * kk];
            float* sB = sAcc[2 * kk + 1];
            uint32_t aH[4];
            aH[0] = pack2h(sA[0], sA[1]); aH[1] = pack2h(sA[2], sA[3]);
            aH[2] = pack2h(sB[0], sB[1]); aH[3] = pack2h(sB[2], sB[3]);
            #pragma unroll
            for (int vb = 0; vb < 4; vb++) {
                uint32_t off = (uint32_t)(kk * 1024 + swz(vb * 16 + brow, bko)) * 2;
                uint32_t r0, r1, r2, r3;
                LDSM4(r0, r1, r2, r3, vbase + off);
                HMMA(oAcc[2 * vb],     aH, r0, r1);
                HMMA(oAcc[2 * vb + 1], aH, r2, r3);
            }
        }
    }

    float inv0 = 1.f / l_run[0], inv1 = 1.f / l_run[1];
    #pragma unroll
    for (int ot = 0; ot < 8; ot++)
        #pragma unroll
        for (int e = 0; e < 4; e++) {
            float v = oAcc[ot][e] * ((e >> 1) ? inv1 : inv0);
            int rowl = w * 16 + r4 + ((e >> 1) ? 8 : 0);
            long long oi = ((long long)(b * 1024 + qb * 128 + rowl)) * 1024
                           + h * 64 + ot * 8 + c2 + (e & 1);
            batt[oi] = __float2half(v);
        }
}

// ---------------- launch ----------------
extern "C" void kernel_launch(void* const* d_in, const int* in_sizes, int n_in,
                              void* d_out, int out_size) {
    const float* x   = (const float*)d_in[0];
    const float* wq  = (const float*)d_in[1];
    const float* wk  = (const float*)d_in[2];
    const float* wv  = (const float*)d_in[3];
    const float* wo  = (const float*)d_in[4];
    const float* rw  = (const float*)d_in[5];
    const float* rb  = (const float*)d_in[6];
    const float* w1  = (const float*)d_in[7];
    const float* w2  = (const float*)d_in[8];
    const float* w3  = (const float*)d_in[9];
    const float* ns1 = (const float*)d_in[10];
    const float* ns2 = (const float*)d_in[11];

    float *qkv, *x1, *h2, *grp, *t1, *t2, *eout;
    cudaGetSymbolAddress((void**)&qkv, g_qkv);
    cudaGetSymbolAddress((void**)&x1, g_x1);
    cudaGetSymbolAddress((void**)&h2, g_h2);
    cudaGetSymbolAddress((void**)&grp, g_grp);
    cudaGetSymbolAddress((void**)&t1, g_t1);
    cudaGetSymbolAddress((void**)&t2, g_t2);
    cudaGetSymbolAddress((void**)&eout, g_eout);

    __half *bh, *bq, *bk, *bvt, *batt, *bgrp, *bt1;
    __half *wqkvT, *woT, *w1T, *w2T, *w3T;
    cudaGetSymbolAddress((void**)&bh, b_h);
    cudaGetSymbolAddress((void**)&bq, b_q);
    cudaGetSymbolAddress((void**)&bk, b_k);
    cudaGetSymbolAddress((void**)&bvt, b_vt);
    cudaGetSymbolAddress((void**)&batt, b_attn);
    cudaGetSymbolAddress((void**)&bgrp, b_grp);
    cudaGetSymbolAddress((void**)&bt1, b_t1);
    cudaGetSymbolAddress((void**)&wqkvT, b_wqkvT);
    cudaGetSymbolAddress((void**)&woT, b_woT);
    cudaGetSymbolAddress((void**)&w1T, b_w1T);
    cudaGetSymbolAddress((void**)&w2T, b_w2T);
    cudaGetSymbolAddress((void**)&w3T, b_w3T);

    cudaFuncSetAttribute(flash_kernel, cudaFuncAttributeMaxDynamicSharedMemorySize, 49152);

    auto tconv = [&](const float* s, __half* d,
                     int R, int C, int lds, long long so, long long si, int zdiv, int Z) {
        dim3 grid((C + 31) / 32, (R + 31) / 32, Z);
        tconv_kernel<<<grid, dim3(32, 8)>>>(s, d, R, C, lds, so, si, zdiv);
    };
    auto hgemm = [&](int M, int N, int K,
                     const __half* A, int lda, long long soA, long long siA, int divA,
                     const __half* B, int ldb, long long soB, long long siB, int divB,
                     float* C, int ldc, long long soC, long long siC, int divC,
                     int Z, int zdiv, int epi, const float* R) {
        dim3 grid(N / 128, M / 128, Z);
        hgemm_kernel<<<grid, 256>>>(M, N, K, A, lda, soA, siA, divA,
            B, ldb, soB, siB, divB, C, ldc, soC, siC, divC, zdiv, epi, R);
    };

    // pack wq|wk|wv transposed into one NT-layout buffer [1536][1024]
    tconv(wq, wqkvT,               1024, 1024, 1024, 0, 0, 1, 1);
    tconv(wk, wqkvT + 1024 * 1024, 1024, 256, 256, 0, 0, 1, 1);
    tconv(wv, wqkvT + 1280 * 1024, 1024, 256, 256, 0, 0, 1, 1);
    tconv(wo, woT, 1024, 1024, 1024, 0, 0, 1, 1);
    tconv(w1, w1T, 1024, 2048, 2048, (long long)DD * HIDn, 0, 1, En);
    tconv(w2, w2T, 1024, 2048, 2048, (long long)DD * HIDn, 0, 1, En);
    tconv(w3, w3T, 2048, 1024, 1024, (long long)HIDn * DD, 0, 1, En);

    // ---- attention ----
    rmsnorm_kernel<<<NTOK, 256>>>(x, ns1, nullptr, bh);
    hgemm(NTOK, 1536, 1024, bh, 1024, 0, 0, 1,
          wqkvT, 1024, 0, 0, 1, qkv, 1536, 0, 0, 1, 1, 1, 0, nullptr);
    {
        long long tq = (long long)NTOK * HQn * 32;
        rope_kernel<<<(unsigned)((tq + 255) / 256), 256>>>(qkv, 0, HQn, tq);
        long long tk = (long long)NTOK * HKVn * 32;
        rope_kernel<<<(unsigned)((tk + 255) / 256), 256>>>(qkv, 1024, HKVn, tk);
    }
    sconv_kernel<<<(SZ_Q + 255) / 256, 256>>>(qkv, 1536, 1024, bq, SZ_Q);
    sconv_kernel<<<(SZ_K + 255) / 256, 256>>>(qkv + 1024, 1536, 256, bk, SZ_K);
    tconv(qkv + 1280, bvt, TT, VDn, 1536, (long long)TT * 1536, VDn, HKVn, BB * HKVn);

    flash_kernel<<<dim3(8, 32), 256, 49152>>>(bq, bk, bvt, batt);

    hgemm(NTOK, 1024, 1024, batt, 1024, 0, 0, 1,
          woT, 1024, 0, 0, 1, x1, 1024, 0, 0, 1, 1, 1, 2, x);

    // ---- MoE ----
    rmsnorm_kernel<<<NTOK, 256>>>(x1, ns2, h2, nullptr);
    router_kernel<<<NTOK, 256>>>(rw, rb);
    scan_kernel<<<1, 256>>>();
    {
        long long n = (long long)En * CAPn * DD;
        zero_kernel<<<(unsigned)((n + 255) / 256), 256>>>(grp, n);
    }
    scatter_kernel<<<NTOK * 2, 256>>>();
    conv4_kernel<<<(SZ_GRP / 4 + 255) / 256, 256>>>(grp, bgrp, SZ_GRP / 4);
    hgemm(CAPn, HIDn, DD,
          bgrp, 1024, (long long)CAPn * DD, 0, 1,
          w1T, 1024, (long long)HIDn * DD, 0, 1,
          t1, HIDn, (long long)CAPn * HIDn, 0, 1, En, 1, 0, nullptr);
    hgemm(CAPn, HIDn, DD,
          bgrp, 1024, (long long)CAPn * DD, 0, 1,
          w2T, 1024, (long long)HIDn * DD, 0, 1,
          t2, HIDn, (long long)CAPn * HIDn, 0, 1, En, 1, 0, nullptr);
    gelu_mul_kernel<<<(SZ_T1 / 4 + 255) / 256, 256>>>(bt1, SZ_T1 / 4);
    hgemm(CAPn, DD, HIDn,
          bt1, HIDn, (long long)CAPn * HIDn, 0, 1,
          w3T, 2048, (long long)DD * HIDn, 0, 1,
          eout, DD, (long long)CAPn * DD, 0, 1, En, 1, 0, nullptr);
    combine_kernel<<<NTOK, 256>>>((float*)d_out);
}

// round 10
// speedup vs baseline: 3.1522x; 1.0620x over previous
#include <cuda_runtime.h>
#include <cuda_fp16.h>
#include <math.h>
#include <stdint.h>

// ---------------- problem dims ----------------
#define BB    2
#define TT    1024
#define NTOK  2048
#define DD    1024
#define HQn   16
#define HKVn  4
#define KDn   64
#define VDn   64
#define Gn    4
#define En    8
#define CAPn  1024
#define HIDn  2048

// ---------------- fp32 scratch ----------------
__device__ float g_qkv [NTOK*1536];
__device__ float g_x1  [NTOK*DD];
__device__ float g_h2  [NTOK*DD];
__device__ float g_eout[En*CAPn*DD];
__device__ int   g_assign[NTOK*2];
__device__ float g_gate  [NTOK*2];
__device__ int   g_slot  [NTOK*2];
__device__ int   g_keep  [NTOK*2];

// ---------------- fp16 scratch ----------------
#define SZ_H    (NTOK*DD)
#define SZ_Q    (NTOK*HQn*KDn)
#define SZ_K    (NTOK*HKVn*KDn)
#define SZ_VT   (BB*HKVn*VDn*TT)
#define SZ_ATT  (NTOK*DD)
#define SZ_GRP  (En*CAPn*DD)
#define SZ_T1   (En*CAPn*HIDn)
#define SZ_QKVW (DD*1536)
#define SZ_WO   (DD*DD)
#define SZ_W1   (En*DD*HIDn)
#define SZ_W3   (En*HIDn*DD)

__device__ __half b_h    [SZ_H];
__device__ __half b_q    [SZ_Q];
__device__ __half b_k    [SZ_K];
__device__ __half b_vt   [SZ_VT];
__device__ __half b_attn [SZ_ATT];
__device__ __half b_grp  [SZ_GRP];
__device__ __half h_t1   [SZ_T1];
__device__ __half h_t2   [SZ_T1];
__device__ __half h_act  [SZ_T1];
__device__ __half b_wqkv [SZ_QKVW];     // [1024][1536] K-major packed
__device__ __half b_wo   [SZ_WO];       // [1024][1024] K-major
__device__ __half b_w1   [SZ_W1];       // [E][1024][2048]
__device__ __half b_w2   [SZ_W1];
__device__ __half b_w3   [SZ_W3];       // [E][2048][1024]

// ---------------- helpers ----------------
__device__ __forceinline__ uint32_t pack2h(float a, float b) {
    __half2 t = __floats2half2_rn(a, b);
    return *reinterpret_cast<uint32_t*>(&t);
}
__device__ __forceinline__ int swz(int row, int k) {
    return row * 16 + ((((k >> 3) ^ (row >> 2)) & 1) << 3) + (k & 7);
}

#define LDSM4(r0,r1,r2,r3,a) \
  asm volatile("ldmatrix.sync.aligned.m8n8.x4.shared.b16 {%0,%1,%2,%3}, [%4];" \
    : "=r"(r0), "=r"(r1), "=r"(r2), "=r"(r3) : "r"(a))

#define LDSM4T(r0,r1,r2,r3,a) \
  asm volatile("ldmatrix.sync.aligned.m8n8.x4.trans.shared.b16 {%0,%1,%2,%3}, [%4];" \
    : "=r"(r0), "=r"(r1), "=r"(r2), "=r"(r3) : "r"(a))

#define HMMA(d, a, b0, b1) \
  asm volatile("mma.sync.aligned.m16n8k16.row.col.f32.f16.f16.f32 " \
    "{%0,%1,%2,%3}, {%4,%5,%6,%7}, {%8,%9}, {%0,%1,%2,%3};" \
    : "+f"(d[0]), "+f"(d[1]), "+f"(d[2]), "+f"(d[3]) \
    : "r"(a[0]), "r"(a[1]), "r"(a[2]), "r"(a[3]), "r"(b0), "r"(b1))

// ---------------- small kernels ----------------
__global__ void rmsnorm_kernel(const float* __restrict__ x,
                               const float* __restrict__ scale,
                               float* __restrict__ outF,
                               __half* __restrict__ outH) {
    int row = blockIdx.x;
    const float* xr = x + (long long)row * DD;
    __shared__ float red[256];
    float s = 0.f;
    for (int d = threadIdx.x; d < DD; d += 256) { float v = xr[d]; s += v * v; }
    red[threadIdx.x] = s; __syncthreads();
    for (int o = 128; o > 0; o >>= 1) {
        if (threadIdx.x < o) red[threadIdx.x] += red[threadIdx.x + o];
        __syncthreads();
    }
    float inv = 1.0f / sqrtf(red[0] / (float)DD + 1e-6f);
    for (int d = threadIdx.x; d < DD; d += 256) {
        float v = xr[d] * inv * scale[d];
        if (outF) outF[(long long)row * DD + d] = v;
        if (outH) outH[(long long)row * DD + d] = __float2half(v);
    }
}

__global__ void rope_kernel(float* __restrict__ p, int colBase, int H, long long total) {
    long long i = (long long)blockIdx.x * 256 + threadIdx.x;
    if (i >= total) return;
    int j = (int)(i & 31);
    long long nh = i >> 5;
    int h = (int)(nh % H);
    long long n = nh / H;
    int t = (int)(n % TT);
    float* v = p + n * 1536 + colBase + h * 64;
    float theta = powf(10000.0f, -(2.0f * j) / 64.0f);
    float a = (float)t * theta;
    float c = cosf(a), s = sinf(a);
    float x1 = v[j], x2 = v[j + 32];
    v[j]      = x1 * c - x2 * s;
    v[j + 32] = x2 * c + x1 * s;
}

__global__ void router_kernel(const float* __restrict__ rw, const float* __restrict__ rb) {
    int t = blockIdx.x;
    const float* xr = g_h2 + (long long)t * DD;
    float part[En];
    #pragma unroll
    for (int e = 0; e < En; e++) part[e] = 0.f;
    for (int d = threadIdx.x; d < DD; d += 256) {
        float xv = xr[d];
        #pragma unroll
        for (int e = 0; e < En; e++) part[e] += xv * rw[d * En + e];
    }
    __shared__ float red[En][8];
    int lane = threadIdx.x & 31, warp = threadIdx.x >> 5;
    #pragma unroll
    for (int e = 0; e < En; e++) {
        float v = part[e];
        for (int o = 16; o > 0; o >>= 1) v += __shfl_down_sync(0xffffffffu, v, o);
        if (lane == 0) red[e][warp] = v;
    }
    __syncthreads();
    if (threadIdx.x == 0) {
        float lg[En];
        #pragma unroll
        for (int e = 0; e < En; e++) {
            float s = 0.f;
            for (int w = 0; w < 8; w++) s += red[e][w];
            lg[e] = s + rb[e];
        }
        int i0 = 0;
        for (int e = 1; e < En; e++) if (lg[e] > lg[i0]) i0 = e;
        int i1 = -1;
        for (int e = 0; e < En; e++) {
            if (e == i0) continue;
            if (i1 < 0 || lg[e] > lg[i1]) i1 = e;
        }
        float e1 = expf(lg[i1] - lg[i0]);
        float denom = 1.f + e1;
        g_assign[2 * t] = i0;     g_assign[2 * t + 1] = i1;
        g_gate[2 * t] = 1.f / denom; g_gate[2 * t + 1] = e1 / denom;
    }
}

__global__ void scan_kernel() {
    int lane = threadIdx.x & 31;
    int e = threadIdx.x >> 5;
    uint32_t mle = 0xFFFFFFFFu >> (31 - lane);
    int base0 = 0, base1 = 0;
    for (int chunk = 0; chunk < NTOK / 32; chunk++) {
        int t = chunk * 32 + lane;
        int a0 = g_assign[2 * t], a1 = g_assign[2 * t + 1];
        uint32_t b0 = __ballot_sync(0xFFFFFFFFu, a0 == e);
        uint32_t b1 = __ballot_sync(0xFFFFFFFFu, a1 == e);
        int incl0 = __popc(b0 & mle);
        int incl1 = __popc(b1 & mle);
        if (a0 == e) {
            int p0 = base0 + incl0;
            g_slot[2 * t] = p0; g_keep[2 * t] = (p0 < CAPn) ? 1 : 0;
        }
        if (a1 == e) {
            int p1 = (base0 + incl0) + (base1 + incl1);
            g_slot[2 * t + 1] = p1; g_keep[2 * t + 1] = (p1 < CAPn) ? 1 : 0;
        }
        base0 += __popc(b0); base1 += __popc(b1);
    }
}

__global__ void zeroh_kernel(__half* __restrict__ p, long long n8) {
    long long i = (long long)blockIdx.x * 256 + threadIdx.x;
    if (i < n8) *(uint4*)&p[i * 8] = make_uint4(0, 0, 0, 0);
}

__global__ void scatter_kernel() {
    int i = blockIdx.x;
    if (!g_keep[i]) return;
    int t = i >> 1;
    int e = g_assign[i], s = g_slot[i];
    __half2* dst = (__half2*)(b_grp + ((long long)e * CAPn + s) * DD);
    const float* src = g_h2 + (long long)t * DD;
    for (int d = threadIdx.x; d < DD / 2; d += 256) {
        __half2 v = __floats2half2_rn(src[2 * d], src[2 * d + 1]);
        atomicAdd(&dst[d], v);
    }
}

// gated gelu: reads h_t1,h_t2 (half), writes h_act (half), 8 elems/thread
__global__ void gelu_mul_kernel(long long n8) {
    long long i = (long long)blockIdx.x * 256 + threadIdx.x;
    if (i >= n8) return;
    uint4 av = *(const uint4*)&h_t1[i * 8];
    uint4 bv = *(const uint4*)&h_t2[i * 8];
    const uint32_t* aa = (const uint32_t*)&av;
    const uint32_t* bb = (const uint32_t*)&bv;
    uint4 ov;
    uint32_t* oo = (uint32_t*)&ov;
    #pragma unroll
    for (int j = 0; j < 4; j++) {
        __half2 a2 = *(const __half2*)&aa[j];
        __half2 b2 = *(const __half2*)&bb[j];
        float2 af = __half22float2(a2), bf = __half22float2(b2);
        float x0 = af.x * bf.x, x1 = af.y * bf.y;
        float r0 = 0.5f * x0 * (1.0f + tanhf(0.7978845608028654f * (x0 + 0.044715f * x0 * x0 * x0)));
        float r1 = 0.5f * x1 * (1.0f + tanhf(0.7978845608028654f * (x1 + 0.044715f * x1 * x1 * x1)));
        oo[j] = pack2h(r0, r1);
    }
    *(uint4*)&h_act[i * 8] = ov;
}

__global__ void combine_kernel(float* __restrict__ out) {
    int t = blockIdx.x;
    float gte0 = g_gate[2 * t], gte1 = g_gate[2 * t + 1];
    const float* s0 = g_keep[2 * t]
        ? g_eout + ((long long)g_assign[2 * t] * CAPn + g_slot[2 * t]) * DD
        : g_h2 + (long long)t * DD;
    const float* s1 = g_keep[2 * t + 1]
        ? g_eout + ((long long)g_assign[2 * t + 1] * CAPn + g_slot[2 * t + 1]) * DD
        : g_h2 + (long long)t * DD;
    const float* xr = g_x1 + (long long)t * DD;
    float* orow = out + (long long)t * DD;
    for (int d = threadIdx.x; d < DD; d += 256)
        orow[d] = xr[d] + gte0 * s0[d] + gte1 * s1[d];
}

__global__ void conv4_kernel(const float* __restrict__ src, __half* __restrict__ hi, long long n4) {
    long long i = (long long)blockIdx.x * 256 + threadIdx.x;
    if (i >= n4) return;
    float4 v = *(const float4*)&src[i * 4];
    uint2 hv;
    hv.x = pack2h(v.x, v.y); hv.y = pack2h(v.z, v.w);
    *(uint2*)&hi[i * 4] = hv;
}

// packed conv: dst[row*1536 + colOff + col] = src[row*Nsrc + col]
__global__ void pconv_kernel(const float* __restrict__ src, __half* __restrict__ dst,
                             int Nsrc, int colOff, long long n4) {
    long long i = (long long)blockIdx.x * 256 + threadIdx.x;
    if (i >= n4) return;
    int nq = Nsrc / 4;
    int row = (int)(i / nq), col = (int)(i % nq) * 4;
    float4 v = *(const float4*)&src[(long long)row * Nsrc + col];
    uint2 hv;
    hv.x = pack2h(v.x, v.y); hv.y = pack2h(v.z, v.w);
    *(uint2*)&dst[(long long)row * 1536 + colOff + col] = hv;
}

__global__ void sconv_kernel(const float* __restrict__ src, int srcStride, int width,
                             __half* __restrict__ hi, long long n) {
    long long i = (long long)blockIdx.x * 256 + threadIdx.x;
    if (i >= n) return;
    int row = (int)(i / width), col = (int)(i % width);
    hi[i] = __float2half(src[(long long)row * srcStride + col]);
}

__global__ void tconv_kernel(const float* __restrict__ src, __half* __restrict__ hi,
                             int R, int C, int lds, long long so, long long si, int zdiv) {
    int z = blockIdx.z;
    src += (long long)(z / zdiv) * so + (long long)(z % zdiv) * si;
    hi += (long long)z * R * C;
    __shared__ float t[32][33];
    int c0 = blockIdx.x * 32, r0 = blockIdx.y * 32;
    for (int i = threadIdx.y; i < 32; i += 8) {
        int r = r0 + i, c = c0 + threadIdx.x;
        if (r < R && c < C) t[i][threadIdx.x] = src[(long long)r * lds + c];
    }
    __syncthreads();
    for (int i = threadIdx.y; i < 32; i += 8) {
        int c = c0 + i, r = r0 + threadIdx.x;
        if (r < R && c < C)
            hi[(long long)c * R + r] = __float2half(t[threadIdx.x][i]);
    }
}

// ---------------- fp16 TN GEMM: C = A[M][K] * B[K][N], 3-stage ----------------
// A row-major, B row-major [K][N] (natural weight layout). b-frag via ldmatrix.trans.
#define AE (128*16)      // A tile elems
#define BE (16*128)      // B tile elems

__global__ void __launch_bounds__(256)
hgemm_kernel(int M, int N, int K,
             const __half* __restrict__ A, int lda, long long soA, int divA,
             const __half* __restrict__ B, int ldb, long long soB, int divB,
             float* __restrict__ C, int ldc, long long soC, int divC,
             int epi, int outHalf, const float* __restrict__ Rz) {
    int z = blockIdx.z;
    A += (long long)(z / divA) * soA;
    B += (long long)(z / divB) * soB;
    long long offC = (long long)(z / divC) * soC;
    const float* Rp = Rz ? (Rz + offC) : (const float*)0;

    int m0 = blockIdx.y * 128, n0 = blockIdx.x * 128;
    int tid = threadIdx.x;

    __shared__ __half sm[3][AE + BE];   // 24KB
    uint32_t sbase = (uint32_t)__cvta_generic_to_shared(&sm[0][0]);

    int lr = tid >> 1, lc = tid & 1;
    const __half* gA = A + (long long)(m0 + lr) * lda + lc * 8;
    uint32_t soffA = (uint32_t)swz(lr, lc * 8) * 2;

    int kr = tid >> 4, jj = tid & 15;
    const __half* gB = B + (long long)kr * ldb + n0 + jj * 8;
    uint32_t soffB = (uint32_t)((jj >> 1) * 256 + swz(kr, (jj & 1) * 8)) * 2;

    int KT = K / 16;

    auto prefetch = [&](int kt, int st) {
        uint32_t b0 = sbase + (uint32_t)(st * (AE + BE) * 2);
        asm volatile("cp.async.cg.shared.global [%0], [%1], 16;"
                     :: "r"(b0 + soffA), "l"(gA + (long long)kt * 16));
        asm volatile("cp.async.cg.shared.global [%0], [%1], 16;"
                     :: "r"(b0 + (uint32_t)(AE * 2) + soffB), "l"(gB + (long long)kt * 16 * ldb));
        asm volatile("cp.async.commit_group;");
    };

    float acc[4][4][4];
    #pragma unroll
    for (int i = 0; i < 4; i++)
        #pragma unroll
        for (int j = 0; j < 4; j++)
            #pragma unroll
            for (int e = 0; e < 4; e++) acc[i][j][e] = 0.f;

    int lane = tid & 31, wid = tid >> 5;
    int wm = wid & 1, wn = wid >> 1;
    int arow = wm * 64 + (lane & 15);
    int ak = (lane >> 4) * 8;
    uint32_t bline = (uint32_t)swz(lane & 15, (lane >> 4) * 8) * 2;

    prefetch(0, 0);
    if (KT > 1) prefetch(1, 1);

    for (int kt = 0; kt < KT; kt++) {
        if (kt + 2 < KT) {
            prefetch(kt + 2, (kt + 2) % 3);
            asm volatile("cp.async.wait_group 2;");
        } else if (kt + 1 < KT) {
            asm volatile("cp.async.wait_group 1;");
        } else {
            asm volatile("cp.async.wait_group 0;");
        }
        __syncthreads();

        uint32_t base = sbase + (uint32_t)((kt % 3) * (AE + BE) * 2);
        uint32_t fA[4][4], fB[4][2];
        #pragma unroll
        for (int mi = 0; mi < 4; mi++) {
            uint32_t ao = base + (uint32_t)swz(arow + mi * 16, ak) * 2;
            LDSM4(fA[mi][0], fA[mi][1], fA[mi][2], fA[mi][3], ao);
        }
        #pragma unroll
        for (int nj = 0; nj < 2; nj++) {
            uint32_t bo = base + (uint32_t)(AE * 2) + (uint32_t)((wn * 2 + nj) * 512) + bline;
            uint32_t r0, r1, r2, r3;
            LDSM4T(r0, r1, r2, r3, bo);
            fB[nj * 2][0] = r0; fB[nj * 2][1] = r1;
            fB[nj * 2 + 1][0] = r2; fB[nj * 2 + 1][1] = r3;
        }
        #pragma unroll
        for (int mi = 0; mi < 4; mi++)
            #pragma unroll
            for (int ni = 0; ni < 4; ni++)
                HMMA(acc[mi][ni], fA[mi], fB[ni][0], fB[ni][1]);
        __syncthreads();
    }

    int r4 = lane >> 2, c2 = (lane & 3) * 2;
    #pragma unroll
    for (int mi = 0; mi < 4; mi++)
        #pragma unroll
        for (int ni = 0; ni < 4; ni++) {
            int row = m0 + wm * 64 + mi * 16 + r4;
            int col = n0 + wn * 32 + ni * 8 + c2;
            #pragma unroll
            for (int e = 0; e < 4; e++) {
                int rr = row + (e >> 1) * 8;
                int cc = col + (e & 1);
                float v = acc[mi][ni][e];
                if (outHalf) {
                    ((__half*)C)[offC + (long long)rr * ldc + cc] = __float2half(v);
                } else {
                    if (epi == 2) v += Rp[(long long)rr * ldc + cc];
                    C[offC + (long long)rr * ldc + cc] = v;
                }
            }
        }
}

// ---------------- flash attention (fp16 single-pass) ----------------
__global__ void __launch_bounds__(256, 1)
flash_kernel(const __half* __restrict__ bq,
             const __half* __restrict__ bk,
             const __half* __restrict__ bvt,
             __half* __restrict__ batt) {
    extern __shared__ __half smf[];
    __half *qh = smf, *kh = smf + 8192, *vh = smf + 16384;

    int tid = threadIdx.x, lane = tid & 31, w = tid >> 5;
    int qb = blockIdx.x, bhid = blockIdx.y;
    int b = bhid >> 4, h = bhid & 15, hk = h >> 2;

    for (int idx = tid; idx < 2048; idx += 256) {
        int row = idx >> 4, c4 = (idx & 15) * 4;
        long long ga = ((long long)((b * 1024 + qb * 128 + row) * 16 + h)) * 64 + c4;
        int sa = (c4 >> 4) * 2048 + swz(row, c4 & 15);
        *(uint2*)&qh[sa] = *(const uint2*)&bq[ga];
    }

    uint32_t qbase = (uint32_t)__cvta_generic_to_shared(qh);
    uint32_t kbase = (uint32_t)__cvta_generic_to_shared(kh);
    uint32_t vbase = (uint32_t)__cvta_generic_to_shared(vh);

    float oAcc[8][4];
    #pragma unroll
    for (int i = 0; i < 8; i++)
        #pragma unroll
        for (int e = 0; e < 4; e++) oAcc[i][e] = 0.f;
    float m_prev[2] = {-1e30f, -1e30f};
    float l_run[2] = {0.f, 0.f};

    int arow = w * 16 + (lane & 15), akk = (lane >> 4) * 8;
    int brow = (lane & 7) + ((lane & 16) ? 8 : 0);
    int bko = (lane & 8) ? 8 : 0;
    int r4 = lane >> 2, c2 = (lane & 3) * 2;

    for (int kb = 0; kb <= qb; kb++) {
        __syncthreads();
        for (int idx = tid; idx < 2048; idx += 256) {
            int row = idx >> 4, c4 = (idx & 15) * 4;
            long long ga = ((long long)((b * 1024 + kb * 128 + row) * 4 + hk)) * 64 + c4;
            int sa = (c4 >> 4) * 2048 + swz(row, c4 & 15);
            *(uint2*)&kh[sa] = *(const uint2*)&bk[ga];
        }
        for (int idx = tid; idx < 2048; idx += 256) {
            int vd = idx >> 5, t4 = (idx & 31) * 4;
            long long ga = ((long long)((b * 4 + hk) * 64 + vd)) * 1024 + kb * 128 + t4;
            int sa = (t4 >> 4) * 1024 + swz(vd, t4 & 15);
            *(uint2*)&vh[sa] = *(const uint2*)&bvt[ga];
        }
        __syncthreads();

        float sAcc[16][4];
        #pragma unroll
        for (int t = 0; t < 16; t++)
            #pragma unroll
            for (int e = 0; e < 4; e++) sAcc[t][e] = 0.f;

        #pragma unroll
        for (int kk = 0; kk < 4; kk++) {
            uint32_t aH[4];
            uint32_t qa = qbase + (uint32_t)(kk * 2048 + swz(arow, akk)) * 2;
            LDSM4(aH[0], aH[1], aH[2], aH[3], qa);
            #pragma unroll
            for (int nb = 0; nb < 8; nb++) {
                uint32_t off = (uint32_t)(kk * 2048 + swz(nb * 16 + brow, bko)) * 2;
                uint32_t r0, r1, r2, r3;
                LDSM4(r0, r1, r2, r3, kbase + off);
                HMMA(sAcc[2 * nb],     aH, r0, r1);
                HMMA(sAcc[2 * nb + 1], aH, r2, r3);
            }
        }

        #pragma unroll
        for (int t = 0; t < 16; t++)
            #pragma unroll
            for (int e = 0; e < 4; e++) {
                float v = sAcc[t][e] * 0.125f;
                if (kb == qb) {
                    int col = t * 8 + c2 + (e & 1);
                    int rowl = w * 16 + r4 + ((e >> 1) ? 8 : 0);
                    if (col > rowl) v = -1e30f;
                }
                sAcc[t][e] = v;
            }

        float m0 = -1e30f, m1 = -1e30f;
        #pragma unroll
        for (int t = 0; t < 16; t++) {
            m0 = fmaxf(m0, fmaxf(sAcc[t][0], sAcc[t][1]));
            m1 = fmaxf(m1, fmaxf(sAcc[t][2], sAcc[t][3]));
        }
        m0 = fmaxf(m0, __shfl_xor_sync(0xFFFFFFFFu, m0, 1));
        m0 = fmaxf(m0, __shfl_xor_sync(0xFFFFFFFFu, m0, 2));
        m1 = fmaxf(m1, __shfl_xor_sync(0xFFFFFFFFu, m1, 1));
        m1 = fmaxf(m1, __shfl_xor_sync(0xFFFFFFFFu, m1, 2));
        float mn0 = fmaxf(m_prev[0], m0), mn1 = fmaxf(m_prev[1], m1);
        float al0 = __expf(m_prev[0] - mn0), al1 = __expf(m_prev[1] - mn1);
        float rs0 = 0.f, rs1 = 0.f;
        #pragma unroll
        for (int t = 0; t < 16; t++) {
            sAcc[t][0] = __expf(sAcc[t][0] - mn0);
            sAcc[t][1] = __expf(sAcc[t][1] - mn0);
            sAcc[t][2] = __expf(sAcc[t][2] - mn1);
            sAcc[t][3] = __expf(sAcc[t][3] - mn1);
            rs0 += sAcc[t][0] + sAcc[t][1];
            rs1 += sAcc[t][2] + sAcc[t][3];
        }
        rs0 += __shfl_xor_sync(0xFFFFFFFFu, rs0, 1);
        rs0 += __shfl_xor_sync(0xFFFFFFFFu, rs0, 2);
        rs1 += __shfl_xor_sync(0xFFFFFFFFu, rs1, 1);
        rs1 += __shfl_xor_sync(0xFFFFFFFFu, rs1, 2);
        l_run[0] = l_run[0] * al0 + rs0;
        l_run[1] = l_run[1] * al1 + rs1;
        m_prev[0] = mn0; m_prev[1] = mn1;
        #pragma unroll
        for (int ot = 0; ot < 8; ot++) {
            oAcc[ot][0] *= al0; oAcc[ot][1] *= al0;
            oAcc[ot][2] *= al1; oAcc[ot][3] *= al1;
        }

        #pragma unroll
        for (int kk = 0; kk < 8; kk++) {
            float* sA = sAcc[2 * kk];
            float* sB = sAcc[2 * kk + 1];
            uint32_t aH[4];
            aH[0] = pack2h(sA[0], sA[1]); aH[1] = pack2h(sA[2], sA[3]);
            aH[2] = pack2h(sB[0], sB[1]); aH[3] = pack2h(sB[2], sB[3]);
            #pragma unroll
            for (int vb = 0; vb < 4; vb++) {
                uint32_t off = (uint32_t)(kk * 1024 + swz(vb * 16 + brow, bko)) * 2;
                uint32_t r0, r1, r2, r3;
                LDSM4(r0, r1, r2, r3, vbase + off);
                HMMA(oAcc[2 * vb],     aH, r0, r1);
                HMMA(oAcc[2 * vb + 1], aH, r2, r3);
            }
        }
    }

    float inv0 = 1.f / l_run[0], inv1 = 1.f / l_run[1];
    #pragma unroll
    for (int ot = 0; ot < 8; ot++)
        #pragma unroll
        for (int e = 0; e < 4; e++) {
            float v = oAcc[ot][e] * ((e >> 1) ? inv1 : inv0);
            int rowl = w * 16 + r4 + ((e >> 1) ? 8 : 0);
            long long oi = ((long long)(b * 1024 + qb * 128 + rowl)) * 1024
                           + h * 64 + ot * 8 + c2 + (e & 1);
            batt[oi] = __float2half(v);
        }
}

// ---------------- launch ----------------
extern "C" void kernel_launch(void* const* d_in, const int* in_sizes, int n_in,
                              void* d_out, int out_size) {
    const float* x   = (const float*)d_in[0];
    const float* wq  = (const float*)d_in[1];
    const float* wk  = (const float*)d_in[2];
    const float* wv  = (const float*)d_in[3];
    const float* wo  = (const float*)d_in[4];
    const float* rw  = (const float*)d_in[5];
    const float* rb  = (const float*)d_in[6];
    const float* w1  = (const float*)d_in[7];
    const float* w2  = (const float*)d_in[8];
    const float* w3  = (const float*)d_in[9];
    const float* ns1 = (const float*)d_in[10];
    const float* ns2 = (const float*)d_in[11];

    float *qkv, *x1, *h2, *eout;
    cudaGetSymbolAddress((void**)&qkv, g_qkv);
    cudaGetSymbolAddress((void**)&x1, g_x1);
    cudaGetSymbolAddress((void**)&h2, g_h2);
    cudaGetSymbolAddress((void**)&eout, g_eout);

    __half *bh, *bq, *bk, *bvt, *batt, *bgrp, *t1h, *t2h, *acth;
    __half *wqkvh, *woh, *w1h, *w2h, *w3h;
    cudaGetSymbolAddress((void**)&bh, b_h);
    cudaGetSymbolAddress((void**)&bq, b_q);
    cudaGetSymbolAddress((void**)&bk, b_k);
    cudaGetSymbolAddress((void**)&bvt, b_vt);
    cudaGetSymbolAddress((void**)&batt, b_attn);
    cudaGetSymbolAddress((void**)&bgrp, b_grp);
    cudaGetSymbolAddress((void**)&t1h, h_t1);
    cudaGetSymbolAddress((void**)&t2h, h_t2);
    cudaGetSymbolAddress((void**)&acth, h_act);
    cudaGetSymbolAddress((void**)&wqkvh, b_wqkv);
    cudaGetSymbolAddress((void**)&woh, b_wo);
    cudaGetSymbolAddress((void**)&w1h, b_w1);
    cudaGetSymbolAddress((void**)&w2h, b_w2);
    cudaGetSymbolAddress((void**)&w3h, b_w3);

    cudaFuncSetAttribute(flash_kernel, cudaFuncAttributeMaxDynamicSharedMemorySize, 49152);

    auto hgemm = [&](int M, int N, int K,
                     const __half* A, int lda, long long soA, int divA,
                     const __half* B, int ldb, long long soB, int divB,
                     float* C, int ldc, long long soC, int divC,
                     int Z, int epi, int outHalf, const float* R) {
        dim3 grid(N / 128, M / 128, Z);
        hgemm_kernel<<<grid, 256>>>(M, N, K, A, lda, soA, divA,
            B, ldb, soB, divB, C, ldc, soC, divC, epi, outHalf, R);
    };

    // ---- weight conversion (no transposes) ----
    pconv_kernel<<<(DD * 1024 / 4 + 255) / 256, 256>>>(wq, wqkvh, 1024, 0, DD * 1024 / 4);
    pconv_kernel<<<(DD * 256 / 4 + 255) / 256, 256>>>(wk, wqkvh, 256, 1024, DD * 256 / 4);
    pconv_kernel<<<(DD * 256 / 4 + 255) / 256, 256>>>(wv, wqkvh, 256, 1280, DD * 256 / 4);
    conv4_kernel<<<(SZ_WO / 4 + 255) / 256, 256>>>(wo, woh, SZ_WO / 4);
    conv4_kernel<<<(SZ_W1 / 4 + 255) / 256, 256>>>(w1, w1h, SZ_W1 / 4);
    conv4_kernel<<<(SZ_W1 / 4 + 255) / 256, 256>>>(w2, w2h, SZ_W1 / 4);
    conv4_kernel<<<(SZ_W3 / 4 + 255) / 256, 256>>>(w3, w3h, SZ_W3 / 4);

    // ---- attention ----
    rmsnorm_kernel<<<NTOK, 256>>>(x, ns1, nullptr, bh);
    hgemm(NTOK, 1536, 1024, bh, 1024, 0, 1, wqkvh, 1536, 0, 1,
          qkv, 1536, 0, 1, 1, 0, 0, nullptr);
    {
        long long tq = (long long)NTOK * HQn * 32;
        rope_kernel<<<(unsigned)((tq + 255) / 256), 256>>>(qkv, 0, HQn, tq);
        long long tk = (long long)NTOK * HKVn * 32;
        rope_kernel<<<(unsigned)((tk + 255) / 256), 256>>>(qkv, 1024, HKVn, tk);
    }
    sconv_kernel<<<(SZ_Q + 255) / 256, 256>>>(qkv, 1536, 1024, bq, SZ_Q);
    sconv_kernel<<<(SZ_K + 255) / 256, 256>>>(qkv + 1024, 1536, 256, bk, SZ_K);
    {
        dim3 grid((VDn + 31) / 32, (TT + 31) / 32, BB * HKVn);
        tconv_kernel<<<grid, dim3(32, 8)>>>(qkv + 1280, bvt, TT, VDn, 1536,
                                            (long long)TT * 1536, VDn, HKVn);
    }

    flash_kernel<<<dim3(8, 32), 256, 49152>>>(bq, bk, bvt, batt);

    hgemm(NTOK, 1024, 1024, batt, 1024, 0, 1, woh, 1024, 0, 1,
          x1, 1024, 0, 1, 1, 2, 0, x);

    // ---- MoE ----
    rmsnorm_kernel<<<NTOK, 256>>>(x1, ns2, h2, nullptr);
    router_kernel<<<NTOK, 256>>>(rw, rb);
    scan_kernel<<<1, 256>>>();
    zeroh_kernel<<<(SZ_GRP / 8 + 255) / 256, 256>>>(bgrp, SZ_GRP / 8);
    scatter_kernel<<<NTOK * 2, 256>>>();
    hgemm(CAPn, HIDn, DD,
          bgrp, 1024, (long long)CAPn * DD, 1,
          w1h, 2048, (long long)DD * HIDn, 1,
          (float*)t1h, HIDn, (long long)CAPn * HIDn, 1, En, 0, 1, nullptr);
    hgemm(CAPn, HIDn, DD,
          bgrp, 1024, (long long)CAPn * DD, 1,
          w2h, 2048, (long long)DD * HIDn, 1,
          (float*)t2h, HIDn, (long long)CAPn * HIDn, 1, En, 0, 1, nullptr);
    gelu_mul_kernel<<<(SZ_T1 / 8 + 255) / 256, 256>>>(SZ_T1 / 8);
    hgemm(CAPn, DD, HIDn,
          acth, 2048, (long long)CAPn * HIDn, 1,
          w3h, 1024, (long long)HIDn * DD, 1,
          eout, DD, (long long)CAPn * DD, 1, En, 0, 0, nullptr);
    combine_kernel<<<NTOK, 256>>>((float*)d_out);
}

// round 12
// speedup vs baseline: 3.2631x; 1.0352x over previous
#include <cuda_runtime.h>
#include <cuda_fp16.h>
#include <math.h>
#include <stdint.h>

// ---------------- problem dims ----------------
#define BB    2
#define TT    1024
#define NTOK  2048
#define DD    1024
#define HQn   16
#define HKVn  4
#define KDn   64
#define VDn   64
#define Gn    4
#define En    8
#define CAPn  1024
#define HIDn  2048

// ---------------- fp32 scratch ----------------
__device__ float g_qkv [NTOK*1536];
__device__ float g_x1  [NTOK*DD];
__device__ float g_h2  [NTOK*DD];
__device__ float g_eout[En*CAPn*DD];
__device__ int   g_assign[NTOK*2];
__device__ float g_gate  [NTOK*2];
__device__ int   g_slot  [NTOK*2];
__device__ int   g_keep  [NTOK*2];

// ---------------- fp16 scratch ----------------
#define SZ_H    (NTOK*DD)
#define SZ_Q    (NTOK*HQn*KDn)
#define SZ_K    (NTOK*HKVn*KDn)
#define SZ_VT   (BB*HKVn*VDn*TT)
#define SZ_ATT  (NTOK*DD)
#define SZ_GRP  (En*CAPn*DD)
#define SZ_T1   (En*CAPn*HIDn)
#define SZ_T12  (En*CAPn*4096)
#define SZ_QKVW (DD*1536)
#define SZ_WO   (DD*DD)
#define SZ_W12  (En*DD*4096)
#define SZ_W3   (En*HIDn*DD)

__device__ __half b_h    [SZ_H];
__device__ __half b_q    [SZ_Q];
__device__ __half b_k    [SZ_K];
__device__ __half b_vt   [SZ_VT];
__device__ __half b_attn [SZ_ATT];
__device__ __half b_grp  [SZ_GRP];
__device__ __half h_t12  [SZ_T12];
__device__ __half h_act  [SZ_T1];
__device__ __half b_wqkv [SZ_QKVW];     // [1024][1536] K-major packed
__device__ __half b_wo   [SZ_WO];       // [1024][1024] K-major
__device__ __half b_w12  [SZ_W12];      // [E][1024][w1(2048)|w2(2048)]
__device__ __half b_w3   [SZ_W3];       // [E][2048][1024]

// ---------------- helpers ----------------
__device__ __forceinline__ uint32_t pack2h(float a, float b) {
    __half2 t = __floats2half2_rn(a, b);
    return *reinterpret_cast<uint32_t*>(&t);
}
__device__ __forceinline__ int swz(int row, int k) {
    return row * 16 + ((((k >> 3) ^ (row >> 2)) & 1) << 3) + (k & 7);
}

#define LDSM4(r0,r1,r2,r3,a) \
  asm volatile("ldmatrix.sync.aligned.m8n8.x4.shared.b16 {%0,%1,%2,%3}, [%4];" \
    : "=r"(r0), "=r"(r1), "=r"(r2), "=r"(r3) : "r"(a))

#define LDSM4T(r0,r1,r2,r3,a) \
  asm volatile("ldmatrix.sync.aligned.m8n8.x4.trans.shared.b16 {%0,%1,%2,%3}, [%4];" \
    : "=r"(r0), "=r"(r1), "=r"(r2), "=r"(r3) : "r"(a))

#define HMMA(d, a, b0, b1) \
  asm volatile("mma.sync.aligned.m16n8k16.row.col.f32.f16.f16.f32 " \
    "{%0,%1,%2,%3}, {%4,%5,%6,%7}, {%8,%9}, {%0,%1,%2,%3};" \
    : "+f"(d[0]), "+f"(d[1]), "+f"(d[2]), "+f"(d[3]) \
    : "r"(a[0]), "r"(a[1]), "r"(a[2]), "r"(a[3]), "r"(b0), "r"(b1))

// ---------------- small kernels ----------------
__global__ void rmsnorm_kernel(const float* __restrict__ x,
                               const float* __restrict__ scale,
                               float* __restrict__ outF,
                               __half* __restrict__ outH) {
    int row = blockIdx.x;
    const float* xr = x + (long long)row * DD;
    __shared__ float red[256];
    float s = 0.f;
    for (int d = threadIdx.x; d < DD; d += 256) { float v = xr[d]; s += v * v; }
    red[threadIdx.x] = s; __syncthreads();
    for (int o = 128; o > 0; o >>= 1) {
        if (threadIdx.x < o) red[threadIdx.x] += red[threadIdx.x + o];
        __syncthreads();
    }
    float inv = 1.0f / sqrtf(red[0] / (float)DD + 1e-6f);
    for (int d = threadIdx.x; d < DD; d += 256) {
        float v = xr[d] * inv * scale[d];
        if (outF) outF[(long long)row * DD + d] = v;
        if (outH) outH[(long long)row * DD + d] = __float2half(v);
    }
}

__global__ void rope_kernel(float* __restrict__ p, int colBase, int H, long long total) {
    long long i = (long long)blockIdx.x * 256 + threadIdx.x;
    if (i >= total) return;
    int j = (int)(i & 31);
    long long nh = i >> 5;
    int h = (int)(nh % H);
    long long n = nh / H;
    int t = (int)(n % TT);
    float* v = p + n * 1536 + colBase + h * 64;
    float theta = powf(10000.0f, -(2.0f * j) / 64.0f);
    float a = (float)t * theta;
    float c = cosf(a), s = sinf(a);
    float x1 = v[j], x2 = v[j + 32];
    v[j]      = x1 * c - x2 * s;
    v[j + 32] = x2 * c + x1 * s;
}

__global__ void router_kernel(const float* __restrict__ rw, const float* __restrict__ rb) {
    int t = blockIdx.x;
    const float* xr = g_h2 + (long long)t * DD;
    float part[En];
    #pragma unroll
    for (int e = 0; e < En; e++) part[e] = 0.f;
    for (int d = threadIdx.x; d < DD; d += 256) {
        float xv = xr[d];
        #pragma unroll
        for (int e = 0; e < En; e++) part[e] += xv * rw[d * En + e];
    }
    __shared__ float red[En][8];
    int lane = threadIdx.x & 31, warp = threadIdx.x >> 5;
    #pragma unroll
    for (int e = 0; e < En; e++) {
        float v = part[e];
        for (int o = 16; o > 0; o >>= 1) v += __shfl_down_sync(0xffffffffu, v, o);
        if (lane == 0) red[e][warp] = v;
    }
    __syncthreads();
    if (threadIdx.x == 0) {
        float lg[En];
        #pragma unroll
        for (int e = 0; e < En; e++) {
            float s = 0.f;
            for (int w = 0; w < 8; w++) s += red[e][w];
            lg[e] = s + rb[e];
        }
        int i0 = 0;
        for (int e = 1; e < En; e++) if (lg[e] > lg[i0]) i0 = e;
        int i1 = -1;
        for (int e = 0; e < En; e++) {
            if (e == i0) continue;
            if (i1 < 0 || lg[e] > lg[i1]) i1 = e;
        }
        float e1 = expf(lg[i1] - lg[i0]);
        float denom = 1.f + e1;
        g_assign[2 * t] = i0;     g_assign[2 * t + 1] = i1;
        g_gate[2 * t] = 1.f / denom; g_gate[2 * t + 1] = e1 / denom;
    }
}

__global__ void scan_kernel() {
    int lane = threadIdx.x & 31;
    int e = threadIdx.x >> 5;
    uint32_t mle = 0xFFFFFFFFu >> (31 - lane);
    int base0 = 0, base1 = 0;
    for (int chunk = 0; chunk < NTOK / 32; chunk++) {
        int t = chunk * 32 + lane;
        int a0 = g_assign[2 * t], a1 = g_assign[2 * t + 1];
        uint32_t b0 = __ballot_sync(0xFFFFFFFFu, a0 == e);
        uint32_t b1 = __ballot_sync(0xFFFFFFFFu, a1 == e);
        int incl0 = __popc(b0 & mle);
        int incl1 = __popc(b1 & mle);
        if (a0 == e) {
            int p0 = base0 + incl0;
            g_slot[2 * t] = p0; g_keep[2 * t] = (p0 < CAPn) ? 1 : 0;
        }
        if (a1 == e) {
            int p1 = (base0 + incl0) + (base1 + incl1);
            g_slot[2 * t + 1] = p1; g_keep[2 * t + 1] = (p1 < CAPn) ? 1 : 0;
        }
        base0 += __popc(b0); base1 += __popc(b1);
    }
}

__global__ void zeroh_kernel(__half* __restrict__ p, long long n8) {
    long long i = (long long)blockIdx.x * 256 + threadIdx.x;
    if (i < n8) *(uint4*)&p[i * 8] = make_uint4(0, 0, 0, 0);
}

__global__ void scatter_kernel() {
    int i = blockIdx.x;
    if (!g_keep[i]) return;
    int t = i >> 1;
    int e = g_assign[i], s = g_slot[i];
    __half2* dst = (__half2*)(b_grp + ((long long)e * CAPn + s) * DD);
    const float* src = g_h2 + (long long)t * DD;
    for (int d = threadIdx.x; d < DD / 2; d += 256) {
        __half2 v = __floats2half2_rn(src[2 * d], src[2 * d + 1]);
        atomicAdd(&dst[d], v);
    }
}

// gated gelu: t12 rows of 4096 = [w1out(2048) | w2out(2048)] -> h_act rows of 2048
__global__ void gelu_mul_kernel(long long n8) {
    long long i = (long long)blockIdx.x * 256 + threadIdx.x;
    if (i >= n8) return;
    long long idx = i * 8;                // output element index (rows of 2048)
    long long row = idx >> 11;
    int col = (int)(idx & 2047);
    const __half* base = h_t12 + row * 4096 + col;
    uint4 av = *(const uint4*)base;
    uint4 bv = *(const uint4*)(base + 2048);
    const uint32_t* aa = (const uint32_t*)&av;
    const uint32_t* bb = (const uint32_t*)&bv;
    uint4 ov;
    uint32_t* oo = (uint32_t*)&ov;
    #pragma unroll
    for (int j = 0; j < 4; j++) {
        __half2 a2 = *(const __half2*)&aa[j];
        __half2 b2 = *(const __half2*)&bb[j];
        float2 af = __half22float2(a2), bf = __half22float2(b2);
        float x0 = af.x * bf.x, x1 = af.y * bf.y;
        float r0 = 0.5f * x0 * (1.0f + tanhf(0.7978845608028654f * (x0 + 0.044715f * x0 * x0 * x0)));
        float r1 = 0.5f * x1 * (1.0f + tanhf(0.7978845608028654f * (x1 + 0.044715f * x1 * x1 * x1)));
        oo[j] = pack2h(r0, r1);
    }
    *(uint4*)&h_act[idx] = ov;
}

__global__ void combine_kernel(float* __restrict__ out) {
    int t = blockIdx.x;
    float gte0 = g_gate[2 * t], gte1 = g_gate[2 * t + 1];
    const float* s0 = g_keep[2 * t]
        ? g_eout + ((long long)g_assign[2 * t] * CAPn + g_slot[2 * t]) * DD
        : g_h2 + (long long)t * DD;
    const float* s1 = g_keep[2 * t + 1]
        ? g_eout + ((long long)g_assign[2 * t + 1] * CAPn + g_slot[2 * t + 1]) * DD
        : g_h2 + (long long)t * DD;
    const float* xr = g_x1 + (long long)t * DD;
    float* orow = out + (long long)t * DD;
    for (int d = threadIdx.x; d < DD; d += 256)
        orow[d] = xr[d] + gte0 * s0[d] + gte1 * s1[d];
}

__global__ void conv4_kernel(const float* __restrict__ src, __half* __restrict__ hi, long long n4) {
    long long i = (long long)blockIdx.x * 256 + threadIdx.x;
    if (i >= n4) return;
    float4 v = *(const float4*)&src[i * 4];
    uint2 hv;
    hv.x = pack2h(v.x, v.y); hv.y = pack2h(v.z, v.w);
    *(uint2*)&hi[i * 4] = hv;
}

// w1,w2 [E][1024][2048] fp32 -> w12 [E][1024][4096] fp16 (w1 cols 0-2047, w2 cols 2048-4095)
__global__ void w12conv_kernel(const float* __restrict__ w1, const float* __restrict__ w2,
                               long long n4) {
    long long i = (long long)blockIdx.x * 256 + threadIdx.x;
    if (i >= n4) return;
    long long idx = i * 4;                // element in [E*1024*2048]
    long long row = idx >> 11;
    int col = (int)(idx & 2047);
    float4 a = *(const float4*)&w1[idx];
    float4 b = *(const float4*)&w2[idx];
    uint2 ha, hb;
    ha.x = pack2h(a.x, a.y); ha.y = pack2h(a.z, a.w);
    hb.x = pack2h(b.x, b.y); hb.y = pack2h(b.z, b.w);
    *(uint2*)&b_w12[row * 4096 + col] = ha;
    *(uint2*)&b_w12[row * 4096 + 2048 + col] = hb;
}

// packed conv: dst[row*1536 + colOff + col] = src[row*Nsrc + col]
__global__ void pconv_kernel(const float* __restrict__ src, __half* __restrict__ dst,
                             int Nsrc, int colOff, long long n4) {
    long long i = (long long)blockIdx.x * 256 + threadIdx.x;
    if (i >= n4) return;
    int nq = Nsrc / 4;
    int row = (int)(i / nq), col = (int)(i % nq) * 4;
    float4 v = *(const float4*)&src[(long long)row * Nsrc + col];
    uint2 hv;
    hv.x = pack2h(v.x, v.y); hv.y = pack2h(v.z, v.w);
    *(uint2*)&dst[(long long)row * 1536 + colOff + col] = hv;
}

__global__ void sconv_kernel(const float* __restrict__ src, int srcStride, int width,
                             __half* __restrict__ hi, long long n) {
    long long i = (long long)blockIdx.x * 256 + threadIdx.x;
    if (i >= n) return;
    int row = (int)(i / width), col = (int)(i % width);
    hi[i] = __float2half(src[(long long)row * srcStride + col]);
}

__global__ void tconv_kernel(const float* __restrict__ src, __half* __restrict__ hi,
                             int R, int C, int lds, long long so, long long si, int zdiv) {
    int z = blockIdx.z;
    src += (long long)(z / zdiv) * so + (long long)(z % zdiv) * si;
    hi += (long long)z * R * C;
    __shared__ float t[32][33];
    int c0 = blockIdx.x * 32, r0 = blockIdx.y * 32;
    for (int i = threadIdx.y; i < 32; i += 8) {
        int r = r0 + i, c = c0 + threadIdx.x;
        if (r < R && c < C) t[i][threadIdx.x] = src[(long long)r * lds + c];
    }
    __syncthreads();
    for (int i = threadIdx.y; i < 32; i += 8) {
        int c = c0 + i, r = r0 + threadIdx.x;
        if (r < R && c < C)
            hi[(long long)c * R + r] = __float2half(t[threadIdx.x][i]);
    }
}

// ---------------- fp16 TN GEMM, BK=32: C = A[M][K] * B[K][N] ----------------
#define AE2 (128*32)      // A tile elems per stage
#define BE2 (32*128)      // B tile elems per stage

__global__ void __launch_bounds__(256)
hgemm_kernel(int M, int N, int K,
             const __half* __restrict__ A, int lda, long long soA, int divA,
             const __half* __restrict__ B, int ldb, long long soB, int divB,
             float* __restrict__ C, int ldc, long long soC, int divC,
             int epi, int outHalf, const float* __restrict__ Rz) {
    int z = blockIdx.z;
    A += (long long)(z / divA) * soA;
    B += (long long)(z / divB) * soB;
    long long offC = (long long)(z / divC) * soC;
    const float* Rp = Rz ? (Rz + offC) : (const float*)0;

    int m0 = blockIdx.y * 128, n0 = blockIdx.x * 128;
    int tid = threadIdx.x;

    __shared__ __half sm[3][AE2 + BE2];   // 48KB exactly
    uint32_t sbase = (uint32_t)__cvta_generic_to_shared(&sm[0][0]);

    int lr = tid >> 1, lc = tid & 1;
    const __half* gA = A + (long long)(m0 + lr) * lda + lc * 8;
    uint32_t soffA = (uint32_t)swz(lr, lc * 8) * 2;

    int kr = tid >> 4, jj = tid & 15;
    const __half* gB = B + (long long)kr * ldb + n0 + jj * 8;
    uint32_t soffB = (uint32_t)((jj >> 1) * 256 + swz(kr, (jj & 1) * 8)) * 2;

    int KT = K / 32;

    auto prefetch = [&](int kt, int st) {
        uint32_t b0 = sbase + (uint32_t)(st * (AE2 + BE2) * 2);
        #pragma unroll
        for (int ch = 0; ch < 2; ch++) {
            asm volatile("cp.async.cg.shared.global [%0], [%1], 16;"
                         :: "r"(b0 + (uint32_t)(ch * 2048 * 2) + soffA),
                            "l"(gA + (long long)kt * 32 + ch * 16));
            asm volatile("cp.async.cg.shared.global [%0], [%1], 16;"
                         :: "r"(b0 + (uint32_t)((AE2 + ch * 2048) * 2) + soffB),
                            "l"(gB + (long long)(kt * 32 + ch * 16) * ldb));
        }
        asm volatile("cp.async.commit_group;");
    };

    float acc[4][4][4];
    #pragma unroll
    for (int i = 0; i < 4; i++)
        #pragma unroll
        for (int j = 0; j < 4; j++)
            #pragma unroll
            for (int e = 0; e < 4; e++) acc[i][j][e] = 0.f;

    int lane = tid & 31, wid = tid >> 5;
    int wm = wid & 1, wn = wid >> 1;
    int arow = wm * 64 + (lane & 15);
    int ak = (lane >> 4) * 8;
    uint32_t bline = (uint32_t)swz(lane & 15, (lane >> 4) * 8) * 2;

    prefetch(0, 0);
    if (KT > 1) prefetch(1, 1);

    for (int kt = 0; kt < KT; kt++) {
        if (kt + 2 < KT) {
            prefetch(kt + 2, (kt + 2) % 3);
            asm volatile("cp.async.wait_group 2;");
        } else if (kt + 1 < KT) {
            asm volatile("cp.async.wait_group 1;");
        } else {
            asm volatile("cp.async.wait_group 0;");
        }
        __syncthreads();

        uint32_t base = sbase + (uint32_t)((kt % 3) * (AE2 + BE2) * 2);
        #pragma unroll
        for (int ks = 0; ks < 2; ks++) {
            uint32_t abase = base + (uint32_t)(ks * 2048 * 2);
            uint32_t bbase = base + (uint32_t)((AE2 + ks * 2048) * 2);
            uint32_t fA[4][4], fB[4][2];
            #pragma unroll
            for (int mi = 0; mi < 4; mi++) {
                uint32_t ao = abase + (uint32_t)swz(arow + mi * 16, ak) * 2;
                LDSM4(fA[mi][0], fA[mi][1], fA[mi][2], fA[mi][3], ao);
            }
            #pragma unroll
            for (int nj = 0; nj < 2; nj++) {
                uint32_t bo = bbase + (uint32_t)((wn * 2 + nj) * 512) + bline;
                uint32_t r0, r1, r2, r3;
                LDSM4T(r0, r1, r2, r3, bo);
                fB[nj * 2][0] = r0; fB[nj * 2][1] = r1;
                fB[nj * 2 + 1][0] = r2; fB[nj * 2 + 1][1] = r3;
            }
            #pragma unroll
            for (int mi = 0; mi < 4; mi++)
                #pragma unroll
                for (int ni = 0; ni < 4; ni++)
                    HMMA(acc[mi][ni], fA[mi], fB[ni][0], fB[ni][1]);
        }
        __syncthreads();
    }

    int r4 = lane >> 2, c2 = (lane & 3) * 2;
    #pragma unroll
    for (int mi = 0; mi < 4; mi++)
        #pragma unroll
        for (int ni = 0; ni < 4; ni++) {
            int row = m0 + wm * 64 + mi * 16 + r4;
            int col = n0 + wn * 32 + ni * 8 + c2;
            #pragma unroll
            for (int e = 0; e < 4; e++) {
                int rr = row + (e >> 1) * 8;
                int cc = col + (e & 1);
                float v = acc[mi][ni][e];
                if (outHalf) {
                    ((__half*)C)[offC + (long long)rr * ldc + cc] = __float2half(v);
                } else {
                    if (epi == 2) v += Rp[(long long)rr * ldc + cc];
                    C[offC + (long long)rr * ldc + cc] = v;
                }
            }
        }
}

// ---------------- flash attention (fp16 single-pass) ----------------
__global__ void __launch_bounds__(256, 1)
flash_kernel(const __half* __restrict__ bq,
             const __half* __restrict__ bk,
             const __half* __restrict__ bvt,
             __half* __restrict__ batt) {
    extern __shared__ __half smf[];
    __half *qh = smf, *kh = smf + 8192, *vh = smf + 16384;

    int tid = threadIdx.x, lane = tid & 31, w = tid >> 5;
    int qb = blockIdx.x, bhid = blockIdx.y;
    int b = bhid >> 4, h = bhid & 15, hk = h >> 2;

    for (int idx = tid; idx < 2048; idx += 256) {
        int row = idx >> 4, c4 = (idx & 15) * 4;
        long long ga = ((long long)((b * 1024 + qb * 128 + row) * 16 + h)) * 64 + c4;
        int sa = (c4 >> 4) * 2048 + swz(row, c4 & 15);
        *(uint2*)&qh[sa] = *(const uint2*)&bq[ga];
    }

    uint32_t qbase = (uint32_t)__cvta_generic_to_shared(qh);
    uint32_t kbase = (uint32_t)__cvta_generic_to_shared(kh);
    uint32_t vbase = (uint32_t)__cvta_generic_to_shared(vh);

    float oAcc[8][4];
    #pragma unroll
    for (int i = 0; i < 8; i++)
        #pragma unroll
        for (int e = 0; e < 4; e++) oAcc[i][e] = 0.f;
    float m_prev[2] = {-1e30f, -1e30f};
    float l_run[2] = {0.f, 0.f};

    int arow = w * 16 + (lane & 15), akk = (lane >> 4) * 8;
    int brow = (lane & 7) + ((lane & 16) ? 8 : 0);
    int bko = (lane & 8) ? 8 : 0;
    int r4 = lane >> 2, c2 = (lane & 3) * 2;

    for (int kb = 0; kb <= qb; kb++) {
        __syncthreads();
        for (int idx = tid; idx < 2048; idx += 256) {
            int row = idx >> 4, c4 = (idx & 15) * 4;
            long long ga = ((long long)((b * 1024 + kb * 128 + row) * 4 + hk)) * 64 + c4;
            int sa = (c4 >> 4) * 2048 + swz(row, c4 & 15);
            *(uint2*)&kh[sa] = *(const uint2*)&bk[ga];
        }
        for (int idx = tid; idx < 2048; idx += 256) {
            int vd = idx >> 5, t4 = (idx & 31) * 4;
            long long ga = ((long long)((b * 4 + hk) * 64 + vd)) * 1024 + kb * 128 + t4;
            int sa = (t4 >> 4) * 1024 + swz(vd, t4 & 15);
            *(uint2*)&vh[sa] = *(const uint2*)&bvt[ga];
        }
        __syncthreads();

        float sAcc[16][4];
        #pragma unroll
        for (int t = 0; t < 16; t++)
            #pragma unroll
            for (int e = 0; e < 4; e++) sAcc[t][e] = 0.f;

        #pragma unroll
        for (int kk = 0; kk < 4; kk++) {
            uint32_t aH[4];
            uint32_t qa = qbase + (uint32_t)(kk * 2048 + swz(arow, akk)) * 2;
            LDSM4(aH[0], aH[1], aH[2], aH[3], qa);
            #pragma unroll
            for (int nb = 0; nb < 8; nb++) {
                uint32_t off = (uint32_t)(kk * 2048 + swz(nb * 16 + brow, bko)) * 2;
                uint32_t r0, r1, r2, r3;
                LDSM4(r0, r1, r2, r3, kbase + off);
                HMMA(sAcc[2 * nb],     aH, r0, r1);
                HMMA(sAcc[2 * nb + 1], aH, r2, r3);
            }
        }

        #pragma unroll
        for (int t = 0; t < 16; t++)
            #pragma unroll
            for (int e = 0; e < 4; e++) {
                float v = sAcc[t][e] * 0.125f;
                if (kb == qb) {
                    int col = t * 8 + c2 + (e & 1);
                    int rowl = w * 16 + r4 + ((e >> 1) ? 8 : 0);
                    if (col > rowl) v = -1e30f;
                }
                sAcc[t][e] = v;
            }

        float m0 = -1e30f, m1 = -1e30f;
        #pragma unroll
        for (int t = 0; t < 16; t++) {
            m0 = fmaxf(m0, fmaxf(sAcc[t][0], sAcc[t][1]));
            m1 = fmaxf(m1, fmaxf(sAcc[t][2], sAcc[t][3]));
        }
        m0 = fmaxf(m0, __shfl_xor_sync(0xFFFFFFFFu, m0, 1));
        m0 = fmaxf(m0, __shfl_xor_sync(0xFFFFFFFFu, m0, 2));
        m1 = fmaxf(m1, __shfl_xor_sync(0xFFFFFFFFu, m1, 1));
        m1 = fmaxf(m1, __shfl_xor_sync(0xFFFFFFFFu, m1, 2));
        float mn0 = fmaxf(m_prev[0], m0), mn1 = fmaxf(m_prev[1], m1);
        float al0 = __expf(m_prev[0] - mn0), al1 = __expf(m_prev[1] - mn1);
        float rs0 = 0.f, rs1 = 0.f;
        #pragma unroll
        for (int t = 0; t < 16; t++) {
            sAcc[t][0] = __expf(sAcc[t][0] - mn0);
            sAcc[t][1] = __expf(sAcc[t][1] - mn0);
            sAcc[t][2] = __expf(sAcc[t][2] - mn1);
            sAcc[t][3] = __expf(sAcc[t][3] - mn1);
            rs0 += sAcc[t][0] + sAcc[t][1];
            rs1 += sAcc[t][2] + sAcc[t][3];
        }
        rs0 += __shfl_xor_sync(0xFFFFFFFFu, rs0, 1);
        rs0 += __shfl_xor_sync(0xFFFFFFFFu, rs0, 2);
        rs1 += __shfl_xor_sync(0xFFFFFFFFu, rs1, 1);
        rs1 += __shfl_xor_sync(0xFFFFFFFFu, rs1, 2);
        l_run[0] = l_run[0] * al0 + rs0;
        l_run[1] = l_run[1] * al1 + rs1;
        m_prev[0] = mn0; m_prev[1] = mn1;
        #pragma unroll
        for (int ot = 0; ot < 8; ot++) {
            oAcc[ot][0] *= al0; oAcc[ot][1] *= al0;
            oAcc[ot][2] *= al1; oAcc[ot][3] *= al1;
        }

        #pragma unroll
        for (int kk = 0; kk < 8; kk++) {
            float* sA = sAcc[2 * kk];
            float* sB = sAcc[2 * kk + 1];
            uint32_t aH[4];
            aH[0] = pack2h(sA[0], sA[1]); aH[1] = pack2h(sA[2], sA[3]);
            aH[2] = pack2h(sB[0], sB[1]); aH[3] = pack2h(sB[2], sB[3]);
            #pragma unroll
            for (int vb = 0; vb < 4; vb++) {
                uint32_t off = (uint32_t)(kk * 1024 + swz(vb * 16 + brow, bko)) * 2;
                uint32_t r0, r1, r2, r3;
                LDSM4(r0, r1, r2, r3, vbase + off);
                HMMA(oAcc[2 * vb],     aH, r0, r1);
                HMMA(oAcc[2 * vb + 1], aH, r2, r3);
            }
        }
    }

    float inv0 = 1.f / l_run[0], inv1 = 1.f / l_run[1];
    #pragma unroll
    for (int ot = 0; ot < 8; ot++)
        #pragma unroll
        for (int e = 0; e < 4; e++) {
            float v = oAcc[ot][e] * ((e >> 1) ? inv1 : inv0);
            int rowl = w * 16 + r4 + ((e >> 1) ? 8 : 0);
            long long oi = ((long long)(b * 1024 + qb * 128 + rowl)) * 1024
                           + h * 64 + ot * 8 + c2 + (e & 1);
            batt[oi] = __float2half(v);
        }
}

// ---------------- launch ----------------
extern "C" void kernel_launch(void* const* d_in, const int* in_sizes, int n_in,
                              void* d_out, int out_size) {
    const float* x   = (const float*)d_in[0];
    const float* wq  = (const float*)d_in[1];
    const float* wk  = (const float*)d_in[2];
    const float* wv  = (const float*)d_in[3];
    const float* wo  = (const float*)d_in[4];
    const float* rw  = (const float*)d_in[5];
    const float* rb  = (const float*)d_in[6];
    const float* w1  = (const float*)d_in[7];
    const float* w2  = (const float*)d_in[8];
    const float* w3  = (const float*)d_in[9];
    const float* ns1 = (const float*)d_in[10];
    const float* ns2 = (const float*)d_in[11];

    float *qkv, *x1, *h2, *eout;
    cudaGetSymbolAddress((void**)&qkv, g_qkv);
    cudaGetSymbolAddress((void**)&x1, g_x1);
    cudaGetSymbolAddress((void**)&h2, g_h2);
    cudaGetSymbolAddress((void**)&eout, g_eout);

    __half *bh, *bq, *bk, *bvt, *batt, *bgrp, *t12h, *acth;
    __half *wqkvh, *woh, *w12h, *w3h;
    cudaGetSymbolAddress((void**)&bh, b_h);
    cudaGetSymbolAddress((void**)&bq, b_q);
    cudaGetSymbolAddress((void**)&bk, b_k);
    cudaGetSymbolAddress((void**)&bvt, b_vt);
    cudaGetSymbolAddress((void**)&batt, b_attn);
    cudaGetSymbolAddress((void**)&bgrp, b_grp);
    cudaGetSymbolAddress((void**)&t12h, h_t12);
    cudaGetSymbolAddress((void**)&acth, h_act);
    cudaGetSymbolAddress((void**)&wqkvh, b_wqkv);
    cudaGetSymbolAddress((void**)&woh, b_wo);
    cudaGetSymbolAddress((void**)&w12h, b_w12);
    cudaGetSymbolAddress((void**)&w3h, b_w3);

    cudaFuncSetAttribute(flash_kernel, cudaFuncAttributeMaxDynamicSharedMemorySize, 49152);

    auto hgemm = [&](int M, int N, int K,
                     const __half* A, int lda, long long soA, int divA,
                     const __half* B, int ldb, long long soB, int divB,
                     float* C, int ldc, long long soC, int divC,
                     int Z, int epi, int outHalf, const float* R) {
        dim3 grid(N / 128, M / 128, Z);
        hgemm_kernel<<<grid, 256>>>(M, N, K, A, lda, soA, divA,
            B, ldb, soB, divB, C, ldc, soC, divC, epi, outHalf, R);
    };

    // ---- weight conversion (no transposes) ----
    pconv_kernel<<<(DD * 1024 / 4 + 255) / 256, 256>>>(wq, wqkvh, 1024, 0, DD * 1024 / 4);
    pconv_kernel<<<(DD * 256 / 4 + 255) / 256, 256>>>(wk, wqkvh, 256, 1024, DD * 256 / 4);
    pconv_kernel<<<(DD * 256 / 4 + 255) / 256, 256>>>(wv, wqkvh, 256, 1280, DD * 256 / 4);
    conv4_kernel<<<(SZ_WO / 4 + 255) / 256, 256>>>(wo, woh, SZ_WO / 4);
    w12conv_kernel<<<(SZ_T1 / 4 + 255) / 256, 256>>>(w1, w2, (long long)En * DD * HIDn / 4);
    conv4_kernel<<<(SZ_W3 / 4 + 255) / 256, 256>>>(w3, w3h, SZ_W3 / 4);

    // ---- attention ----
    rmsnorm_kernel<<<NTOK, 256>>>(x, ns1, nullptr, bh);
    hgemm(NTOK, 1536, 1024, bh, 1024, 0, 1, wqkvh, 1536, 0, 1,
          qkv, 1536, 0, 1, 1, 0, 0, nullptr);
    {
        long long tq = (long long)NTOK * HQn * 32;
        rope_kernel<<<(unsigned)((tq + 255) / 256), 256>>>(qkv, 0, HQn, tq);
        long long tk = (long long)NTOK * HKVn * 32;
        rope_kernel<<<(unsigned)((tk + 255) / 256), 256>>>(qkv, 1024, HKVn, tk);
    }
    sconv_kernel<<<(SZ_Q + 255) / 256, 256>>>(qkv, 1536, 1024, bq, SZ_Q);
    sconv_kernel<<<(SZ_K + 255) / 256, 256>>>(qkv + 1024, 1536, 256, bk, SZ_K);
    {
        dim3 grid((VDn + 31) / 32, (TT + 31) / 32, BB * HKVn);
        tconv_kernel<<<grid, dim3(32, 8)>>>(qkv + 1280, bvt, TT, VDn, 1536,
                                            (long long)TT * 1536, VDn, HKVn);
    }

    flash_kernel<<<dim3(8, 32), 256, 49152>>>(bq, bk, bvt, batt);

    hgemm(NTOK, 1024, 1024, batt, 1024, 0, 1, woh, 1024, 0, 1,
          x1, 1024, 0, 1, 1, 2, 0, x);

    // ---- MoE ----
    rmsnorm_kernel<<<NTOK, 256>>>(x1, ns2, h2, nullptr);
    router_kernel<<<NTOK, 256>>>(rw, rb);
    scan_kernel<<<1, 256>>>();
    zeroh_kernel<<<(SZ_GRP / 8 + 255) / 256, 256>>>(bgrp, SZ_GRP / 8);
    scatter_kernel<<<NTOK * 2, 256>>>();
    // fused w1|w2: one N=4096 GEMM per expert, fp16 out
    hgemm(CAPn, 4096, DD,
          bgrp, 1024, (long long)CAPn * DD, 1,
          w12h, 4096, (long long)DD * 4096, 1,
          (float*)t12h, 4096, (long long)CAPn * 4096, 1, En, 0, 1, nullptr);
    gelu_mul_kernel<<<(SZ_T1 / 8 + 255) / 256, 256>>>(SZ_T1 / 8);
    hgemm(CAPn, DD, HIDn,
          acth, 2048, (long long)CAPn * HIDn, 1,
          w3h, 1024, (long long)HIDn * DD, 1,
          eout, DD, (long long)CAPn * DD, 1, En, 0, 0, nullptr);
    combine_kernel<<<NTOK, 256>>>((float*)d_out);
}

// round 13
// speedup vs baseline: 3.2890x; 1.0079x over previous
#include <cuda_runtime.h>
#include <cuda_fp16.h>
#include <math.h>
#include <stdint.h>

// ---------------- problem dims ----------------
#define BB    2
#define TT    1024
#define NTOK  2048
#define DD    1024
#define HQn   16
#define HKVn  4
#define KDn   64
#define VDn   64
#define Gn    4
#define En    8
#define CAPn  1024
#define HIDn  2048

// ---------------- fp32 scratch ----------------
__device__ float g_qkv [NTOK*1536];
__device__ float g_x1  [NTOK*DD];
__device__ float g_h2  [NTOK*DD];
__device__ float g_eout[En*CAPn*DD];
__device__ int   g_assign[NTOK*2];
__device__ float g_gate  [NTOK*2];
__device__ int   g_slot  [NTOK*2];
__device__ int   g_keep  [NTOK*2];

// ---------------- fp16 scratch ----------------
#define SZ_H    (NTOK*DD)
#define SZ_Q    (NTOK*HQn*KDn)
#define SZ_K    (NTOK*HKVn*KDn)
#define SZ_VT   (BB*HKVn*VDn*TT)
#define SZ_ATT  (NTOK*DD)
#define SZ_GRP  (En*CAPn*DD)
#define SZ_T1   (En*CAPn*HIDn)
#define SZ_T12  (En*CAPn*4096)
#define SZ_QKVW (DD*1536)
#define SZ_WO   (DD*DD)
#define SZ_W12  (En*DD*4096)
#define SZ_W3   (En*HIDn*DD)

__device__ __half b_h    [SZ_H];
__device__ __half b_q    [SZ_Q];
__device__ __half b_k    [SZ_K];
__device__ __half b_vt   [SZ_VT];
__device__ __half b_attn [SZ_ATT];
__device__ __half b_grp  [SZ_GRP];
__device__ __half h_t12  [SZ_T12];
__device__ __half h_act  [SZ_T1];
__device__ __half b_wqkv [SZ_QKVW];
__device__ __half b_wo   [SZ_WO];
__device__ __half b_w12  [SZ_W12];
__device__ __half b_w3   [SZ_W3];

// ---------------- helpers ----------------
__device__ __forceinline__ uint32_t pack2h(float a, float b) {
    __half2 t = __floats2half2_rn(a, b);
    return *reinterpret_cast<uint32_t*>(&t);
}
__device__ __forceinline__ int swz(int row, int k) {
    return row * 16 + ((((k >> 3) ^ (row >> 2)) & 1) << 3) + (k & 7);
}

#define LDSM4(r0,r1,r2,r3,a) \
  asm volatile("ldmatrix.sync.aligned.m8n8.x4.shared.b16 {%0,%1,%2,%3}, [%4];" \
    : "=r"(r0), "=r"(r1), "=r"(r2), "=r"(r3) : "r"(a))

#define LDSM4T(r0,r1,r2,r3,a) \
  asm volatile("ldmatrix.sync.aligned.m8n8.x4.trans.shared.b16 {%0,%1,%2,%3}, [%4];" \
    : "=r"(r0), "=r"(r1), "=r"(r2), "=r"(r3) : "r"(a))

#define HMMA(d, a, b0, b1) \
  asm volatile("mma.sync.aligned.m16n8k16.row.col.f32.f16.f16.f32 " \
    "{%0,%1,%2,%3}, {%4,%5,%6,%7}, {%8,%9}, {%0,%1,%2,%3};" \
    : "+f"(d[0]), "+f"(d[1]), "+f"(d[2]), "+f"(d[3]) \
    : "r"(a[0]), "r"(a[1]), "r"(a[2]), "r"(a[3]), "r"(b0), "r"(b1))

// ---------------- small kernels ----------------
__global__ void rmsnorm_kernel(const float* __restrict__ x,
                               const float* __restrict__ scale,
                               float* __restrict__ outF,
                               __half* __restrict__ outH) {
    int row = blockIdx.x;
    const float* xr = x + (long long)row * DD;
    __shared__ float red[256];
    float s = 0.f;
    for (int d = threadIdx.x; d < DD; d += 256) { float v = xr[d]; s += v * v; }
    red[threadIdx.x] = s; __syncthreads();
    for (int o = 128; o > 0; o >>= 1) {
        if (threadIdx.x < o) red[threadIdx.x] += red[threadIdx.x + o];
        __syncthreads();
    }
    float inv = 1.0f / sqrtf(red[0] / (float)DD + 1e-6f);
    for (int d = threadIdx.x; d < DD; d += 256) {
        float v = xr[d] * inv * scale[d];
        if (outF) outF[(long long)row * DD + d] = v;
        if (outH) outH[(long long)row * DD + d] = __float2half(v);
    }
}

__global__ void rope_kernel(float* __restrict__ p, int colBase, int H, long long total) {
    long long i = (long long)blockIdx.x * 256 + threadIdx.x;
    if (i >= total) return;
    int j = (int)(i & 31);
    long long nh = i >> 5;
    int h = (int)(nh % H);
    long long n = nh / H;
    int t = (int)(n % TT);
    float* v = p + n * 1536 + colBase + h * 64;
    float theta = powf(10000.0f, -(2.0f * j) / 64.0f);
    float a = (float)t * theta;
    float c = cosf(a), s = sinf(a);
    float x1 = v[j], x2 = v[j + 32];
    v[j]      = x1 * c - x2 * s;
    v[j + 32] = x2 * c + x1 * s;
}

__global__ void router_kernel(const float* __restrict__ rw, const float* __restrict__ rb) {
    int t = blockIdx.x;
    const float* xr = g_h2 + (long long)t * DD;
    float part[En];
    #pragma unroll
    for (int e = 0; e < En; e++) part[e] = 0.f;
    for (int d = threadIdx.x; d < DD; d += 256) {
        float xv = xr[d];
        #pragma unroll
        for (int e = 0; e < En; e++) part[e] += xv * rw[d * En + e];
    }
    __shared__ float red[En][8];
    int lane = threadIdx.x & 31, warp = threadIdx.x >> 5;
    #pragma unroll
    for (int e = 0; e < En; e++) {
        float v = part[e];
        for (int o = 16; o > 0; o >>= 1) v += __shfl_down_sync(0xffffffffu, v, o);
        if (lane == 0) red[e][warp] = v;
    }
    __syncthreads();
    if (threadIdx.x == 0) {
        float lg[En];
        #pragma unroll
        for (int e = 0; e < En; e++) {
            float s = 0.f;
            for (int w = 0; w < 8; w++) s += red[e][w];
            lg[e] = s + rb[e];
        }
        int i0 = 0;
        for (int e = 1; e < En; e++) if (lg[e] > lg[i0]) i0 = e;
        int i1 = -1;
        for (int e = 0; e < En; e++) {
            if (e == i0) continue;
            if (i1 < 0 || lg[e] > lg[i1]) i1 = e;
        }
        float e1 = expf(lg[i1] - lg[i0]);
        float denom = 1.f + e1;
        g_assign[2 * t] = i0;     g_assign[2 * t + 1] = i1;
        g_gate[2 * t] = 1.f / denom; g_gate[2 * t + 1] = e1 / denom;
    }
}

__global__ void scan_kernel() {
    int lane = threadIdx.x & 31;
    int e = threadIdx.x >> 5;
    uint32_t mle = 0xFFFFFFFFu >> (31 - lane);
    int base0 = 0, base1 = 0;
    for (int chunk = 0; chunk < NTOK / 32; chunk++) {
        int t = chunk * 32 + lane;
        int a0 = g_assign[2 * t], a1 = g_assign[2 * t + 1];
        uint32_t b0 = __ballot_sync(0xFFFFFFFFu, a0 == e);
        uint32_t b1 = __ballot_sync(0xFFFFFFFFu, a1 == e);
        int incl0 = __popc(b0 & mle);
        int incl1 = __popc(b1 & mle);
        if (a0 == e) {
            int p0 = base0 + incl0;
            g_slot[2 * t] = p0; g_keep[2 * t] = (p0 < CAPn) ? 1 : 0;
        }
        if (a1 == e) {
            int p1 = (base0 + incl0) + (base1 + incl1);
            g_slot[2 * t + 1] = p1; g_keep[2 * t + 1] = (p1 < CAPn) ? 1 : 0;
        }
        base0 += __popc(b0); base1 += __popc(b1);
    }
}

__global__ void zeroh_kernel(__half* __restrict__ p, long long n8) {
    long long i = (long long)blockIdx.x * 256 + threadIdx.x;
    if (i < n8) *(uint4*)&p[i * 8] = make_uint4(0, 0, 0, 0);
}

__global__ void scatter_kernel() {
    int i = blockIdx.x;
    if (!g_keep[i]) return;
    int t = i >> 1;
    int e = g_assign[i], s = g_slot[i];
    __half2* dst = (__half2*)(b_grp + ((long long)e * CAPn + s) * DD);
    const float* src = g_h2 + (long long)t * DD;
    for (int d = threadIdx.x; d < DD / 2; d += 256) {
        __half2 v = __floats2half2_rn(src[2 * d], src[2 * d + 1]);
        atomicAdd(&dst[d], v);
    }
}

__global__ void gelu_mul_kernel(long long n8) {
    long long i = (long long)blockIdx.x * 256 + threadIdx.x;
    if (i >= n8) return;
    long long idx = i * 8;
    long long row = idx >> 11;
    int col = (int)(idx & 2047);
    const __half* base = h_t12 + row * 4096 + col;
    uint4 av = *(const uint4*)base;
    uint4 bv = *(const uint4*)(base + 2048);
    const uint32_t* aa = (const uint32_t*)&av;
    const uint32_t* bb = (const uint32_t*)&bv;
    uint4 ov;
    uint32_t* oo = (uint32_t*)&ov;
    #pragma unroll
    for (int j = 0; j < 4; j++) {
        __half2 a2 = *(const __half2*)&aa[j];
        __half2 b2 = *(const __half2*)&bb[j];
        float2 af = __half22float2(a2), bf = __half22float2(b2);
        float x0 = af.x * bf.x, x1 = af.y * bf.y;
        float r0 = 0.5f * x0 * (1.0f + tanhf(0.7978845608028654f * (x0 + 0.044715f * x0 * x0 * x0)));
        float r1 = 0.5f * x1 * (1.0f + tanhf(0.7978845608028654f * (x1 + 0.044715f * x1 * x1 * x1)));
        oo[j] = pack2h(r0, r1);
    }
    *(uint4*)&h_act[idx] = ov;
}

__global__ void combine_kernel(float* __restrict__ out) {
    int t = blockIdx.x;
    float gte0 = g_gate[2 * t], gte1 = g_gate[2 * t + 1];
    const float* s0 = g_keep[2 * t]
        ? g_eout + ((long long)g_assign[2 * t] * CAPn + g_slot[2 * t]) * DD
        : g_h2 + (long long)t * DD;
    const float* s1 = g_keep[2 * t + 1]
        ? g_eout + ((long long)g_assign[2 * t + 1] * CAPn + g_slot[2 * t + 1]) * DD
        : g_h2 + (long long)t * DD;
    const float* xr = g_x1 + (long long)t * DD;
    float* orow = out + (long long)t * DD;
    for (int d = threadIdx.x; d < DD; d += 256)
        orow[d] = xr[d] + gte0 * s0[d] + gte1 * s1[d];
}

__global__ void conv4_kernel(const float* __restrict__ src, __half* __restrict__ hi, long long n4) {
    long long i = (long long)blockIdx.x * 256 + threadIdx.x;
    if (i >= n4) return;
    float4 v = *(const float4*)&src[i * 4];
    uint2 hv;
    hv.x = pack2h(v.x, v.y); hv.y = pack2h(v.z, v.w);
    *(uint2*)&hi[i * 4] = hv;
}

__global__ void w12conv_kernel(const float* __restrict__ w1, const float* __restrict__ w2,
                               long long n4) {
    long long i = (long long)blockIdx.x * 256 + threadIdx.x;
    if (i >= n4) return;
    long long idx = i * 4;
    long long row = idx >> 11;
    int col = (int)(idx & 2047);
    float4 a = *(const float4*)&w1[idx];
    float4 b = *(const float4*)&w2[idx];
    uint2 ha, hb;
    ha.x = pack2h(a.x, a.y); ha.y = pack2h(a.z, a.w);
    hb.x = pack2h(b.x, b.y); hb.y = pack2h(b.z, b.w);
    *(uint2*)&b_w12[row * 4096 + col] = ha;
    *(uint2*)&b_w12[row * 4096 + 2048 + col] = hb;
}

__global__ void pconv_kernel(const float* __restrict__ src, __half* __restrict__ dst,
                             int Nsrc, int colOff, long long n4) {
    long long i = (long long)blockIdx.x * 256 + threadIdx.x;
    if (i >= n4) return;
    int nq = Nsrc / 4;
    int row = (int)(i / nq), col = (int)(i % nq) * 4;
    float4 v = *(const float4*)&src[(long long)row * Nsrc + col];
    uint2 hv;
    hv.x = pack2h(v.x, v.y); hv.y = pack2h(v.z, v.w);
    *(uint2*)&dst[(long long)row * 1536 + colOff + col] = hv;
}

__global__ void sconv_kernel(const float* __restrict__ src, int srcStride, int width,
                             __half* __restrict__ hi, long long n) {
    long long i = (long long)blockIdx.x * 256 + threadIdx.x;
    if (i >= n) return;
    int row = (int)(i / width), col = (int)(i % width);
    hi[i] = __float2half(src[(long long)row * srcStride + col]);
}

__global__ void tconv_kernel(const float* __restrict__ src, __half* __restrict__ hi,
                             int R, int C, int lds, long long so, long long si, int zdiv) {
    int z = blockIdx.z;
    src += (long long)(z / zdiv) * so + (long long)(z % zdiv) * si;
    hi += (long long)z * R * C;
    __shared__ float t[32][33];
    int c0 = blockIdx.x * 32, r0 = blockIdx.y * 32;
    for (int i = threadIdx.y; i < 32; i += 8) {
        int r = r0 + i, c = c0 + threadIdx.x;
        if (r < R && c < C) t[i][threadIdx.x] = src[(long long)r * lds + c];
    }
    __syncthreads();
    for (int i = threadIdx.y; i < 32; i += 8) {
        int c = c0 + i, r = r0 + threadIdx.x;
        if (r < R && c < C)
            hi[(long long)c * R + r] = __float2half(t[threadIdx.x][i]);
    }
}

// ---------------- fp16 TN GEMM, BK=32, templated N-tile ----------------
template<int NT>
__global__ void __launch_bounds__(256)
hgemm_kernel(int M, int N, int K,
             const __half* __restrict__ A, int lda, long long soA, int divA,
             const __half* __restrict__ B, int ldb, long long soB, int divB,
             float* __restrict__ C, int ldc, long long soC, int divC,
             int epi, int outHalf, const float* __restrict__ Rz) {
    constexpr int AE2 = 128 * 32;
    constexpr int BE2 = 32 * NT;
    constexpr int STG = AE2 + BE2;
    constexpr int NF = NT / 32;          // fB frag count per warp
    constexpr int NLOAD = NT / 128;      // B col passes per 16-row group

    int z = blockIdx.z;
    A += (long long)(z / divA) * soA;
    B += (long long)(z / divB) * soB;
    long long offC = (long long)(z / divC) * soC;
    const float* Rp = Rz ? (Rz + offC) : (const float*)0;

    int m0 = blockIdx.y * 128, n0 = blockIdx.x * NT;
    int tid = threadIdx.x;

    extern __shared__ __half sm[];       // 3 * STG
    uint32_t sbase = (uint32_t)__cvta_generic_to_shared(sm);

    int lr = tid >> 1, lc = tid & 1;
    const __half* gA = A + (long long)(m0 + lr) * lda + lc * 8;
    uint32_t soffA = (uint32_t)swz(lr, lc * 8) * 2;

    int kr = tid >> 4, jj = tid & 15;
    const __half* gB = B + (long long)kr * ldb + n0 + jj * 8;
    uint32_t soffB[NLOAD];
    #pragma unroll
    for (int p = 0; p < NLOAD; p++) {
        int jjx = jj + p * 16;
        soffB[p] = (uint32_t)((jjx >> 1) * 256 + swz(kr, (jjx & 1) * 8)) * 2;
    }

    int KT = K / 32;

    auto prefetch = [&](int kt, int st) {
        uint32_t b0 = sbase + (uint32_t)(st * STG * 2);
        #pragma unroll
        for (int ch = 0; ch < 2; ch++) {
            asm volatile("cp.async.cg.shared.global [%0], [%1], 16;"
                         :: "r"(b0 + (uint32_t)(ch * 2048 * 2) + soffA),
                            "l"(gA + (long long)kt * 32 + ch * 16));
            #pragma unroll
            for (int p = 0; p < NLOAD; p++) {
                asm volatile("cp.async.cg.shared.global [%0], [%1], 16;"
                             :: "r"(b0 + (uint32_t)((AE2 + ch * 16 * NT) * 2) + soffB[p]),
                                "l"(gB + (long long)(kt * 32 + ch * 16) * ldb + p * 128));
            }
        }
        asm volatile("cp.async.commit_group;");
    };

    float acc[4][NF][4];
    #pragma unroll
    for (int i = 0; i < 4; i++)
        #pragma unroll
        for (int j = 0; j < NF; j++)
            #pragma unroll
            for (int e = 0; e < 4; e++) acc[i][j][e] = 0.f;

    int lane = tid & 31, wid = tid >> 5;
    int wm = wid & 1, wn = wid >> 1;
    int arow = wm * 64 + (lane & 15);
    int ak = (lane >> 4) * 8;
    uint32_t bline = (uint32_t)swz(lane & 15, (lane >> 4) * 8) * 2;

    prefetch(0, 0);
    if (KT > 1) prefetch(1, 1);

    for (int kt = 0; kt < KT; kt++) {
        if (kt + 2 < KT) {
            prefetch(kt + 2, (kt + 2) % 3);
            asm volatile("cp.async.wait_group 2;");
        } else if (kt + 1 < KT) {
            asm volatile("cp.async.wait_group 1;");
        } else {
            asm volatile("cp.async.wait_group 0;");
        }
        __syncthreads();

        uint32_t base = sbase + (uint32_t)((kt % 3) * STG * 2);
        #pragma unroll
        for (int ks = 0; ks < 2; ks++) {
            uint32_t abase = base + (uint32_t)(ks * 2048 * 2);
            uint32_t bbase = base + (uint32_t)((AE2 + ks * 16 * NT) * 2);
            uint32_t fA[4][4];
            #pragma unroll
            for (int mi = 0; mi < 4; mi++) {
                uint32_t ao = abase + (uint32_t)swz(arow + mi * 16, ak) * 2;
                LDSM4(fA[mi][0], fA[mi][1], fA[mi][2], fA[mi][3], ao);
            }
            #pragma unroll
            for (int nj = 0; nj < NF / 2; nj++) {
                uint32_t bo = bbase + (uint32_t)((wn * (NF / 2) + nj) * 512) + bline;
                uint32_t r0, r1, r2, r3;
                LDSM4T(r0, r1, r2, r3, bo);
                #pragma unroll
                for (int mi = 0; mi < 4; mi++) {
                    HMMA(acc[mi][nj * 2],     fA[mi], r0, r1);
                    HMMA(acc[mi][nj * 2 + 1], fA[mi], r2, r3);
                }
            }
        }
        __syncthreads();
    }

    int r4 = lane >> 2, c2 = (lane & 3) * 2;
    #pragma unroll
    for (int mi = 0; mi < 4; mi++)
        #pragma unroll
        for (int ni = 0; ni < NF; ni++) {
            int row = m0 + wm * 64 + mi * 16 + r4;
            int col = n0 + wn * (NT / 4) + ni * 8 + c2;
            #pragma unroll
            for (int e = 0; e < 4; e++) {
                int rr = row + (e >> 1) * 8;
                int cc = col + (e & 1);
                float v = acc[mi][ni][e];
                if (outHalf) {
                    ((__half*)C)[offC + (long long)rr * ldc + cc] = __float2half(v);
                } else {
                    if (epi == 2) v += Rp[(long long)rr * ldc + cc];
                    C[offC + (long long)rr * ldc + cc] = v;
                }
            }
        }
}

// ---------------- flash attention (fp16 single-pass) ----------------
__global__ void __launch_bounds__(256, 1)
flash_kernel(const __half* __restrict__ bq,
             const __half* __restrict__ bk,
             const __half* __restrict__ bvt,
             __half* __restrict__ batt) {
    extern __shared__ __half smf[];
    __half *qh = smf, *kh = smf + 8192, *vh = smf + 16384;

    int tid = threadIdx.x, lane = tid & 31, w = tid >> 5;
    int qb = blockIdx.x, bhid = blockIdx.y;
    int b = bhid >> 4, h = bhid & 15, hk = h >> 2;

    for (int idx = tid; idx < 2048; idx += 256) {
        int row = idx >> 4, c4 = (idx & 15) * 4;
        long long ga = ((long long)((b * 1024 + qb * 128 + row) * 16 + h)) * 64 + c4;
        int sa = (c4 >> 4) * 2048 + swz(row, c4 & 15);
        *(uint2*)&qh[sa] = *(const uint2*)&bq[ga];
    }

    uint32_t qbase = (uint32_t)__cvta_generic_to_shared(qh);
    uint32_t kbase = (uint32_t)__cvta_generic_to_shared(kh);
    uint32_t vbase = (uint32_t)__cvta_generic_to_shared(vh);

    float oAcc[8][4];
    #pragma unroll
    for (int i = 0; i < 8; i++)
        #pragma unroll
        for (int e = 0; e < 4; e++) oAcc[i][e] = 0.f;
    float m_prev[2] = {-1e30f, -1e30f};
    float l_run[2] = {0.f, 0.f};

    int arow = w * 16 + (lane & 15), akk = (lane >> 4) * 8;
    int brow = (lane & 7) + ((lane & 16) ? 8 : 0);
    int bko = (lane & 8) ? 8 : 0;
    int r4 = lane >> 2, c2 = (lane & 3) * 2;

    for (int kb = 0; kb <= qb; kb++) {
        __syncthreads();
        for (int idx = tid; idx < 2048; idx += 256) {
            int row = idx >> 4, c4 = (idx & 15) * 4;
            long long ga = ((long long)((b * 1024 + kb * 128 + row) * 4 + hk)) * 64 + c4;
            int sa = (c4 >> 4) * 2048 + swz(row, c4 & 15);
            *(uint2*)&kh[sa] = *(const uint2*)&bk[ga];
        }
        for (int idx = tid; idx < 2048; idx += 256) {
            int vd = idx >> 5, t4 = (idx & 31) * 4;
            long long ga = ((long long)((b * 4 + hk) * 64 + vd)) * 1024 + kb * 128 + t4;
            int sa = (t4 >> 4) * 1024 + swz(vd, t4 & 15);
            *(uint2*)&vh[sa] = *(const uint2*)&bvt[ga];
        }
        __syncthreads();

        float sAcc[16][4];
        #pragma unroll
        for (int t = 0; t < 16; t++)
            #pragma unroll
            for (int e = 0; e < 4; e++) sAcc[t][e] = 0.f;

        #pragma unroll
        for (int kk = 0; kk < 4; kk++) {
            uint32_t aH[4];
            uint32_t qa = qbase + (uint32_t)(kk * 2048 + swz(arow, akk)) * 2;
            LDSM4(aH[0], aH[1], aH[2], aH[3], qa);
            #pragma unroll
            for (int nb = 0; nb < 8; nb++) {
                uint32_t off = (uint32_t)(kk * 2048 + swz(nb * 16 + brow, bko)) * 2;
                uint32_t r0, r1, r2, r3;
                LDSM4(r0, r1, r2, r3, kbase + off);
                HMMA(sAcc[2 * nb],     aH, r0, r1);
                HMMA(sAcc[2 * nb + 1], aH, r2, r3);
            }
        }

        #pragma unroll
        for (int t = 0; t < 16; t++)
            #pragma unroll
            for (int e = 0; e < 4; e++) {
                float v = sAcc[t][e] * 0.125f;
                if (kb == qb) {
                    int col = t * 8 + c2 + (e & 1);
                    int rowl = w * 16 + r4 + ((e >> 1) ? 8 : 0);
                    if (col > rowl) v = -1e30f;
                }
                sAcc[t][e] = v;
            }

        float m0 = -1e30f, m1 = -1e30f;
        #pragma unroll
        for (int t = 0; t < 16; t++) {
            m0 = fmaxf(m0, fmaxf(sAcc[t][0], sAcc[t][1]));
            m1 = fmaxf(m1, fmaxf(sAcc[t][2], sAcc[t][3]));
        }
        m0 = fmaxf(m0, __shfl_xor_sync(0xFFFFFFFFu, m0, 1));
        m0 = fmaxf(m0, __shfl_xor_sync(0xFFFFFFFFu, m0, 2));
        m1 = fmaxf(m1, __shfl_xor_sync(0xFFFFFFFFu, m1, 1));
        m1 = fmaxf(m1, __shfl_xor_sync(0xFFFFFFFFu, m1, 2));
        float mn0 = fmaxf(m_prev[0], m0), mn1 = fmaxf(m_prev[1], m1);
        float al0 = __expf(m_prev[0] - mn0), al1 = __expf(m_prev[1] - mn1);
        float rs0 = 0.f, rs1 = 0.f;
        #pragma unroll
        for (int t = 0; t < 16; t++) {
            sAcc[t][0] = __expf(sAcc[t][0] - mn0);
            sAcc[t][1] = __expf(sAcc[t][1] - mn0);
            sAcc[t][2] = __expf(sAcc[t][2] - mn1);
            sAcc[t][3] = __expf(sAcc[t][3] - mn1);
            rs0 += sAcc[t][0] + sAcc[t][1];
            rs1 += sAcc[t][2] + sAcc[t][3];
        }
        rs0 += __shfl_xor_sync(0xFFFFFFFFu, rs0, 1);
        rs0 += __shfl_xor_sync(0xFFFFFFFFu, rs0, 2);
        rs1 += __shfl_xor_sync(0xFFFFFFFFu, rs1, 1);
        rs1 += __shfl_xor_sync(0xFFFFFFFFu, rs1, 2);
        l_run[0] = l_run[0] * al0 + rs0;
        l_run[1] = l_run[1] * al1 + rs1;
        m_prev[0] = mn0; m_prev[1] = mn1;
        #pragma unroll
        for (int ot = 0; ot < 8; ot++) {
            oAcc[ot][0] *= al0; oAcc[ot][1] *= al0;
            oAcc[ot][2] *= al1; oAcc[ot][3] *= al1;
        }

        #pragma unroll
        for (int kk = 0; kk < 8; kk++) {
            float* sA = sAcc[2 * kk];
            float* sB = sAcc[2 * kk + 1];
            uint32_t aH[4];
            aH[0] = pack2h(sA[0], sA[1]); aH[1] = pack2h(sA[2], sA[3]);
            aH[2] = pack2h(sB[0], sB[1]); aH[3] = pack2h(sB[2], sB[3]);
            #pragma unroll
            for (int vb = 0; vb < 4; vb++) {
                uint32_t off = (uint32_t)(kk * 1024 + swz(vb * 16 + brow, bko)) * 2;
                uint32_t r0, r1, r2, r3;
                LDSM4(r0, r1, r2, r3, vbase + off);
                HMMA(oAcc[2 * vb],     aH, r0, r1);
                HMMA(oAcc[2 * vb + 1], aH, r2, r3);
            }
        }
    }

    float inv0 = 1.f / l_run[0], inv1 = 1.f / l_run[1];
    #pragma unroll
    for (int ot = 0; ot < 8; ot++)
        #pragma unroll
        for (int e = 0; e < 4; e++) {
            float v = oAcc[ot][e] * ((e >> 1) ? inv1 : inv0);
            int rowl = w * 16 + r4 + ((e >> 1) ? 8 : 0);
            long long oi = ((long long)(b * 1024 + qb * 128 + rowl)) * 1024
                           + h * 64 + ot * 8 + c2 + (e & 1);
            batt[oi] = __float2half(v);
        }
}

// ---------------- launch ----------------
extern "C" void kernel_launch(void* const* d_in, const int* in_sizes, int n_in,
                              void* d_out, int out_size) {
    const float* x   = (const float*)d_in[0];
    const float* wq  = (const float*)d_in[1];
    const float* wk  = (const float*)d_in[2];
    const float* wv  = (const float*)d_in[3];
    const float* wo  = (const float*)d_in[4];
    const float* rw  = (const float*)d_in[5];
    const float* rb  = (const float*)d_in[6];
    const float* w1  = (const float*)d_in[7];
    const float* w2  = (const float*)d_in[8];
    const float* w3  = (const float*)d_in[9];
    const float* ns1 = (const float*)d_in[10];
    const float* ns2 = (const float*)d_in[11];

    float *qkv, *x1, *h2, *eout;
    cudaGetSymbolAddress((void**)&qkv, g_qkv);
    cudaGetSymbolAddress((void**)&x1, g_x1);
    cudaGetSymbolAddress((void**)&h2, g_h2);
    cudaGetSymbolAddress((void**)&eout, g_eout);

    __half *bh, *bq, *bk, *bvt, *batt, *bgrp, *t12h, *acth;
    __half *wqkvh, *woh, *w12h, *w3h;
    cudaGetSymbolAddress((void**)&bh, b_h);
    cudaGetSymbolAddress((void**)&bq, b_q);
    cudaGetSymbolAddress((void**)&bk, b_k);
    cudaGetSymbolAddress((void**)&bvt, b_vt);
    cudaGetSymbolAddress((void**)&batt, b_attn);
    cudaGetSymbolAddress((void**)&bgrp, b_grp);
    cudaGetSymbolAddress((void**)&t12h, h_t12);
    cudaGetSymbolAddress((void**)&acth, h_act);
    cudaGetSymbolAddress((void**)&wqkvh, b_wqkv);
    cudaGetSymbolAddress((void**)&woh, b_wo);
    cudaGetSymbolAddress((void**)&w12h, b_w12);
    cudaGetSymbolAddress((void**)&w3h, b_w3);

    const int SM128 = 3 * (128 * 32 + 32 * 128) * 2;   // 49152
    const int SM256 = 3 * (128 * 32 + 32 * 256) * 2;   // 73728
    cudaFuncSetAttribute(hgemm_kernel<128>, cudaFuncAttributeMaxDynamicSharedMemorySize, SM128);
    cudaFuncSetAttribute(hgemm_kernel<256>, cudaFuncAttributeMaxDynamicSharedMemorySize, SM256);
    cudaFuncSetAttribute(flash_kernel, cudaFuncAttributeMaxDynamicSharedMemorySize, 49152);

    auto hgemm = [&](int NT, int M, int N, int K,
                     const __half* A, int lda, long long soA, int divA,
                     const __half* B, int ldb, long long soB, int divB,
                     float* C, int ldc, long long soC, int divC,
                     int Z, int epi, int outHalf, const float* R) {
        dim3 grid(N / NT, M / 128, Z);
        if (NT == 128)
            hgemm_kernel<128><<<grid, 256, SM128>>>(M, N, K, A, lda, soA, divA,
                B, ldb, soB, divB, C, ldc, soC, divC, epi, outHalf, R);
        else
            hgemm_kernel<256><<<grid, 256, SM256>>>(M, N, K, A, lda, soA, divA,
                B, ldb, soB, divB, C, ldc, soC, divC, epi, outHalf, R);
    };

    // ---- weight conversion (no transposes) ----
    pconv_kernel<<<(DD * 1024 / 4 + 255) / 256, 256>>>(wq, wqkvh, 1024, 0, DD * 1024 / 4);
    pconv_kernel<<<(DD * 256 / 4 + 255) / 256, 256>>>(wk, wqkvh, 256, 1024, DD * 256 / 4);
    pconv_kernel<<<(DD * 256 / 4 + 255) / 256, 256>>>(wv, wqkvh, 256, 1280, DD * 256 / 4);
    conv4_kernel<<<(SZ_WO / 4 + 255) / 256, 256>>>(wo, woh, SZ_WO / 4);
    w12conv_kernel<<<(SZ_T1 / 4 + 255) / 256, 256>>>(w1, w2, (long long)En * DD * HIDn / 4);
    conv4_kernel<<<(SZ_W3 / 4 + 255) / 256, 256>>>(w3, w3h, SZ_W3 / 4);

    // ---- attention ----
    rmsnorm_kernel<<<NTOK, 256>>>(x, ns1, nullptr, bh);
    hgemm(128, NTOK, 1536, 1024, bh, 1024, 0, 1, wqkvh, 1536, 0, 1,
          qkv, 1536, 0, 1, 1, 0, 0, nullptr);
    {
        long long tq = (long long)NTOK * HQn * 32;
        rope_kernel<<<(unsigned)((tq + 255) / 256), 256>>>(qkv, 0, HQn, tq);
        long long tk = (long long)NTOK * HKVn * 32;
        rope_kernel<<<(unsigned)((tk + 255) / 256), 256>>>(qkv, 1024, HKVn, tk);
    }
    sconv_kernel<<<(SZ_Q + 255) / 256, 256>>>(qkv, 1536, 1024, bq, SZ_Q);
    sconv_kernel<<<(SZ_K + 255) / 256, 256>>>(qkv + 1024, 1536, 256, bk, SZ_K);
    {
        dim3 grid((VDn + 31) / 32, (TT + 31) / 32, BB * HKVn);
        tconv_kernel<<<grid, dim3(32, 8)>>>(qkv + 1280, bvt, TT, VDn, 1536,
                                            (long long)TT * 1536, VDn, HKVn);
    }

    flash_kernel<<<dim3(8, 32), 256, 49152>>>(bq, bk, bvt, batt);

    hgemm(128, NTOK, 1024, 1024, batt, 1024, 0, 1, woh, 1024, 0, 1,
          x1, 1024, 0, 1, 1, 2, 0, x);

    // ---- MoE ----
    rmsnorm_kernel<<<NTOK, 256>>>(x1, ns2, h2, nullptr);
    router_kernel<<<NTOK, 256>>>(rw, rb);
    scan_kernel<<<1, 256>>>();
    zeroh_kernel<<<(SZ_GRP / 8 + 255) / 256, 256>>>(bgrp, SZ_GRP / 8);
    scatter_kernel<<<NTOK * 2, 256>>>();
    hgemm(256, CAPn, 4096, DD,
          bgrp, 1024, (long long)CAPn * DD, 1,
          w12h, 4096, (long long)DD * 4096, 1,
          (float*)t12h, 4096, (long long)CAPn * 4096, 1, En, 0, 1, nullptr);
    gelu_mul_kernel<<<(SZ_T1 / 8 + 255) / 256, 256>>>(SZ_T1 / 8);
    hgemm(256, CAPn, DD, HIDn,
          acth, 2048, (long long)CAPn * HIDn, 1,
          w3h, 1024, (long long)HIDn * DD, 1,
          eout, DD, (long long)CAPn * DD, 1, En, 0, 0, nullptr);
    combine_kernel<<<NTOK, 256>>>((float*)d_out);
}

// round 15
// speedup vs baseline: 4.5241x; 1.3755x over previous
#include <cuda_runtime.h>
#include <cuda_fp16.h>
#include <math.h>
#include <stdint.h>

// ---------------- problem dims ----------------
#define BB    2
#define TT    1024
#define NTOK  2048
#define DD    1024
#define HQn   16
#define HKVn  4
#define KDn   64
#define VDn   64
#define Gn    4
#define En    8
#define CAPn  1024
#define HIDn  2048

// ---------------- fp32 scratch ----------------
__device__ float g_qkv [NTOK*1536];
__device__ float g_x1  [NTOK*DD];
__device__ float g_h2  [NTOK*DD];
__device__ float g_eout[En*CAPn*DD];
__device__ int   g_assign[NTOK*2];
__device__ float g_gate  [NTOK*2];
__device__ int   g_slot  [NTOK*2];
__device__ int   g_keep  [NTOK*2];
__device__ int   g_mbound[En];          // per-expert used-row bound (mult of 128)

// ---------------- fp16 scratch ----------------
#define SZ_H    (NTOK*DD)
#define SZ_Q    (NTOK*HQn*KDn)
#define SZ_K    (NTOK*HKVn*KDn)
#define SZ_VT   (BB*HKVn*VDn*TT)
#define SZ_ATT  (NTOK*DD)
#define SZ_GRP  (En*CAPn*DD)
#define SZ_T1   (En*CAPn*HIDn)
#define SZ_T12  (En*CAPn*4096)
#define SZ_QKVW (DD*1536)
#define SZ_WO   (DD*DD)
#define SZ_W12  (En*DD*4096)
#define SZ_W3   (En*HIDn*DD)

__device__ __half b_h    [SZ_H];
__device__ __half b_q    [SZ_Q];
__device__ __half b_k    [SZ_K];
__device__ __half b_vt   [SZ_VT];
__device__ __half b_attn [SZ_ATT];
__device__ __half b_grp  [SZ_GRP];
__device__ __half h_t12  [SZ_T12];
__device__ __half h_act  [SZ_T1];
__device__ __half b_wqkv [SZ_QKVW];
__device__ __half b_wo   [SZ_WO];
__device__ __half b_w12  [SZ_W12];
__device__ __half b_w3   [SZ_W3];

// ---------------- helpers ----------------
__device__ __forceinline__ uint32_t pack2h(float a, float b) {
    __half2 t = __floats2half2_rn(a, b);
    return *reinterpret_cast<uint32_t*>(&t);
}
__device__ __forceinline__ int swz(int row, int k) {
    return row * 16 + ((((k >> 3) ^ (row >> 2)) & 1) << 3) + (k & 7);
}

#define LDSM4(r0,r1,r2,r3,a) \
  asm volatile("ldmatrix.sync.aligned.m8n8.x4.shared.b16 {%0,%1,%2,%3}, [%4];" \
    : "=r"(r0), "=r"(r1), "=r"(r2), "=r"(r3) : "r"(a))

#define LDSM4T(r0,r1,r2,r3,a) \
  asm volatile("ldmatrix.sync.aligned.m8n8.x4.trans.shared.b16 {%0,%1,%2,%3}, [%4];" \
    : "=r"(r0), "=r"(r1), "=r"(r2), "=r"(r3) : "r"(a))

#define HMMA(d, a, b0, b1) \
  asm volatile("mma.sync.aligned.m16n8k16.row.col.f32.f16.f16.f32 " \
    "{%0,%1,%2,%3}, {%4,%5,%6,%7}, {%8,%9}, {%0,%1,%2,%3};" \
    : "+f"(d[0]), "+f"(d[1]), "+f"(d[2]), "+f"(d[3]) \
    : "r"(a[0]), "r"(a[1]), "r"(a[2]), "r"(a[3]), "r"(b0), "r"(b1))

// ---------------- small kernels ----------------
__global__ void rmsnorm_kernel(const float* __restrict__ x,
                               const float* __restrict__ scale,
                               float* __restrict__ outF,
                               __half* __restrict__ outH) {
    int row = blockIdx.x;
    const float* xr = x + (long long)row * DD;
    __shared__ float red[256];
    float s = 0.f;
    for (int d = threadIdx.x; d < DD; d += 256) { float v = xr[d]; s += v * v; }
    red[threadIdx.x] = s; __syncthreads();
    for (int o = 128; o > 0; o >>= 1) {
        if (threadIdx.x < o) red[threadIdx.x] += red[threadIdx.x + o];
        __syncthreads();
    }
    float inv = 1.0f / sqrtf(red[0] / (float)DD + 1e-6f);
    for (int d = threadIdx.x; d < DD; d += 256) {
        float v = xr[d] * inv * scale[d];
        if (outF) outF[(long long)row * DD + d] = v;
        if (outH) outH[(long long)row * DD + d] = __float2half(v);
    }
}

__global__ void rope_kernel(float* __restrict__ p, int colBase, int H, long long total) {
    long long i = (long long)blockIdx.x * 256 + threadIdx.x;
    if (i >= total) return;
    int j = (int)(i & 31);
    long long nh = i >> 5;
    int h = (int)(nh % H);
    long long n = nh / H;
    int t = (int)(n % TT);
    float* v = p + n * 1536 + colBase + h * 64;
    float theta = powf(10000.0f, -(2.0f * j) / 64.0f);
    float a = (float)t * theta;
    float c = cosf(a), s = sinf(a);
    float x1 = v[j], x2 = v[j + 32];
    v[j]      = x1 * c - x2 * s;
    v[j + 32] = x2 * c + x1 * s;
}

__global__ void router_kernel(const float* __restrict__ rw, const float* __restrict__ rb) {
    int t = blockIdx.x;
    const float* xr = g_h2 + (long long)t * DD;
    float part[En];
    #pragma unroll
    for (int e = 0; e < En; e++) part[e] = 0.f;
    for (int d = threadIdx.x; d < DD; d += 256) {
        float xv = xr[d];
        #pragma unroll
        for (int e = 0; e < En; e++) part[e] += xv * rw[d * En + e];
    }
    __shared__ float red[En][8];
    int lane = threadIdx.x & 31, warp = threadIdx.x >> 5;
    #pragma unroll
    for (int e = 0; e < En; e++) {
        float v = part[e];
        for (int o = 16; o > 0; o >>= 1) v += __shfl_down_sync(0xffffffffu, v, o);
        if (lane == 0) red[e][warp] = v;
    }
    __syncthreads();
    if (threadIdx.x == 0) {
        float lg[En];
        #pragma unroll
        for (int e = 0; e < En; e++) {
            float s = 0.f;
            for (int w = 0; w < 8; w++) s += red[e][w];
            lg[e] = s + rb[e];
        }
        int i0 = 0;
        for (int e = 1; e < En; e++) if (lg[e] > lg[i0]) i0 = e;
        int i1 = -1;
        for (int e = 0; e < En; e++) {
            if (e == i0) continue;
            if (i1 < 0 || lg[e] > lg[i1]) i1 = e;
        }
        float e1 = expf(lg[i1] - lg[i0]);
        float denom = 1.f + e1;
        g_assign[2 * t] = i0;     g_assign[2 * t + 1] = i1;
        g_gate[2 * t] = 1.f / denom; g_gate[2 * t + 1] = e1 / denom;
    }
}

__global__ void scan_kernel() {
    int lane = threadIdx.x & 31;
    int e = threadIdx.x >> 5;
    uint32_t mle = 0xFFFFFFFFu >> (31 - lane);
    int base0 = 0, base1 = 0;
    for (int chunk = 0; chunk < NTOK / 32; chunk++) {
        int t = chunk * 32 + lane;
        int a0 = g_assign[2 * t], a1 = g_assign[2 * t + 1];
        uint32_t b0 = __ballot_sync(0xFFFFFFFFu, a0 == e);
        uint32_t b1 = __ballot_sync(0xFFFFFFFFu, a1 == e);
        int incl0 = __popc(b0 & mle);
        int incl1 = __popc(b1 & mle);
        if (a0 == e) {
            int p0 = base0 + incl0;
            g_slot[2 * t] = p0; g_keep[2 * t] = (p0 < CAPn) ? 1 : 0;
        }
        if (a1 == e) {
            int p1 = (base0 + incl0) + (base1 + incl1);
            g_slot[2 * t + 1] = p1; g_keep[2 * t + 1] = (p1 < CAPn) ? 1 : 0;
        }
        base0 += __popc(b0); base1 += __popc(b1);
    }
    // per-expert used-row bound: max kept slot <= min(1023, cnt0+cnt1)
    if (lane == 0) {
        int rows = base0 + base1 + 1;
        if (rows > CAPn) rows = CAPn;
        g_mbound[e] = ((rows + 127) / 128) * 128;
    }
}

__global__ void zeroh_kernel(__half* __restrict__ p, long long n8) {
    long long i = (long long)blockIdx.x * 256 + threadIdx.x;
    if (i < n8) *(uint4*)&p[i * 8] = make_uint4(0, 0, 0, 0);
}

__global__ void scatter_kernel() {
    int i = blockIdx.x;
    if (!g_keep[i]) return;
    int t = i >> 1;
    int e = g_assign[i], s = g_slot[i];
    __half2* dst = (__half2*)(b_grp + ((long long)e * CAPn + s) * DD);
    const float* src = g_h2 + (long long)t * DD;
    for (int d = threadIdx.x; d < DD / 2; d += 256) {
        __half2 v = __floats2half2_rn(src[2 * d], src[2 * d + 1]);
        atomicAdd(&dst[d], v);
    }
}

__global__ void gelu_mul_kernel(long long n8) {
    long long i = (long long)blockIdx.x * 256 + threadIdx.x;
    if (i >= n8) return;
    long long idx = i * 8;
    long long row = idx >> 11;
    // skip rows beyond the expert's used bound (t12 there is stale)
    int e = (int)(row >> 10);
    int rloc = (int)(row & 1023);
    if (rloc >= g_mbound[e]) return;
    int col = (int)(idx & 2047);
    const __half* base = h_t12 + row * 4096 + col;
    uint4 av = *(const uint4*)base;
    uint4 bv = *(const uint4*)(base + 2048);
    const uint32_t* aa = (const uint32_t*)&av;
    const uint32_t* bb = (const uint32_t*)&bv;
    uint4 ov;
    uint32_t* oo = (uint32_t*)&ov;
    #pragma unroll
    for (int j = 0; j < 4; j++) {
        __half2 a2 = *(const __half2*)&aa[j];
        __half2 b2 = *(const __half2*)&bb[j];
        float2 af = __half22float2(a2), bf = __half22float2(b2);
        float x0 = af.x * bf.x, x1 = af.y * bf.y;
        float r0 = 0.5f * x0 * (1.0f + tanhf(0.7978845608028654f * (x0 + 0.044715f * x0 * x0 * x0)));
        float r1 = 0.5f * x1 * (1.0f + tanhf(0.7978845608028654f * (x1 + 0.044715f * x1 * x1 * x1)));
        oo[j] = pack2h(r0, r1);
    }
    *(uint4*)&h_act[idx] = ov;
}

__global__ void combine_kernel(float* __restrict__ out) {
    int t = blockIdx.x;
    float gte0 = g_gate[2 * t], gte1 = g_gate[2 * t + 1];
    const float* s0 = g_keep[2 * t]
        ? g_eout + ((long long)g_assign[2 * t] * CAPn + g_slot[2 * t]) * DD
        : g_h2 + (long long)t * DD;
    const float* s1 = g_keep[2 * t + 1]
        ? g_eout + ((long long)g_assign[2 * t + 1] * CAPn + g_slot[2 * t + 1]) * DD
        : g_h2 + (long long)t * DD;
    const float* xr = g_x1 + (long long)t * DD;
    float* orow = out + (long long)t * DD;
    for (int d = threadIdx.x; d < DD; d += 256)
        orow[d] = xr[d] + gte0 * s0[d] + gte1 * s1[d];
}

__global__ void conv4_kernel(const float* __restrict__ src, __half* __restrict__ hi, long long n4) {
    long long i = (long long)blockIdx.x * 256 + threadIdx.x;
    if (i >= n4) return;
    float4 v = *(const float4*)&src[i * 4];
    uint2 hv;
    hv.x = pack2h(v.x, v.y); hv.y = pack2h(v.z, v.w);
    *(uint2*)&hi[i * 4] = hv;
}

__global__ void w12conv_kernel(const float* __restrict__ w1, const float* __restrict__ w2,
                               long long n4) {
    long long i = (long long)blockIdx.x * 256 + threadIdx.x;
    if (i >= n4) return;
    long long idx = i * 4;
    long long row = idx >> 11;
    int col = (int)(idx & 2047);
    float4 a = *(const float4*)&w1[idx];
    float4 b = *(const float4*)&w2[idx];
    uint2 ha, hb;
    ha.x = pack2h(a.x, a.y); ha.y = pack2h(a.z, a.w);
    hb.x = pack2h(b.x, b.y); hb.y = pack2h(b.z, b.w);
    *(uint2*)&b_w12[row * 4096 + col] = ha;
    *(uint2*)&b_w12[row * 4096 + 2048 + col] = hb;
}

__global__ void pconv_kernel(const float* __restrict__ src, __half* __restrict__ dst,
                             int Nsrc, int colOff, long long n4) {
    long long i = (long long)blockIdx.x * 256 + threadIdx.x;
    if (i >= n4) return;
    int nq = Nsrc / 4;
    int row = (int)(i / nq), col = (int)(i % nq) * 4;
    float4 v = *(const float4*)&src[(long long)row * Nsrc + col];
    uint2 hv;
    hv.x = pack2h(v.x, v.y); hv.y = pack2h(v.z, v.w);
    *(uint2*)&dst[(long long)row * 1536 + colOff + col] = hv;
}

__global__ void sconv_kernel(const float* __restrict__ src, int srcStride, int width,
                             __half* __restrict__ hi, long long n) {
    long long i = (long long)blockIdx.x * 256 + threadIdx.x;
    if (i >= n) return;
    int row = (int)(i / width), col = (int)(i % width);
    hi[i] = __float2half(src[(long long)row * srcStride + col]);
}

__global__ void tconv_kernel(const float* __restrict__ src, __half* __restrict__ hi,
                             int R, int C, int lds, long long so, long long si, int zdiv) {
    int z = blockIdx.z;
    src += (long long)(z / zdiv) * so + (long long)(z % zdiv) * si;
    hi += (long long)z * R * C;
    __shared__ float t[32][33];
    int c0 = blockIdx.x * 32, r0 = blockIdx.y * 32;
    for (int i = threadIdx.y; i < 32; i += 8) {
        int r = r0 + i, c = c0 + threadIdx.x;
        if (r < R && c < C) t[i][threadIdx.x] = src[(long long)r * lds + c];
    }
    __syncthreads();
    for (int i = threadIdx.y; i < 32; i += 8) {
        int c = c0 + i, r = r0 + threadIdx.x;
        if (r < R && c < C)
            hi[(long long)c * R + r] = __float2half(t[threadIdx.x][i]);
    }
}

// ---------------- fp16 TN GEMM, BK=32, templated N-tile, optional row bound ----------------
template<int NT>
__global__ void __launch_bounds__(256)
hgemm_kernel(int M, int N, int K,
             const __half* __restrict__ A, int lda, long long soA, int divA,
             const __half* __restrict__ B, int ldb, long long soB, int divB,
             float* __restrict__ C, int ldc, long long soC, int divC,
             int epi, int outHalf, const float* __restrict__ Rz,
             const int* __restrict__ mBound) {
    constexpr int AE2 = 128 * 32;
    constexpr int BE2 = 32 * NT;
    constexpr int STG = AE2 + BE2;
    constexpr int NF = NT / 32;
    constexpr int NLOAD = NT / 128;

    int z = blockIdx.z;
    int m0 = blockIdx.y * 128, n0 = blockIdx.x * NT;
    if (mBound && m0 >= mBound[z]) return;    // expert capacity row bound

    A += (long long)(z / divA) * soA;
    B += (long long)(z / divB) * soB;
    long long offC = (long long)(z / divC) * soC;
    const float* Rp = Rz ? (Rz + offC) : (const float*)0;

    int tid = threadIdx.x;

    extern __shared__ __half sm[];
    uint32_t sbase = (uint32_t)__cvta_generic_to_shared(sm);

    int lr = tid >> 1, lc = tid & 1;
    const __half* gA = A + (long long)(m0 + lr) * lda + lc * 8;
    uint32_t soffA = (uint32_t)swz(lr, lc * 8) * 2;

    int kr = tid >> 4, jj = tid & 15;
    const __half* gB = B + (long long)kr * ldb + n0 + jj * 8;
    uint32_t soffB[NLOAD];
    #pragma unroll
    for (int p = 0; p < NLOAD; p++) {
        int jjx = jj + p * 16;
        soffB[p] = (uint32_t)((jjx >> 1) * 256 + swz(kr, (jjx & 1) * 8)) * 2;
    }

    int KT = K / 32;

    auto prefetch = [&](int kt, int st) {
        uint32_t b0 = sbase + (uint32_t)(st * STG * 2);
        #pragma unroll
        for (int ch = 0; ch < 2; ch++) {
            asm volatile("cp.async.cg.shared.global [%0], [%1], 16;"
                         :: "r"(b0 + (uint32_t)(ch * 2048 * 2) + soffA),
                            "l"(gA + (long long)kt * 32 + ch * 16));
            #pragma unroll
            for (int p = 0; p < NLOAD; p++) {
                asm volatile("cp.async.cg.shared.global [%0], [%1], 16;"
                             :: "r"(b0 + (uint32_t)((AE2 + ch * 16 * NT) * 2) + soffB[p]),
                                "l"(gB + (long long)(kt * 32 + ch * 16) * ldb + p * 128));
            }
        }
        asm volatile("cp.async.commit_group;");
    };

    float acc[4][NF][4];
    #pragma unroll
    for (int i = 0; i < 4; i++)
        #pragma unroll
        for (int j = 0; j < NF; j++)
            #pragma unroll
            for (int e = 0; e < 4; e++) acc[i][j][e] = 0.f;

    int lane = tid & 31, wid = tid >> 5;
    int wm = wid & 1, wn = wid >> 1;
    int arow = wm * 64 + (lane & 15);
    int ak = (lane >> 4) * 8;
    uint32_t bline = (uint32_t)swz(lane & 15, (lane >> 4) * 8) * 2;

    prefetch(0, 0);
    if (KT > 1) prefetch(1, 1);

    for (int kt = 0; kt < KT; kt++) {
        if (kt + 2 < KT) {
            prefetch(kt + 2, (kt + 2) % 3);
            asm volatile("cp.async.wait_group 2;");
        } else if (kt + 1 < KT) {
            asm volatile("cp.async.wait_group 1;");
        } else {
            asm volatile("cp.async.wait_group 0;");
        }
        __syncthreads();

        uint32_t base = sbase + (uint32_t)((kt % 3) * STG * 2);
        #pragma unroll
        for (int ks = 0; ks < 2; ks++) {
            uint32_t abase = base + (uint32_t)(ks * 2048 * 2);
            uint32_t bbase = base + (uint32_t)((AE2 + ks * 16 * NT) * 2);
            uint32_t fA[4][4];
            #pragma unroll
            for (int mi = 0; mi < 4; mi++) {
                uint32_t ao = abase + (uint32_t)swz(arow + mi * 16, ak) * 2;
                LDSM4(fA[mi][0], fA[mi][1], fA[mi][2], fA[mi][3], ao);
            }
            #pragma unroll
            for (int nj = 0; nj < NF / 2; nj++) {
                uint32_t bo = bbase + (uint32_t)((wn * (NF / 2) + nj) * 512) + bline;
                uint32_t r0, r1, r2, r3;
                LDSM4T(r0, r1, r2, r3, bo);
                #pragma unroll
                for (int mi = 0; mi < 4; mi++) {
                    HMMA(acc[mi][nj * 2],     fA[mi], r0, r1);
                    HMMA(acc[mi][nj * 2 + 1], fA[mi], r2, r3);
                }
            }
        }
        __syncthreads();
    }

    int r4 = lane >> 2, c2 = (lane & 3) * 2;
    #pragma unroll
    for (int mi = 0; mi < 4; mi++)
        #pragma unroll
        for (int ni = 0; ni < NF; ni++) {
            int row = m0 + wm * 64 + mi * 16 + r4;
            int col = n0 + wn * (NT / 4) + ni * 8 + c2;
            #pragma unroll
            for (int e = 0; e < 4; e++) {
                int rr = row + (e >> 1) * 8;
                int cc = col + (e & 1);
                float v = acc[mi][ni][e];
                if (outHalf) {
                    ((__half*)C)[offC + (long long)rr * ldc + cc] = __float2half(v);
                } else {
                    if (epi == 2) v += Rp[(long long)rr * ldc + cc];
                    C[offC + (long long)rr * ldc + cc] = v;
                }
            }
        }
}

// ---------------- flash attention (fp16 single-pass) ----------------
__global__ void __launch_bounds__(256, 1)
flash_kernel(const __half* __restrict__ bq,
             const __half* __restrict__ bk,
             const __half* __restrict__ bvt,
             __half* __restrict__ batt) {
    extern __shared__ __half smf[];
    __half *qh = smf, *kh = smf + 8192, *vh = smf + 16384;

    int tid = threadIdx.x, lane = tid & 31, w = tid >> 5;
    int qb = blockIdx.x, bhid = blockIdx.y;
    int b = bhid >> 4, h = bhid & 15, hk = h >> 2;

    for (int idx = tid; idx < 2048; idx += 256) {
        int row = idx >> 4, c4 = (idx & 15) * 4;
        long long ga = ((long long)((b * 1024 + qb * 128 + row) * 16 + h)) * 64 + c4;
        int sa = (c4 >> 4) * 2048 + swz(row, c4 & 15);
        *(uint2*)&qh[sa] = *(const uint2*)&bq[ga];
    }

    uint32_t qbase = (uint32_t)__cvta_generic_to_shared(qh);
    uint32_t kbase = (uint32_t)__cvta_generic_to_shared(kh);
    uint32_t vbase = (uint32_t)__cvta_generic_to_shared(vh);

    float oAcc[8][4];
    #pragma unroll
    for (int i = 0; i < 8; i++)
        #pragma unroll
        for (int e = 0; e < 4; e++) oAcc[i][e] = 0.f;
    float m_prev[2] = {-1e30f, -1e30f};
    float l_run[2] = {0.f, 0.f};

    int arow = w * 16 + (lane & 15), akk = (lane >> 4) * 8;
    int brow = (lane & 7) + ((lane & 16) ? 8 : 0);
    int bko = (lane & 8) ? 8 : 0;
    int r4 = lane >> 2, c2 = (lane & 3) * 2;

    for (int kb = 0; kb <= qb; kb++) {
        __syncthreads();
        for (int idx = tid; idx < 2048; idx += 256) {
            int row = idx >> 4, c4 = (idx & 15) * 4;
            long long ga = ((long long)((b * 1024 + kb * 128 + row) * 4 + hk)) * 64 + c4;
            int sa = (c4 >> 4) * 2048 + swz(row, c4 & 15);
            *(uint2*)&kh[sa] = *(const uint2*)&bk[ga];
        }
        for (int idx = tid; idx < 2048; idx += 256) {
            int vd = idx >> 5, t4 = (idx & 31) * 4;
            long long ga = ((long long)((b * 4 + hk) * 64 + vd)) * 1024 + kb * 128 + t4;
            int sa = (t4 >> 4) * 1024 + swz(vd, t4 & 15);
            *(uint2*)&vh[sa] = *(const uint2*)&bvt[ga];
        }
        __syncthreads();

        float sAcc[16][4];
        #pragma unroll
        for (int t = 0; t < 16; t++)
            #pragma unroll
            for (int e = 0; e < 4; e++) sAcc[t][e] = 0.f;

        #pragma unroll
        for (int kk = 0; kk < 4; kk++) {
            uint32_t aH[4];
            uint32_t qa = qbase + (uint32_t)(kk * 2048 + swz(arow, akk)) * 2;
            LDSM4(aH[0], aH[1], aH[2], aH[3], qa);
            #pragma unroll
            for (int nb = 0; nb < 8; nb++) {
                uint32_t off = (uint32_t)(kk * 2048 + swz(nb * 16 + brow, bko)) * 2;
                uint32_t r0, r1, r2, r3;
                LDSM4(r0, r1, r2, r3, kbase + off);
                HMMA(sAcc[2 * nb],     aH, r0, r1);
                HMMA(sAcc[2 * nb + 1], aH, r2, r3);
            }
        }

        #pragma unroll
        for (int t = 0; t < 16; t++)
            #pragma unroll
            for (int e = 0; e < 4; e++) {
                float v = sAcc[t][e] * 0.125f;
                if (kb == qb) {
                    int col = t * 8 + c2 + (e & 1);
                    int rowl = w * 16 + r4 + ((e >> 1) ? 8 : 0);
                    if (col > rowl) v = -1e30f;
                }
                sAcc[t][e] = v;
            }

        float m0 = -1e30f, m1 = -1e30f;
        #pragma unroll
        for (int t = 0; t < 16; t++) {
            m0 = fmaxf(m0, fmaxf(sAcc[t][0], sAcc[t][1]));
            m1 = fmaxf(m1, fmaxf(sAcc[t][2], sAcc[t][3]));
        }
        m0 = fmaxf(m0, __shfl_xor_sync(0xFFFFFFFFu, m0, 1));
        m0 = fmaxf(m0, __shfl_xor_sync(0xFFFFFFFFu, m0, 2));
        m1 = fmaxf(m1, __shfl_xor_sync(0xFFFFFFFFu, m1, 1));
        m1 = fmaxf(m1, __shfl_xor_sync(0xFFFFFFFFu, m1, 2));
        float mn0 = fmaxf(m_prev[0], m0), mn1 = fmaxf(m_prev[1], m1);
        float al0 = __expf(m_prev[0] - mn0), al1 = __expf(m_prev[1] - mn1);
        float rs0 = 0.f, rs1 = 0.f;
        #pragma unroll
        for (int t = 0; t < 16; t++) {
            sAcc[t][0] = __expf(sAcc[t][0] - mn0);
            sAcc[t][1] = __expf(sAcc[t][1] - mn0);
            sAcc[t][2] = __expf(sAcc[t][2] - mn1);
            sAcc[t][3] = __expf(sAcc[t][3] - mn1);
            rs0 += sAcc[t][0] + sAcc[t][1];
            rs1 += sAcc[t][2] + sAcc[t][3];
        }
        rs0 += __shfl_xor_sync(0xFFFFFFFFu, rs0, 1);
        rs0 += __shfl_xor_sync(0xFFFFFFFFu, rs0, 2);
        rs1 += __shfl_xor_sync(0xFFFFFFFFu, rs1, 1);
        rs1 += __shfl_xor_sync(0xFFFFFFFFu, rs1, 2);
        l_run[0] = l_run[0] * al0 + rs0;
        l_run[1] = l_run[1] * al1 + rs1;
        m_prev[0] = mn0; m_prev[1] = mn1;
        #pragma unroll
        for (int ot = 0; ot < 8; ot++) {
            oAcc[ot][0] *= al0; oAcc[ot][1] *= al0;
            oAcc[ot][2] *= al1; oAcc[ot][3] *= al1;
        }

        #pragma unroll
        for (int kk = 0; kk < 8; kk++) {
            float* sA = sAcc[2 * kk];
            float* sB = sAcc[2 * kk + 1];
            uint32_t aH[4];
            aH[0] = pack2h(sA[0], sA[1]); aH[1] = pack2h(sA[2], sA[3]);
            aH[2] = pack2h(sB[0], sB[1]); aH[3] = pack2h(sB[2], sB[3]);
            #pragma unroll
            for (int vb = 0; vb < 4; vb++) {
                uint32_t off = (uint32_t)(kk * 1024 + swz(vb * 16 + brow, bko)) * 2;
                uint32_t r0, r1, r2, r3;
                LDSM4(r0, r1, r2, r3, vbase + off);
                HMMA(oAcc[2 * vb],     aH, r0, r1);
                HMMA(oAcc[2 * vb + 1], aH, r2, r3);
            }
        }
    }

    float inv0 = 1.f / l_run[0], inv1 = 1.f / l_run[1];
    #pragma unroll
    for (int ot = 0; ot < 8; ot++)
        #pragma unroll
        for (int e = 0; e < 4; e++) {
            float v = oAcc[ot][e] * ((e >> 1) ? inv1 : inv0);
            int rowl = w * 16 + r4 + ((e >> 1) ? 8 : 0);
            long long oi = ((long long)(b * 1024 + qb * 128 + rowl)) * 1024
                           + h * 64 + ot * 8 + c2 + (e & 1);
            batt[oi] = __float2half(v);
        }
}

// ---------------- launch ----------------
extern "C" void kernel_launch(void* const* d_in, const int* in_sizes, int n_in,
                              void* d_out, int out_size) {
    const float* x   = (const float*)d_in[0];
    const float* wq  = (const float*)d_in[1];
    const float* wk  = (const float*)d_in[2];
    const float* wv  = (const float*)d_in[3];
    const float* wo  = (const float*)d_in[4];
    const float* rw  = (const float*)d_in[5];
    const float* rb  = (const float*)d_in[6];
    const float* w1  = (const float*)d_in[7];
    const float* w2  = (const float*)d_in[8];
    const float* w3  = (const float*)d_in[9];
    const float* ns1 = (const float*)d_in[10];
    const float* ns2 = (const float*)d_in[11];

    float *qkv, *x1, *h2, *eout;
    int* mb;
    cudaGetSymbolAddress((void**)&qkv, g_qkv);
    cudaGetSymbolAddress((void**)&x1, g_x1);
    cudaGetSymbolAddress((void**)&h2, g_h2);
    cudaGetSymbolAddress((void**)&eout, g_eout);
    cudaGetSymbolAddress((void**)&mb, g_mbound);

    __half *bh, *bq, *bk, *bvt, *batt, *bgrp, *t12h, *acth;
    __half *wqkvh, *woh, *w12h, *w3h;
    cudaGetSymbolAddress((void**)&bh, b_h);
    cudaGetSymbolAddress((void**)&bq, b_q);
    cudaGetSymbolAddress((void**)&bk, b_k);
    cudaGetSymbolAddress((void**)&bvt, b_vt);
    cudaGetSymbolAddress((void**)&batt, b_attn);
    cudaGetSymbolAddress((void**)&bgrp, b_grp);
    cudaGetSymbolAddress((void**)&t12h, h_t12);
    cudaGetSymbolAddress((void**)&acth, h_act);
    cudaGetSymbolAddress((void**)&wqkvh, b_wqkv);
    cudaGetSymbolAddress((void**)&woh, b_wo);
    cudaGetSymbolAddress((void**)&w12h, b_w12);
    cudaGetSymbolAddress((void**)&w3h, b_w3);

    const int SM128 = 3 * (128 * 32 + 32 * 128) * 2;   // 49152
    const int SM256 = 3 * (128 * 32 + 32 * 256) * 2;   // 73728
    cudaFuncSetAttribute(hgemm_kernel<128>, cudaFuncAttributeMaxDynamicSharedMemorySize, SM128);
    cudaFuncSetAttribute(hgemm_kernel<256>, cudaFuncAttributeMaxDynamicSharedMemorySize, SM256);
    cudaFuncSetAttribute(flash_kernel, cudaFuncAttributeMaxDynamicSharedMemorySize, 49152);

    auto hgemm = [&](int NT, int M, int N, int K,
                     const __half* A, int lda, long long soA, int divA,
                     const __half* B, int ldb, long long soB, int divB,
                     float* C, int ldc, long long soC, int divC,
                     int Z, int epi, int outHalf, const float* R, const int* mBnd) {
        dim3 grid(N / NT, M / 128, Z);
        if (NT == 128)
            hgemm_kernel<128><<<grid, 256, SM128>>>(M, N, K, A, lda, soA, divA,
                B, ldb, soB, divB, C, ldc, soC, divC, epi, outHalf, R, mBnd);
        else
            hgemm_kernel<256><<<grid, 256, SM256>>>(M, N, K, A, lda, soA, divA,
                B, ldb, soB, divB, C, ldc, soC, divC, epi, outHalf, R, mBnd);
    };

    // ---- weight conversion (no transposes) ----
    pconv_kernel<<<(DD * 1024 / 4 + 255) / 256, 256>>>(wq, wqkvh, 1024, 0, DD * 1024 / 4);
    pconv_kernel<<<(DD * 256 / 4 + 255) / 256, 256>>>(wk, wqkvh, 256, 1024, DD * 256 / 4);
    pconv_kernel<<<(DD * 256 / 4 + 255) / 256, 256>>>(wv, wqkvh, 256, 1280, DD * 256 / 4);
    conv4_kernel<<<(SZ_WO / 4 + 255) / 256, 256>>>(wo, woh, SZ_WO / 4);
    w12conv_kernel<<<(SZ_T1 / 4 + 255) / 256, 256>>>(w1, w2, (long long)En * DD * HIDn / 4);
    conv4_kernel<<<(SZ_W3 / 4 + 255) / 256, 256>>>(w3, w3h, SZ_W3 / 4);

    // ---- attention ----
    rmsnorm_kernel<<<NTOK, 256>>>(x, ns1, nullptr, bh);
    hgemm(128, NTOK, 1536, 1024, bh, 1024, 0, 1, wqkvh, 1536, 0, 1,
          qkv, 1536, 0, 1, 1, 0, 0, nullptr, nullptr);
    {
        long long tq = (long long)NTOK * HQn * 32;
        rope_kernel<<<(unsigned)((tq + 255) / 256), 256>>>(qkv, 0, HQn, tq);
        long long tk = (long long)NTOK * HKVn * 32;
        rope_kernel<<<(unsigned)((tk + 255) / 256), 256>>>(qkv, 1024, HKVn, tk);
    }
    sconv_kernel<<<(SZ_Q + 255) / 256, 256>>>(qkv, 1536, 1024, bq, SZ_Q);
    sconv_kernel<<<(SZ_K + 255) / 256, 256>>>(qkv + 1024, 1536, 256, bk, SZ_K);
    {
        dim3 grid((VDn + 31) / 32, (TT + 31) / 32, BB * HKVn);
        tconv_kernel<<<grid, dim3(32, 8)>>>(qkv + 1280, bvt, TT, VDn, 1536,
                                            (long long)TT * 1536, VDn, HKVn);
    }

    flash_kernel<<<dim3(8, 32), 256, 49152>>>(bq, bk, bvt, batt);

    hgemm(128, NTOK, 1024, 1024, batt, 1024, 0, 1, woh, 1024, 0, 1,
          x1, 1024, 0, 1, 1, 2, 0, x, nullptr);

    // ---- MoE ----
    rmsnorm_kernel<<<NTOK, 256>>>(x1, ns2, h2, nullptr);
    router_kernel<<<NTOK, 256>>>(rw, rb);
    scan_kernel<<<1, 256>>>();
    zeroh_kernel<<<(SZ_GRP / 8 + 255) / 256, 256>>>(bgrp, SZ_GRP / 8);
    scatter_kernel<<<NTOK * 2, 256>>>();
    hgemm(256, CAPn, 4096, DD,
          bgrp, 1024, (long long)CAPn * DD, 1,
          w12h, 4096, (long long)DD * 4096, 1,
          (float*)t12h, 4096, (long long)CAPn * 4096, 1, En, 0, 1, nullptr, mb);
    gelu_mul_kernel<<<(SZ_T1 / 8 + 255) / 256, 256>>>(SZ_T1 / 8);
    hgemm(256, CAPn, DD, HIDn,
          acth, 2048, (long long)CAPn * HIDn, 1,
          w3h, 1024, (long long)HIDn * DD, 1,
          eout, DD, (long long)CAPn * DD, 1, En, 0, 0, nullptr, mb);
    combine_kernel<<<NTOK, 256>>>((float*)d_out);
}